// round 10
// baseline (speedup 1.0000x reference)
#include <cuda_runtime.h>
#include <cuda_bf16.h>
#include <cstdint>

#define BB 4
#define LL 1024
#define DD 512
#define HH 8
#define HD 64

// ---------------------------------------------------------------------------
// Device scratch (static: no allocations allowed)
__device__ __align__(256) float g_S[(size_t)BB * HH * LL * LL];           // 128 MB scores
__device__ __align__(256) __nv_bfloat16 g_Phi[(size_t)BB * HH * LL * LL]; // 64 MB
__device__ __align__(256) __nv_bfloat16 g_Plo[(size_t)BB * HH * LL * LL]; // 64 MB
__device__ __align__(256) __nv_bfloat16 g_Khi[(size_t)BB * HH * LL * HD];
__device__ __align__(256) __nv_bfloat16 g_Klo[(size_t)BB * HH * LL * HD];
__device__ __align__(256) __nv_bfloat16 g_Qhi[(size_t)BB * HH * LL * HD];
__device__ __align__(256) __nv_bfloat16 g_Qlo[(size_t)BB * HH * LL * HD];
__device__ __align__(256) __nv_bfloat16 g_Vthi[(size_t)BB * HH * HD * LL]; // [bh][d][m]
__device__ __align__(256) __nv_bfloat16 g_Vtlo[(size_t)BB * HH * HD * LL];
__device__ float g_wacc[BB * LL];

// ---------------------------------------------------------------------------
__device__ __forceinline__ uint32_t smem_u32(const void* p) {
    uint32_t a;
    asm("{ .reg .u64 t; cvta.to.shared.u64 t, %1; cvt.u32.u64 %0, t; }" : "=r"(a) : "l"(p));
    return a;
}
__device__ __forceinline__ void ldm_x4(uint32_t& r0, uint32_t& r1, uint32_t& r2,
                                       uint32_t& r3, uint32_t addr) {
    asm volatile("ldmatrix.sync.aligned.m8n8.x4.shared.b16 {%0,%1,%2,%3}, [%4];"
                 : "=r"(r0), "=r"(r1), "=r"(r2), "=r"(r3) : "r"(addr));
}
__device__ __forceinline__ void mma_bf16(float& c0, float& c1, float& c2, float& c3,
                                         uint32_t a0, uint32_t a1, uint32_t a2, uint32_t a3,
                                         uint32_t b0, uint32_t b1) {
    asm volatile("mma.sync.aligned.m16n8k16.row.col.f32.bf16.bf16.f32 "
                 "{%0,%1,%2,%3}, {%4,%5,%6,%7}, {%8,%9}, {%0,%1,%2,%3};"
                 : "+f"(c0), "+f"(c1), "+f"(c2), "+f"(c3)
                 : "r"(a0), "r"(a1), "r"(a2), "r"(a3), "r"(b0), "r"(b1));
}

// smem row stride for MMA tiles: 40 bf16 = 80 B; conflict-free ldmatrix.
#define SSTR 40

__device__ __forceinline__ uint16_t bf16_bits(float f) {
    return __bfloat16_as_ushort(__float2bfloat16(f));
}

// ---------------------------------------------------------------------------
// Prep 1: split K,Q fp32 -> bf16 hi/lo in [bh][l][64] layout; zero wacc.
__global__ __launch_bounds__(256) void prep_kq_kernel(
    const float* __restrict__ Kp, const float* __restrict__ Qp)
{
    int idx = blockIdx.x * 256 + threadIdx.x;
    int k = idx & 63, h = (idx >> 6) & 7, l = (idx >> 9) & 1023, b = idx >> 19;
    size_t o = (((size_t)(b * 8 + h) * 1024 + l) << 6) | (unsigned)k;
    float kv = Kp[idx];
    __nv_bfloat16 khi = __float2bfloat16(kv);
    g_Khi[o] = khi;
    g_Klo[o] = __float2bfloat16(kv - __bfloat162float(khi));
    float qv = Qp[idx];
    __nv_bfloat16 qhi = __float2bfloat16(qv);
    g_Qhi[o] = qhi;
    g_Qlo[o] = __float2bfloat16(qv - __bfloat162float(qhi));
    if (idx < BB * LL) g_wacc[idx] = 0.f;
}

// Prep 2: transpose-split V [b][m][h*64+d] -> Vt hi/lo [bh][d][m]
__global__ __launch_bounds__(256) void prep_v_kernel(const float* __restrict__ Vp)
{
    __shared__ float t[32][33];
    int b = blockIdx.z;
    int m0 = blockIdx.x * 32, hd0 = blockIdx.y * 32;
    int tx = threadIdx.x, ty = threadIdx.y;   // (32, 8)
#pragma unroll
    for (int i = 0; i < 4; i++)
        t[ty + 8 * i][tx] = Vp[((size_t)b * 1024 + m0 + ty + 8 * i) * 512 + hd0 + tx];
    __syncthreads();
#pragma unroll
    for (int i = 0; i < 4; i++) {
        int hd = hd0 + ty + 8 * i;
        int h = hd >> 6, d = hd & 63;
        float x = t[tx][ty + 8 * i];
        __nv_bfloat16 hi = __float2bfloat16(x);
        size_t o = ((size_t)(b * 8 + h) * 64 + d) * 1024 + m0 + tx;
        g_Vthi[o] = hi;
        g_Vtlo[o] = __float2bfloat16(x - __bfloat162float(hi));
    }
}

// ---------------------------------------------------------------------------
// GEMM1 (mma.sync bf16): S[bh][l][m] = K[l,:]·Q[m,:], tile 128x128, K=64.
__global__ __launch_bounds__(256) void gemm1_kernel(const float* __restrict__ doc)
{
    __shared__ __nv_bfloat16 sA[2][128 * SSTR];
    __shared__ __nv_bfloat16 sB[2][128 * SSTR];

    int bh = blockIdx.z;
    int b = bh >> 3;
    int len = (int)doc[b];
    int l0 = blockIdx.y * 128, m0 = blockIdx.x * 128;
    if (l0 >= len || m0 >= len) return;

    int tid = threadIdx.x, wid = tid >> 5, lane = tid & 31;
    int wm = (wid >> 2) * 64, wn = (wid & 3) * 32;

    const uint4* srcA[2] = { (const uint4*)(g_Khi + ((size_t)bh * 1024 + l0) * 64),
                             (const uint4*)(g_Klo + ((size_t)bh * 1024 + l0) * 64) };
    const uint4* srcB[2] = { (const uint4*)(g_Qhi + ((size_t)bh * 1024 + m0) * 64),
                             (const uint4*)(g_Qlo + ((size_t)bh * 1024 + m0) * 64) };

    float c[4][4][4];
#pragma unroll
    for (int i = 0; i < 4; i++)
#pragma unroll
        for (int j = 0; j < 4; j++)
#pragma unroll
            for (int q = 0; q < 4; q++) c[i][j][q] = 0.f;

    uint32_t aoff = (uint32_t)(wm + (lane & 15)) * (SSTR * 2) + (((uint32_t)lane >> 4) << 4);
    uint32_t boff = (uint32_t)(wn + (lane & 7) + (((uint32_t)lane >> 4) << 3)) * (SSTR * 2)
                  + ((((uint32_t)lane >> 3) & 1) << 4);
    uint32_t sAh = smem_u32(&sA[0][0]), sAl = smem_u32(&sA[1][0]);
    uint32_t sBh = smem_u32(&sB[0][0]), sBl = smem_u32(&sB[1][0]);

    for (int kc = 0; kc < 64; kc += 32) {
        if (kc) __syncthreads();
#pragma unroll
        for (int e = 0; e < 2; e++) {
#pragma unroll
            for (int i = 0; i < 2; i++) {
                int idx = tid + i * 256;
                int row = idx >> 2, c4 = idx & 3;
                *(uint4*)((char*)&sA[e][0] + row * (SSTR * 2) + c4 * 16) =
                    srcA[e][(size_t)row * 8 + (kc >> 3) + c4];
                *(uint4*)((char*)&sB[e][0] + row * (SSTR * 2) + c4 * 16) =
                    srcB[e][(size_t)row * 8 + (kc >> 3) + c4];
            }
        }
        __syncthreads();

#pragma unroll
        for (int ks = 0; ks < 2; ks++) {
            uint32_t k0b = ks * 32;
            uint32_t Ah[4][4], Al[4][4], Bh[2][4], Bl[2][4];
#pragma unroll
            for (int mt = 0; mt < 4; mt++) {
                ldm_x4(Ah[mt][0], Ah[mt][1], Ah[mt][2], Ah[mt][3],
                       sAh + aoff + mt * 16 * (SSTR * 2) + k0b);
                ldm_x4(Al[mt][0], Al[mt][1], Al[mt][2], Al[mt][3],
                       sAl + aoff + mt * 16 * (SSTR * 2) + k0b);
            }
#pragma unroll
            for (int nt = 0; nt < 2; nt++) {
                ldm_x4(Bh[nt][0], Bh[nt][1], Bh[nt][2], Bh[nt][3],
                       sBh + boff + nt * 16 * (SSTR * 2) + k0b);
                ldm_x4(Bl[nt][0], Bl[nt][1], Bl[nt][2], Bl[nt][3],
                       sBl + boff + nt * 16 * (SSTR * 2) + k0b);
            }
#pragma unroll
            for (int mt = 0; mt < 4; mt++)
#pragma unroll
                for (int ns = 0; ns < 4; ns++) {
                    float* cc = c[mt][ns];
                    uint32_t* bh_ = &Bh[ns >> 1][(ns & 1) * 2];
                    uint32_t* bl_ = &Bl[ns >> 1][(ns & 1) * 2];
                    mma_bf16(cc[0], cc[1], cc[2], cc[3],
                             Ah[mt][0], Ah[mt][1], Ah[mt][2], Ah[mt][3], bh_[0], bh_[1]);
                    mma_bf16(cc[0], cc[1], cc[2], cc[3],
                             Ah[mt][0], Ah[mt][1], Ah[mt][2], Ah[mt][3], bl_[0], bl_[1]);
                    mma_bf16(cc[0], cc[1], cc[2], cc[3],
                             Al[mt][0], Al[mt][1], Al[mt][2], Al[mt][3], bh_[0], bh_[1]);
                }
        }
    }

    float* Sp = g_S + ((size_t)bh * 1024 + l0) * 1024 + m0;
#pragma unroll
    for (int mt = 0; mt < 4; mt++) {
        int r0 = wm + mt * 16 + (lane >> 2);
#pragma unroll
        for (int ns = 0; ns < 4; ns++) {
            int n = wn + ns * 8 + (lane & 3) * 2;
            *(float2*)&Sp[(size_t)r0 * 1024 + n] = make_float2(c[mt][ns][0], c[mt][ns][1]);
            *(float2*)&Sp[(size_t)(r0 + 8) * 1024 + n] = make_float2(c[mt][ns][2], c[mt][ns][3]);
        }
    }
}

// ---------------------------------------------------------------------------
// lnsm v5: R6 loop structure (simple homogeneous sweeps, high ILP), minus the
// max pass (LN output bounded => exp can't overflow; softmax shift-invariant)
// and minus the scale-rewrite pass (1/sum folded into the emit pass).
// Sweeps: copy -> LN -> exp+sum (warp-per-head) -> emit(scale+pack+csum).
__global__ __launch_bounds__(256) void lnsm_kernel(
    const float* __restrict__ doc, const float* __restrict__ gamma,
    const float* __restrict__ beta)
{
    __shared__ float s[HH][LL];       // 32 KB
    __shared__ float binv[HH];

    int b = blockIdx.y, l = blockIdx.x;
    int len = (int)doc[b];
    int kend  = (len + 63) & ~63;
    int lceil = (len + 127) & ~127;
    int tid = threadIdx.x;

    if (l >= len) {                    // zero rows needed by GEMM2
        if (l >= lceil) return;
        int m0 = tid * 4;
        if (m0 < kend) {
            uint2 z = make_uint2(0u, 0u);
#pragma unroll
            for (int h = 0; h < HH; ++h) {
                size_t o = ((size_t)(b * 8 + h) * 1024 + l) * 1024 + m0;
                *(uint2*)(g_Phi + o) = z;
                *(uint2*)(g_Plo + o) = z;
            }
        }
        return;
    }

    // ---- sweep 1: copy S rows into smem (coalesced, high MLP) ----
    for (int h = 0; h < HH; ++h) {
        const float* Sr = g_S + ((size_t)(b * 8 + h) * 1024 + l) * 1024;
        for (int m = tid; m < len; m += 256) s[h][m] = Sr[m];
    }
    __syncthreads();

    float ga[HH], be[HH];
#pragma unroll
    for (int h = 0; h < HH; h++) { ga[h] = gamma[h]; be[h] = beta[h]; }

    // ---- sweep 2: LayerNorm across heads at each m ----
    for (int m = tid; m < len; m += 256) {
        float x[HH]; float mu = 0.f;
#pragma unroll
        for (int h = 0; h < HH; h++) { x[h] = s[h][m]; mu += x[h]; }
        mu *= (1.f / HH);
        float var = 0.f;
#pragma unroll
        for (int h = 0; h < HH; h++) { float d0 = x[h] - mu; var += d0 * d0; }
        var *= (1.f / HH);
        float rstd = rsqrtf(var + 1e-5f);
#pragma unroll
        for (int h = 0; h < HH; h++) s[h][m] = (x[h] - mu) * rstd * ga[h] + be[h];
    }
    __syncthreads();

    // ---- sweep 3: exp in place + sum (warp w owns head w); no max needed ----
    {
        int w = tid >> 5, lane = tid & 31;
        float sum = 0.f;
        for (int m = lane; m < len; m += 32) {
            float e = __expf(s[w][m]);      // bounded: |arg| <= ~2.5 (gamma=1)
            s[w][m] = e; sum += e;
        }
#pragma unroll
        for (int o = 16; o; o >>= 1) sum += __shfl_xor_sync(0xffffffffu, sum, o);
        if (lane == 0) binv[w] = 1.f / sum;
    }
    __syncthreads();

    // ---- sweep 4: emit P bf16 hi/lo (scaled here) + column sums ----
    int m0 = tid * 4;
    if (m0 < kend) {
        int nv = len - m0;                 // may be <= 0
        float csum[4] = {0.f, 0.f, 0.f, 0.f};
#pragma unroll
        for (int h = 0; h < HH; ++h) {
            float inv = binv[h];
            float4 v = *(float4*)&s[h][m0];
            float p0 = (0 < nv) ? v.x * inv : 0.f;
            float p1 = (1 < nv) ? v.y * inv : 0.f;
            float p2 = (2 < nv) ? v.z * inv : 0.f;
            float p3 = (3 < nv) ? v.w * inv : 0.f;
            csum[0] += p0; csum[1] += p1; csum[2] += p2; csum[3] += p3;
            uint16_t h0 = bf16_bits(p0), h1 = bf16_bits(p1);
            uint16_t h2 = bf16_bits(p2), h3 = bf16_bits(p3);
            uint16_t l0b = bf16_bits(p0 - __bfloat162float(__ushort_as_bfloat16(h0)));
            uint16_t l1b = bf16_bits(p1 - __bfloat162float(__ushort_as_bfloat16(h1)));
            uint16_t l2b = bf16_bits(p2 - __bfloat162float(__ushort_as_bfloat16(h2)));
            uint16_t l3b = bf16_bits(p3 - __bfloat162float(__ushort_as_bfloat16(h3)));
            size_t o = ((size_t)(b * 8 + h) * 1024 + l) * 1024 + m0;
            *(uint2*)(g_Phi + o) = make_uint2((uint32_t)h0 | ((uint32_t)h1 << 16),
                                              (uint32_t)h2 | ((uint32_t)h3 << 16));
            *(uint2*)(g_Plo + o) = make_uint2((uint32_t)l0b | ((uint32_t)l1b << 16),
                                              (uint32_t)l2b | ((uint32_t)l3b << 16));
        }
#pragma unroll
        for (int mi = 0; mi < 4; mi++)
            if (mi < nv) atomicAdd(&g_wacc[b * 1024 + m0 + mi], csum[mi]);
    }
}

// ---------------------------------------------------------------------------
// Finalize w: one 1024-thread block per batch, single pass.
__global__ __launch_bounds__(1024) void wfin_kernel(
    const float* __restrict__ doc, float* __restrict__ wout)
{
    __shared__ float red[32];
    __shared__ float s_bmax, s_inv;
    int b = blockIdx.x;
    int len = (int)doc[b];
    int tid = threadIdx.x, w = tid >> 5, lane = tid & 31;
    float scale = 1.f / (8.f * (float)len);

    float v = (tid < len) ? g_wacc[b * LL + tid] * scale : -1e30f;
    float mx = v;
#pragma unroll
    for (int o = 16; o; o >>= 1) mx = fmaxf(mx, __shfl_xor_sync(0xffffffffu, mx, o));
    if (lane == 0) red[w] = mx;
    __syncthreads();
    if (w == 0) {
        float t = red[lane];
#pragma unroll
        for (int o = 16; o; o >>= 1) t = fmaxf(t, __shfl_xor_sync(0xffffffffu, t, o));
        if (lane == 0) s_bmax = t;
    }
    __syncthreads();
    float e = (tid < len) ? __expf(v - s_bmax) : 0.f;
    float sum = e;
#pragma unroll
    for (int o = 16; o; o >>= 1) sum += __shfl_xor_sync(0xffffffffu, sum, o);
    if (lane == 0) red[w] = sum;
    __syncthreads();
    if (w == 0) {
        float t = red[lane];
#pragma unroll
        for (int o = 16; o; o >>= 1) t += __shfl_xor_sync(0xffffffffu, t, o);
        if (lane == 0) s_inv = 1.f / t;
    }
    __syncthreads();
    wout[b * LL + tid] = e * s_inv;
}

// ---------------------------------------------------------------------------
// GEMM2 (mma.sync bf16): out[l,d] = sum_m P[l,m]·Vt[d,m]; tile 128(l) x 64(d).
// Register-prefetch pipeline over K chunks of 32 (next chunk's LDGs overlap MMA).
__global__ __launch_bounds__(256) void gemm2_kernel(
    const float* __restrict__ doc, float* __restrict__ outp)
{
    __shared__ __nv_bfloat16 sP[2][128 * SSTR];
    __shared__ __nv_bfloat16 sV[2][64 * SSTR];

    int b = blockIdx.z, h = blockIdx.y;
    int bh = b * 8 + h;
    int len = (int)doc[b];
    int l0 = blockIdx.x * 128;
    int tid = threadIdx.x, wid = tid >> 5, lane = tid & 31;

    if (l0 >= len) {
        float* dst = outp + ((size_t)b * 1024 + l0 + (tid >> 1)) * 512 + h * 64;
        float4 z = make_float4(0, 0, 0, 0);
#pragma unroll
        for (int j = 0; j < 8; j++) ((float4*)dst)[(tid & 1) * 8 + j] = z;
        return;
    }

    int wm = (wid >> 1) * 32, wn = (wid & 1) * 32;

    const uint4* srcP[2] = { (const uint4*)(g_Phi + ((size_t)bh * 1024 + l0) * 1024),
                             (const uint4*)(g_Plo + ((size_t)bh * 1024 + l0) * 1024) };
    const uint4* srcV[2] = { (const uint4*)(g_Vthi + (size_t)bh * 64 * 1024),
                             (const uint4*)(g_Vtlo + (size_t)bh * 64 * 1024) };

    float c[2][4][4];
#pragma unroll
    for (int i = 0; i < 2; i++)
#pragma unroll
        for (int j = 0; j < 4; j++)
#pragma unroll
            for (int q = 0; q < 4; q++) c[i][j][q] = 0.f;

    uint32_t aoff = (uint32_t)(wm + (lane & 15)) * (SSTR * 2) + (((uint32_t)lane >> 4) << 4);
    uint32_t boff = (uint32_t)(wn + (lane & 7) + (((uint32_t)lane >> 4) << 3)) * (SSTR * 2)
                  + ((((uint32_t)lane >> 3) & 1) << 4);
    uint32_t sPh = smem_u32(&sP[0][0]), sPl = smem_u32(&sP[1][0]);
    uint32_t sVh = smem_u32(&sV[0][0]), sVl = smem_u32(&sV[1][0]);

    int prow = tid >> 2, pc4 = tid & 3;
    int vrow = tid >> 2, vc4 = tid & 3;
    char* stP[2][2];
    char* stV[2];
#pragma unroll
    for (int e = 0; e < 2; e++) {
        stP[e][0] = (char*)&sP[e][0] + prow * (SSTR * 2) + pc4 * 16;
        stP[e][1] = (char*)&sP[e][0] + (prow + 64) * (SSTR * 2) + pc4 * 16;
        stV[e]    = (char*)&sV[e][0] + vrow * (SSTR * 2) + vc4 * 16;
    }

    int kend = (len + 31) & ~31;
    int nch = kend >> 5;

    uint4 rp[2][2], rv[2];
#pragma unroll
    for (int e = 0; e < 2; e++) {
        rp[e][0] = srcP[e][(size_t)prow * 128 + pc4];
        rp[e][1] = srcP[e][(size_t)(prow + 64) * 128 + pc4];
        rv[e]    = srcV[e][(size_t)vrow * 128 + vc4];
    }

    for (int ch = 0; ch < nch; ++ch) {
#pragma unroll
        for (int e = 0; e < 2; e++) {
            *(uint4*)stP[e][0] = rp[e][0];
            *(uint4*)stP[e][1] = rp[e][1];
            *(uint4*)stV[e]    = rv[e];
        }
        __syncthreads();

        if (ch + 1 < nch) {
            int mq = (ch + 1) * 4;
#pragma unroll
            for (int e = 0; e < 2; e++) {
                rp[e][0] = srcP[e][(size_t)prow * 128 + mq + pc4];
                rp[e][1] = srcP[e][(size_t)(prow + 64) * 128 + mq + pc4];
                rv[e]    = srcV[e][(size_t)vrow * 128 + mq + vc4];
            }
        }

#pragma unroll
        for (int ks = 0; ks < 2; ks++) {
            uint32_t k0b = ks * 32;
            uint32_t Ah[2][4], Al[2][4], Bh[2][4], Bl[2][4];
#pragma unroll
            for (int mt = 0; mt < 2; mt++) {
                ldm_x4(Ah[mt][0], Ah[mt][1], Ah[mt][2], Ah[mt][3],
                       sPh + aoff + mt * 16 * (SSTR * 2) + k0b);
                ldm_x4(Al[mt][0], Al[mt][1], Al[mt][2], Al[mt][3],
                       sPl + aoff + mt * 16 * (SSTR * 2) + k0b);
            }
#pragma unroll
            for (int nt = 0; nt < 2; nt++) {
                ldm_x4(Bh[nt][0], Bh[nt][1], Bh[nt][2], Bh[nt][3],
                       sVh + boff + nt * 16 * (SSTR * 2) + k0b);
                ldm_x4(Bl[nt][0], Bl[nt][1], Bl[nt][2], Bl[nt][3],
                       sVl + boff + nt * 16 * (SSTR * 2) + k0b);
            }
#pragma unroll
            for (int mt = 0; mt < 2; mt++)
#pragma unroll
                for (int ns = 0; ns < 4; ns++) {
                    float* cc = c[mt][ns];
                    uint32_t* bh_ = &Bh[ns >> 1][(ns & 1) * 2];
                    uint32_t* bl_ = &Bl[ns >> 1][(ns & 1) * 2];
                    mma_bf16(cc[0], cc[1], cc[2], cc[3],
                             Ah[mt][0], Ah[mt][1], Ah[mt][2], Ah[mt][3], bh_[0], bh_[1]);
                    mma_bf16(cc[0], cc[1], cc[2], cc[3],
                             Ah[mt][0], Ah[mt][1], Ah[mt][2], Ah[mt][3], bl_[0], bl_[1]);
                    mma_bf16(cc[0], cc[1], cc[2], cc[3],
                             Al[mt][0], Al[mt][1], Al[mt][2], Al[mt][3], bh_[0], bh_[1]);
                }
        }
        __syncthreads();
    }

    float* dstb = outp + ((size_t)b * 1024 + l0) * 512 + h * 64;
#pragma unroll
    for (int mt = 0; mt < 2; mt++) {
        int r0 = wm + mt * 16 + (lane >> 2);
#pragma unroll
        for (int ns = 0; ns < 4; ns++) {
            int n = wn + ns * 8 + (lane & 3) * 2;
            *(float2*)&dstb[(size_t)r0 * 512 + n] = make_float2(c[mt][ns][0], c[mt][ns][1]);
            *(float2*)&dstb[(size_t)(r0 + 8) * 512 + n] = make_float2(c[mt][ns][2], c[mt][ns][3]);
        }
    }
}

// ---------------------------------------------------------------------------
extern "C" void kernel_launch(void* const* d_in, const int* in_sizes, int n_in,
                              void* d_out, int out_size) {
    const float* K     = (const float*)d_in[0];
    const float* Q     = (const float*)d_in[1];
    const float* V     = (const float*)d_in[2];
    const float* doc   = (const float*)d_in[3];
    const float* gamma = (const float*)d_in[4];
    const float* beta  = (const float*)d_in[5];
    // pad_mask / bx_packed derivable from doc_sizes; unused.

    float* outp = (float*)d_out;

    prep_kq_kernel<<<(BB * LL * DD) / 256, 256>>>(K, Q);
    prep_v_kernel<<<dim3(LL / 32, DD / 32, BB), dim3(32, 8)>>>(V);

    dim3 g1(LL / 128, LL / 128, BB * HH);      // (8, 8, 32)
    gemm1_kernel<<<g1, 256>>>(doc);

    dim3 g2(LL, BB);
    lnsm_kernel<<<g2, 256>>>(doc, gamma, beta);

    if (out_size >= BB * LL * DD + BB * LL) {
        float* wout = outp + (size_t)BB * LL * DD;
        wfin_kernel<<<BB, 1024>>>(doc, wout);
    }

    dim3 g3(LL / 128, HH, BB);                 // (8, 8, 4)
    gemm2_kernel<<<g3, 256>>>(doc, outp);
}

// round 11
// speedup vs baseline: 1.2459x; 1.2459x over previous
#include <cuda_runtime.h>
#include <cuda_bf16.h>
#include <cstdint>

#define BB 4
#define LL 1024
#define DD 512
#define HH 8
#define HD 64

// ---------------------------------------------------------------------------
// Device scratch (static: no allocations allowed)
__device__ __align__(256) float g_S[(size_t)BB * HH * LL * LL];           // 128 MB scores
__device__ __align__(256) __nv_bfloat16 g_Phi[(size_t)BB * HH * LL * LL]; // 64 MB
__device__ __align__(256) __nv_bfloat16 g_Plo[(size_t)BB * HH * LL * LL]; // 64 MB
__device__ __align__(256) __nv_bfloat16 g_Khi[(size_t)BB * HH * LL * HD];
__device__ __align__(256) __nv_bfloat16 g_Klo[(size_t)BB * HH * LL * HD];
__device__ __align__(256) __nv_bfloat16 g_Qhi[(size_t)BB * HH * LL * HD];
__device__ __align__(256) __nv_bfloat16 g_Qlo[(size_t)BB * HH * LL * HD];
__device__ __align__(256) __nv_bfloat16 g_Vthi[(size_t)BB * HH * HD * LL]; // [bh][d][m]
__device__ __align__(256) __nv_bfloat16 g_Vtlo[(size_t)BB * HH * HD * LL];
__device__ float g_wacc[BB * LL];

// ---------------------------------------------------------------------------
__device__ __forceinline__ uint32_t smem_u32(const void* p) {
    uint32_t a;
    asm("{ .reg .u64 t; cvta.to.shared.u64 t, %1; cvt.u32.u64 %0, t; }" : "=r"(a) : "l"(p));
    return a;
}
__device__ __forceinline__ void ldm_x4(uint32_t& r0, uint32_t& r1, uint32_t& r2,
                                       uint32_t& r3, uint32_t addr) {
    asm volatile("ldmatrix.sync.aligned.m8n8.x4.shared.b16 {%0,%1,%2,%3}, [%4];"
                 : "=r"(r0), "=r"(r1), "=r"(r2), "=r"(r3) : "r"(addr));
}
__device__ __forceinline__ void mma_bf16(float& c0, float& c1, float& c2, float& c3,
                                         uint32_t a0, uint32_t a1, uint32_t a2, uint32_t a3,
                                         uint32_t b0, uint32_t b1) {
    asm volatile("mma.sync.aligned.m16n8k16.row.col.f32.bf16.bf16.f32 "
                 "{%0,%1,%2,%3}, {%4,%5,%6,%7}, {%8,%9}, {%0,%1,%2,%3};"
                 : "+f"(c0), "+f"(c1), "+f"(c2), "+f"(c3)
                 : "r"(a0), "r"(a1), "r"(a2), "r"(a3), "r"(b0), "r"(b1));
}

// smem row stride for MMA tiles: 40 bf16 = 80 B; conflict-free ldmatrix.
#define SSTR 40

__device__ __forceinline__ uint16_t bf16_bits(float f) {
    return __bfloat16_as_ushort(__float2bfloat16(f));
}

// ---------------------------------------------------------------------------
// Prep 1: split K,Q fp32 -> bf16 hi/lo in [bh][l][64] layout; zero wacc.
__global__ __launch_bounds__(256) void prep_kq_kernel(
    const float* __restrict__ Kp, const float* __restrict__ Qp)
{
    int idx = blockIdx.x * 256 + threadIdx.x;
    int k = idx & 63, h = (idx >> 6) & 7, l = (idx >> 9) & 1023, b = idx >> 19;
    size_t o = (((size_t)(b * 8 + h) * 1024 + l) << 6) | (unsigned)k;
    float kv = Kp[idx];
    __nv_bfloat16 khi = __float2bfloat16(kv);
    g_Khi[o] = khi;
    g_Klo[o] = __float2bfloat16(kv - __bfloat162float(khi));
    float qv = Qp[idx];
    __nv_bfloat16 qhi = __float2bfloat16(qv);
    g_Qhi[o] = qhi;
    g_Qlo[o] = __float2bfloat16(qv - __bfloat162float(qhi));
    if (idx < BB * LL) g_wacc[idx] = 0.f;
}

// Prep 2: transpose-split V [b][m][h*64+d] -> Vt hi/lo [bh][d][m]
__global__ __launch_bounds__(256) void prep_v_kernel(const float* __restrict__ Vp)
{
    __shared__ float t[32][33];
    int b = blockIdx.z;
    int m0 = blockIdx.x * 32, hd0 = blockIdx.y * 32;
    int tx = threadIdx.x, ty = threadIdx.y;   // (32, 8)
#pragma unroll
    for (int i = 0; i < 4; i++)
        t[ty + 8 * i][tx] = Vp[((size_t)b * 1024 + m0 + ty + 8 * i) * 512 + hd0 + tx];
    __syncthreads();
#pragma unroll
    for (int i = 0; i < 4; i++) {
        int hd = hd0 + ty + 8 * i;
        int h = hd >> 6, d = hd & 63;
        float x = t[tx][ty + 8 * i];
        __nv_bfloat16 hi = __float2bfloat16(x);
        size_t o = ((size_t)(b * 8 + h) * 64 + d) * 1024 + m0 + tx;
        g_Vthi[o] = hi;
        g_Vtlo[o] = __float2bfloat16(x - __bfloat162float(hi));
    }
}

// ---------------------------------------------------------------------------
// GEMM1 (mma.sync bf16): S[bh][l][m] = K[l,:]·Q[m,:], tile 128x128, K=64.
__global__ __launch_bounds__(256) void gemm1_kernel(const float* __restrict__ doc)
{
    __shared__ __nv_bfloat16 sA[2][128 * SSTR];
    __shared__ __nv_bfloat16 sB[2][128 * SSTR];

    int bh = blockIdx.z;
    int b = bh >> 3;
    int len = (int)doc[b];
    int l0 = blockIdx.y * 128, m0 = blockIdx.x * 128;
    if (l0 >= len || m0 >= len) return;

    int tid = threadIdx.x, wid = tid >> 5, lane = tid & 31;
    int wm = (wid >> 2) * 64, wn = (wid & 3) * 32;

    const uint4* srcA[2] = { (const uint4*)(g_Khi + ((size_t)bh * 1024 + l0) * 64),
                             (const uint4*)(g_Klo + ((size_t)bh * 1024 + l0) * 64) };
    const uint4* srcB[2] = { (const uint4*)(g_Qhi + ((size_t)bh * 1024 + m0) * 64),
                             (const uint4*)(g_Qlo + ((size_t)bh * 1024 + m0) * 64) };

    float c[4][4][4];
#pragma unroll
    for (int i = 0; i < 4; i++)
#pragma unroll
        for (int j = 0; j < 4; j++)
#pragma unroll
            for (int q = 0; q < 4; q++) c[i][j][q] = 0.f;

    uint32_t aoff = (uint32_t)(wm + (lane & 15)) * (SSTR * 2) + (((uint32_t)lane >> 4) << 4);
    uint32_t boff = (uint32_t)(wn + (lane & 7) + (((uint32_t)lane >> 4) << 3)) * (SSTR * 2)
                  + ((((uint32_t)lane >> 3) & 1) << 4);
    uint32_t sAh = smem_u32(&sA[0][0]), sAl = smem_u32(&sA[1][0]);
    uint32_t sBh = smem_u32(&sB[0][0]), sBl = smem_u32(&sB[1][0]);

    for (int kc = 0; kc < 64; kc += 32) {
        if (kc) __syncthreads();
#pragma unroll
        for (int e = 0; e < 2; e++) {
#pragma unroll
            for (int i = 0; i < 2; i++) {
                int idx = tid + i * 256;
                int row = idx >> 2, c4 = idx & 3;
                *(uint4*)((char*)&sA[e][0] + row * (SSTR * 2) + c4 * 16) =
                    srcA[e][(size_t)row * 8 + (kc >> 3) + c4];
                *(uint4*)((char*)&sB[e][0] + row * (SSTR * 2) + c4 * 16) =
                    srcB[e][(size_t)row * 8 + (kc >> 3) + c4];
            }
        }
        __syncthreads();

#pragma unroll
        for (int ks = 0; ks < 2; ks++) {
            uint32_t k0b = ks * 32;
            uint32_t Ah[4][4], Al[4][4], Bh[2][4], Bl[2][4];
#pragma unroll
            for (int mt = 0; mt < 4; mt++) {
                ldm_x4(Ah[mt][0], Ah[mt][1], Ah[mt][2], Ah[mt][3],
                       sAh + aoff + mt * 16 * (SSTR * 2) + k0b);
                ldm_x4(Al[mt][0], Al[mt][1], Al[mt][2], Al[mt][3],
                       sAl + aoff + mt * 16 * (SSTR * 2) + k0b);
            }
#pragma unroll
            for (int nt = 0; nt < 2; nt++) {
                ldm_x4(Bh[nt][0], Bh[nt][1], Bh[nt][2], Bh[nt][3],
                       sBh + boff + nt * 16 * (SSTR * 2) + k0b);
                ldm_x4(Bl[nt][0], Bl[nt][1], Bl[nt][2], Bl[nt][3],
                       sBl + boff + nt * 16 * (SSTR * 2) + k0b);
            }
#pragma unroll
            for (int mt = 0; mt < 4; mt++)
#pragma unroll
                for (int ns = 0; ns < 4; ns++) {
                    float* cc = c[mt][ns];
                    uint32_t* bh_ = &Bh[ns >> 1][(ns & 1) * 2];
                    uint32_t* bl_ = &Bl[ns >> 1][(ns & 1) * 2];
                    mma_bf16(cc[0], cc[1], cc[2], cc[3],
                             Ah[mt][0], Ah[mt][1], Ah[mt][2], Ah[mt][3], bh_[0], bh_[1]);
                    mma_bf16(cc[0], cc[1], cc[2], cc[3],
                             Ah[mt][0], Ah[mt][1], Ah[mt][2], Ah[mt][3], bl_[0], bl_[1]);
                    mma_bf16(cc[0], cc[1], cc[2], cc[3],
                             Al[mt][0], Al[mt][1], Al[mt][2], Al[mt][3], bh_[0], bh_[1]);
                }
        }
    }

    float* Sp = g_S + ((size_t)bh * 1024 + l0) * 1024 + m0;
#pragma unroll
    for (int mt = 0; mt < 4; mt++) {
        int r0 = wm + mt * 16 + (lane >> 2);
#pragma unroll
        for (int ns = 0; ns < 4; ns++) {
            int n = wn + ns * 8 + (lane & 3) * 2;
            *(float2*)&Sp[(size_t)r0 * 1024 + n] = make_float2(c[mt][ns][0], c[mt][ns][1]);
            *(float2*)&Sp[(size_t)(r0 + 8) * 1024 + n] = make_float2(c[mt][ns][2], c[mt][ns][3]);
        }
    }
}

// ---------------------------------------------------------------------------
// lnsm v6: R6's exact sweep structure (the fastest measured variant), with ONE
// change: the softmax max pass is deleted. LN over H=8 heads bounds the input
// (|z| <= ~2.5 for gamma=1), so exp() cannot overflow and shift-invariance
// makes max-subtraction unnecessary (validated: rel_err unchanged in R9/R10).
// Sweeps: copy -> LN -> exp+sum+scale (warp-per-head) -> P write -> csum.
__global__ __launch_bounds__(256) void lnsm_kernel(
    const float* __restrict__ doc, const float* __restrict__ gamma,
    const float* __restrict__ beta)
{
    __shared__ float s[HH][LL];   // 32 KB
    int b = blockIdx.y, l = blockIdx.x;
    int len = (int)doc[b];
    int kend  = (len + 63) & ~63;      // GEMM2 reads cols [0, kend)
    int lceil = (len + 127) & ~127;    // GEMM2 reads rows [0, lceil)
    int tid = threadIdx.x;

    if (l >= len) {
        if (l >= lceil) return;
        for (int h = 0; h < HH; ++h) {
            size_t o = ((size_t)(b * HH + h) * LL + l) * LL;
            for (int m = tid; m < kend; m += 256) {
                g_Phi[o + m] = __float2bfloat16(0.f);
                g_Plo[o + m] = __float2bfloat16(0.f);
            }
        }
        return;
    }

    for (int h = 0; h < HH; ++h) {
        const float* Sr = g_S + ((size_t)(b * HH + h) * LL + l) * LL;
        for (int m = tid; m < len; m += 256) s[h][m] = Sr[m];
    }
    __syncthreads();

    float ga[HH], be[HH];
#pragma unroll
    for (int h = 0; h < HH; h++) { ga[h] = gamma[h]; be[h] = beta[h]; }

    for (int m = tid; m < len; m += 256) {
        float x[HH]; float mu = 0.f;
#pragma unroll
        for (int h = 0; h < HH; h++) { x[h] = s[h][m]; mu += x[h]; }
        mu *= (1.f / HH);
        float var = 0.f;
#pragma unroll
        for (int h = 0; h < HH; h++) { float d0 = x[h] - mu; var += d0 * d0; }
        var *= (1.f / HH);
        float rstd = rsqrtf(var + 1e-5f);
#pragma unroll
        for (int h = 0; h < HH; h++) s[h][m] = (x[h] - mu) * rstd * ga[h] + be[h];
    }
    __syncthreads();

    // per-head softmax WITHOUT max subtraction: warp w handles head w
    int w = tid >> 5, lane = tid & 31;
    {
        float sum = 0.f;
        for (int m = lane; m < len; m += 32) {
            float e = __expf(s[w][m]);     // bounded by LN: no overflow risk
            s[w][m] = e; sum += e;
        }
#pragma unroll
        for (int o = 16; o; o >>= 1) sum += __shfl_xor_sync(0xffffffffu, sum, o);
        float inv = 1.f / sum;
        for (int m = lane; m < len; m += 32) s[w][m] *= inv;
    }
    __syncthreads();

    // write P (zeros beyond len) as bf16 hi/lo
    for (int h = 0; h < HH; ++h) {
        size_t o = ((size_t)(b * HH + h) * LL + l) * LL;
        for (int m = tid; m < kend; m += 256) {
            float p = (m < len) ? s[h][m] : 0.f;
            __nv_bfloat16 hi = __float2bfloat16(p);
            g_Phi[o + m] = hi;
            g_Plo[o + m] = __float2bfloat16(p - __bfloat162float(hi));
        }
    }
    // accumulate column sums for w
    for (int m = tid; m < len; m += 256) {
        float cacc = 0.f;
#pragma unroll
        for (int h = 0; h < HH; h++) cacc += s[h][m];
        atomicAdd(&g_wacc[b * LL + m], cacc);
    }
}

// ---------------------------------------------------------------------------
// Finalize w: one 1024-thread block per batch, single pass.
__global__ __launch_bounds__(1024) void wfin_kernel(
    const float* __restrict__ doc, float* __restrict__ wout)
{
    __shared__ float red[32];
    __shared__ float s_bmax, s_inv;
    int b = blockIdx.x;
    int len = (int)doc[b];
    int tid = threadIdx.x, w = tid >> 5, lane = tid & 31;
    float scale = 1.f / (8.f * (float)len);

    float v = (tid < len) ? g_wacc[b * LL + tid] * scale : -1e30f;
    float mx = v;
#pragma unroll
    for (int o = 16; o; o >>= 1) mx = fmaxf(mx, __shfl_xor_sync(0xffffffffu, mx, o));
    if (lane == 0) red[w] = mx;
    __syncthreads();
    if (w == 0) {
        float t = red[lane];
#pragma unroll
        for (int o = 16; o; o >>= 1) t = fmaxf(t, __shfl_xor_sync(0xffffffffu, t, o));
        if (lane == 0) s_bmax = t;
    }
    __syncthreads();
    float e = (tid < len) ? __expf(v - s_bmax) : 0.f;
    float sum = e;
#pragma unroll
    for (int o = 16; o; o >>= 1) sum += __shfl_xor_sync(0xffffffffu, sum, o);
    if (lane == 0) red[w] = sum;
    __syncthreads();
    if (w == 0) {
        float t = red[lane];
#pragma unroll
        for (int o = 16; o; o >>= 1) t += __shfl_xor_sync(0xffffffffu, t, o);
        if (lane == 0) s_inv = 1.f / t;
    }
    __syncthreads();
    wout[b * LL + tid] = e * s_inv;
}

// ---------------------------------------------------------------------------
// GEMM2 (mma.sync bf16): out[l,d] = sum_m P[l,m]·Vt[d,m]; tile 128(l) x 64(d).
// Register-prefetch pipeline over K chunks of 32 (next chunk's LDGs overlap MMA).
__global__ __launch_bounds__(256) void gemm2_kernel(
    const float* __restrict__ doc, float* __restrict__ outp)
{
    __shared__ __nv_bfloat16 sP[2][128 * SSTR];
    __shared__ __nv_bfloat16 sV[2][64 * SSTR];

    int b = blockIdx.z, h = blockIdx.y;
    int bh = b * 8 + h;
    int len = (int)doc[b];
    int l0 = blockIdx.x * 128;
    int tid = threadIdx.x, wid = tid >> 5, lane = tid & 31;

    if (l0 >= len) {
        float* dst = outp + ((size_t)b * 1024 + l0 + (tid >> 1)) * 512 + h * 64;
        float4 z = make_float4(0, 0, 0, 0);
#pragma unroll
        for (int j = 0; j < 8; j++) ((float4*)dst)[(tid & 1) * 8 + j] = z;
        return;
    }

    int wm = (wid >> 1) * 32, wn = (wid & 1) * 32;

    const uint4* srcP[2] = { (const uint4*)(g_Phi + ((size_t)bh * 1024 + l0) * 1024),
                             (const uint4*)(g_Plo + ((size_t)bh * 1024 + l0) * 1024) };
    const uint4* srcV[2] = { (const uint4*)(g_Vthi + (size_t)bh * 64 * 1024),
                             (const uint4*)(g_Vtlo + (size_t)bh * 64 * 1024) };

    float c[2][4][4];
#pragma unroll
    for (int i = 0; i < 2; i++)
#pragma unroll
        for (int j = 0; j < 4; j++)
#pragma unroll
            for (int q = 0; q < 4; q++) c[i][j][q] = 0.f;

    uint32_t aoff = (uint32_t)(wm + (lane & 15)) * (SSTR * 2) + (((uint32_t)lane >> 4) << 4);
    uint32_t boff = (uint32_t)(wn + (lane & 7) + (((uint32_t)lane >> 4) << 3)) * (SSTR * 2)
                  + ((((uint32_t)lane >> 3) & 1) << 4);
    uint32_t sPh = smem_u32(&sP[0][0]), sPl = smem_u32(&sP[1][0]);
    uint32_t sVh = smem_u32(&sV[0][0]), sVl = smem_u32(&sV[1][0]);

    int prow = tid >> 2, pc4 = tid & 3;
    int vrow = tid >> 2, vc4 = tid & 3;
    char* stP[2][2];
    char* stV[2];
#pragma unroll
    for (int e = 0; e < 2; e++) {
        stP[e][0] = (char*)&sP[e][0] + prow * (SSTR * 2) + pc4 * 16;
        stP[e][1] = (char*)&sP[e][0] + (prow + 64) * (SSTR * 2) + pc4 * 16;
        stV[e]    = (char*)&sV[e][0] + vrow * (SSTR * 2) + vc4 * 16;
    }

    int kend = (len + 31) & ~31;
    int nch = kend >> 5;

    uint4 rp[2][2], rv[2];
#pragma unroll
    for (int e = 0; e < 2; e++) {
        rp[e][0] = srcP[e][(size_t)prow * 128 + pc4];
        rp[e][1] = srcP[e][(size_t)(prow + 64) * 128 + pc4];
        rv[e]    = srcV[e][(size_t)vrow * 128 + vc4];
    }

    for (int ch = 0; ch < nch; ++ch) {
#pragma unroll
        for (int e = 0; e < 2; e++) {
            *(uint4*)stP[e][0] = rp[e][0];
            *(uint4*)stP[e][1] = rp[e][1];
            *(uint4*)stV[e]    = rv[e];
        }
        __syncthreads();

        if (ch + 1 < nch) {
            int mq = (ch + 1) * 4;
#pragma unroll
            for (int e = 0; e < 2; e++) {
                rp[e][0] = srcP[e][(size_t)prow * 128 + mq + pc4];
                rp[e][1] = srcP[e][(size_t)(prow + 64) * 128 + mq + pc4];
                rv[e]    = srcV[e][(size_t)vrow * 128 + mq + vc4];
            }
        }

#pragma unroll
        for (int ks = 0; ks < 2; ks++) {
            uint32_t k0b = ks * 32;
            uint32_t Ah[2][4], Al[2][4], Bh[2][4], Bl[2][4];
#pragma unroll
            for (int mt = 0; mt < 2; mt++) {
                ldm_x4(Ah[mt][0], Ah[mt][1], Ah[mt][2], Ah[mt][3],
                       sPh + aoff + mt * 16 * (SSTR * 2) + k0b);
                ldm_x4(Al[mt][0], Al[mt][1], Al[mt][2], Al[mt][3],
                       sPl + aoff + mt * 16 * (SSTR * 2) + k0b);
            }
#pragma unroll
            for (int nt = 0; nt < 2; nt++) {
                ldm_x4(Bh[nt][0], Bh[nt][1], Bh[nt][2], Bh[nt][3],
                       sVh + boff + nt * 16 * (SSTR * 2) + k0b);
                ldm_x4(Bl[nt][0], Bl[nt][1], Bl[nt][2], Bl[nt][3],
                       sVl + boff + nt * 16 * (SSTR * 2) + k0b);
            }
#pragma unroll
            for (int mt = 0; mt < 2; mt++)
#pragma unroll
                for (int ns = 0; ns < 4; ns++) {
                    float* cc = c[mt][ns];
                    uint32_t* bh_ = &Bh[ns >> 1][(ns & 1) * 2];
                    uint32_t* bl_ = &Bl[ns >> 1][(ns & 1) * 2];
                    mma_bf16(cc[0], cc[1], cc[2], cc[3],
                             Ah[mt][0], Ah[mt][1], Ah[mt][2], Ah[mt][3], bh_[0], bh_[1]);
                    mma_bf16(cc[0], cc[1], cc[2], cc[3],
                             Ah[mt][0], Ah[mt][1], Ah[mt][2], Ah[mt][3], bl_[0], bl_[1]);
                    mma_bf16(cc[0], cc[1], cc[2], cc[3],
                             Al[mt][0], Al[mt][1], Al[mt][2], Al[mt][3], bh_[0], bh_[1]);
                }
        }
        __syncthreads();
    }

    float* dstb = outp + ((size_t)b * 1024 + l0) * 512 + h * 64;
#pragma unroll
    for (int mt = 0; mt < 2; mt++) {
        int r0 = wm + mt * 16 + (lane >> 2);
#pragma unroll
        for (int ns = 0; ns < 4; ns++) {
            int n = wn + ns * 8 + (lane & 3) * 2;
            *(float2*)&dstb[(size_t)r0 * 512 + n] = make_float2(c[mt][ns][0], c[mt][ns][1]);
            *(float2*)&dstb[(size_t)(r0 + 8) * 512 + n] = make_float2(c[mt][ns][2], c[mt][ns][3]);
        }
    }
}

// ---------------------------------------------------------------------------
extern "C" void kernel_launch(void* const* d_in, const int* in_sizes, int n_in,
                              void* d_out, int out_size) {
    const float* K     = (const float*)d_in[0];
    const float* Q     = (const float*)d_in[1];
    const float* V     = (const float*)d_in[2];
    const float* doc   = (const float*)d_in[3];
    const float* gamma = (const float*)d_in[4];
    const float* beta  = (const float*)d_in[5];
    // pad_mask / bx_packed derivable from doc_sizes; unused.

    float* outp = (float*)d_out;

    prep_kq_kernel<<<(BB * LL * DD) / 256, 256>>>(K, Q);
    prep_v_kernel<<<dim3(LL / 32, DD / 32, BB), dim3(32, 8)>>>(V);

    dim3 g1(LL / 128, LL / 128, BB * HH);      // (8, 8, 32)
    gemm1_kernel<<<g1, 256>>>(doc);

    dim3 g2(LL, BB);
    lnsm_kernel<<<g2, 256>>>(doc, gamma, beta);

    if (out_size >= BB * LL * DD + BB * LL) {
        float* wout = outp + (size_t)BB * LL * DD;
        wfin_kernel<<<BB, 1024>>>(doc, wout);
    }

    dim3 g3(LL / 128, HH, BB);                 // (8, 8, 4)
    gemm2_kernel<<<g3, 256>>>(doc, outp);
}

// round 12
// speedup vs baseline: 1.2752x; 1.0235x over previous
#include <cuda_runtime.h>
#include <cuda_bf16.h>
#include <cstdint>

#define BB 4
#define LL 1024
#define DD 512
#define HH 8
#define HD 64

// ---------------------------------------------------------------------------
// Device scratch (static: no allocations allowed)
__device__ __align__(256) float g_S[(size_t)BB * HH * LL * LL];           // 128 MB scores
__device__ __align__(256) __nv_bfloat16 g_Phi[(size_t)BB * HH * LL * LL]; // 64 MB (unnormalized e, hi)
__device__ __align__(256) __nv_bfloat16 g_Plo[(size_t)BB * HH * LL * LL]; // 64 MB (unnormalized e, lo)
__device__ __align__(256) __nv_bfloat16 g_Khi[(size_t)BB * HH * LL * HD];
__device__ __align__(256) __nv_bfloat16 g_Klo[(size_t)BB * HH * LL * HD];
__device__ __align__(256) __nv_bfloat16 g_Qhi[(size_t)BB * HH * LL * HD];
__device__ __align__(256) __nv_bfloat16 g_Qlo[(size_t)BB * HH * LL * HD];
__device__ __align__(256) __nv_bfloat16 g_Vthi[(size_t)BB * HH * HD * LL]; // [bh][d][m]
__device__ __align__(256) __nv_bfloat16 g_Vtlo[(size_t)BB * HH * HD * LL];
__device__ float g_wacc[BB * LL];
__device__ float g_inv[BB * HH * LL];    // per-(bh,l) softmax 1/sum (row scale)

// ---------------------------------------------------------------------------
__device__ __forceinline__ uint32_t smem_u32(const void* p) {
    uint32_t a;
    asm("{ .reg .u64 t; cvta.to.shared.u64 t, %1; cvt.u32.u64 %0, t; }" : "=r"(a) : "l"(p));
    return a;
}
__device__ __forceinline__ void ldm_x4(uint32_t& r0, uint32_t& r1, uint32_t& r2,
                                       uint32_t& r3, uint32_t addr) {
    asm volatile("ldmatrix.sync.aligned.m8n8.x4.shared.b16 {%0,%1,%2,%3}, [%4];"
                 : "=r"(r0), "=r"(r1), "=r"(r2), "=r"(r3) : "r"(addr));
}
__device__ __forceinline__ void mma_bf16(float& c0, float& c1, float& c2, float& c3,
                                         uint32_t a0, uint32_t a1, uint32_t a2, uint32_t a3,
                                         uint32_t b0, uint32_t b1) {
    asm volatile("mma.sync.aligned.m16n8k16.row.col.f32.bf16.bf16.f32 "
                 "{%0,%1,%2,%3}, {%4,%5,%6,%7}, {%8,%9}, {%0,%1,%2,%3};"
                 : "+f"(c0), "+f"(c1), "+f"(c2), "+f"(c3)
                 : "r"(a0), "r"(a1), "r"(a2), "r"(a3), "r"(b0), "r"(b1));
}

// smem row stride for MMA tiles: 40 bf16 = 80 B; conflict-free ldmatrix.
#define SSTR 40

__device__ __forceinline__ uint16_t bf16_bits(float f) {
    return __bfloat16_as_ushort(__float2bfloat16(f));
}

// ---------------------------------------------------------------------------
// Prep 1: split K,Q fp32 -> bf16 hi/lo in [bh][l][64] layout; zero wacc.
__global__ __launch_bounds__(256) void prep_kq_kernel(
    const float* __restrict__ Kp, const float* __restrict__ Qp)
{
    int idx = blockIdx.x * 256 + threadIdx.x;
    int k = idx & 63, h = (idx >> 6) & 7, l = (idx >> 9) & 1023, b = idx >> 19;
    size_t o = (((size_t)(b * 8 + h) * 1024 + l) << 6) | (unsigned)k;
    float kv = Kp[idx];
    __nv_bfloat16 khi = __float2bfloat16(kv);
    g_Khi[o] = khi;
    g_Klo[o] = __float2bfloat16(kv - __bfloat162float(khi));
    float qv = Qp[idx];
    __nv_bfloat16 qhi = __float2bfloat16(qv);
    g_Qhi[o] = qhi;
    g_Qlo[o] = __float2bfloat16(qv - __bfloat162float(qhi));
    if (idx < BB * LL) g_wacc[idx] = 0.f;
}

// Prep 2: transpose-split V [b][m][h*64+d] -> Vt hi/lo [bh][d][m]
__global__ __launch_bounds__(256) void prep_v_kernel(const float* __restrict__ Vp)
{
    __shared__ float t[32][33];
    int b = blockIdx.z;
    int m0 = blockIdx.x * 32, hd0 = blockIdx.y * 32;
    int tx = threadIdx.x, ty = threadIdx.y;   // (32, 8)
#pragma unroll
    for (int i = 0; i < 4; i++)
        t[ty + 8 * i][tx] = Vp[((size_t)b * 1024 + m0 + ty + 8 * i) * 512 + hd0 + tx];
    __syncthreads();
#pragma unroll
    for (int i = 0; i < 4; i++) {
        int hd = hd0 + ty + 8 * i;
        int h = hd >> 6, d = hd & 63;
        float x = t[tx][ty + 8 * i];
        __nv_bfloat16 hi = __float2bfloat16(x);
        size_t o = ((size_t)(b * 8 + h) * 64 + d) * 1024 + m0 + tx;
        g_Vthi[o] = hi;
        g_Vtlo[o] = __float2bfloat16(x - __bfloat162float(hi));
    }
}

// ---------------------------------------------------------------------------
// GEMM1 (mma.sync bf16): S[bh][l][m] = K[l,:]·Q[m,:], tile 128x128, K=64.
__global__ __launch_bounds__(256) void gemm1_kernel(const float* __restrict__ doc)
{
    __shared__ __nv_bfloat16 sA[2][128 * SSTR];
    __shared__ __nv_bfloat16 sB[2][128 * SSTR];

    int bh = blockIdx.z;
    int b = bh >> 3;
    int len = (int)doc[b];
    int l0 = blockIdx.y * 128, m0 = blockIdx.x * 128;
    if (l0 >= len || m0 >= len) return;

    int tid = threadIdx.x, wid = tid >> 5, lane = tid & 31;
    int wm = (wid >> 2) * 64, wn = (wid & 3) * 32;

    const uint4* srcA[2] = { (const uint4*)(g_Khi + ((size_t)bh * 1024 + l0) * 64),
                             (const uint4*)(g_Klo + ((size_t)bh * 1024 + l0) * 64) };
    const uint4* srcB[2] = { (const uint4*)(g_Qhi + ((size_t)bh * 1024 + m0) * 64),
                             (const uint4*)(g_Qlo + ((size_t)bh * 1024 + m0) * 64) };

    float c[4][4][4];
#pragma unroll
    for (int i = 0; i < 4; i++)
#pragma unroll
        for (int j = 0; j < 4; j++)
#pragma unroll
            for (int q = 0; q < 4; q++) c[i][j][q] = 0.f;

    uint32_t aoff = (uint32_t)(wm + (lane & 15)) * (SSTR * 2) + (((uint32_t)lane >> 4) << 4);
    uint32_t boff = (uint32_t)(wn + (lane & 7) + (((uint32_t)lane >> 4) << 3)) * (SSTR * 2)
                  + ((((uint32_t)lane >> 3) & 1) << 4);
    uint32_t sAh = smem_u32(&sA[0][0]), sAl = smem_u32(&sA[1][0]);
    uint32_t sBh = smem_u32(&sB[0][0]), sBl = smem_u32(&sB[1][0]);

    for (int kc = 0; kc < 64; kc += 32) {
        if (kc) __syncthreads();
#pragma unroll
        for (int e = 0; e < 2; e++) {
#pragma unroll
            for (int i = 0; i < 2; i++) {
                int idx = tid + i * 256;
                int row = idx >> 2, c4 = idx & 3;
                *(uint4*)((char*)&sA[e][0] + row * (SSTR * 2) + c4 * 16) =
                    srcA[e][(size_t)row * 8 + (kc >> 3) + c4];
                *(uint4*)((char*)&sB[e][0] + row * (SSTR * 2) + c4 * 16) =
                    srcB[e][(size_t)row * 8 + (kc >> 3) + c4];
            }
        }
        __syncthreads();

#pragma unroll
        for (int ks = 0; ks < 2; ks++) {
            uint32_t k0b = ks * 32;
            uint32_t Ah[4][4], Al[4][4], Bh[2][4], Bl[2][4];
#pragma unroll
            for (int mt = 0; mt < 4; mt++) {
                ldm_x4(Ah[mt][0], Ah[mt][1], Ah[mt][2], Ah[mt][3],
                       sAh + aoff + mt * 16 * (SSTR * 2) + k0b);
                ldm_x4(Al[mt][0], Al[mt][1], Al[mt][2], Al[mt][3],
                       sAl + aoff + mt * 16 * (SSTR * 2) + k0b);
            }
#pragma unroll
            for (int nt = 0; nt < 2; nt++) {
                ldm_x4(Bh[nt][0], Bh[nt][1], Bh[nt][2], Bh[nt][3],
                       sBh + boff + nt * 16 * (SSTR * 2) + k0b);
                ldm_x4(Bl[nt][0], Bl[nt][1], Bl[nt][2], Bl[nt][3],
                       sBl + boff + nt * 16 * (SSTR * 2) + k0b);
            }
#pragma unroll
            for (int mt = 0; mt < 4; mt++)
#pragma unroll
                for (int ns = 0; ns < 4; ns++) {
                    float* cc = c[mt][ns];
                    uint32_t* bh_ = &Bh[ns >> 1][(ns & 1) * 2];
                    uint32_t* bl_ = &Bl[ns >> 1][(ns & 1) * 2];
                    mma_bf16(cc[0], cc[1], cc[2], cc[3],
                             Ah[mt][0], Ah[mt][1], Ah[mt][2], Ah[mt][3], bh_[0], bh_[1]);
                    mma_bf16(cc[0], cc[1], cc[2], cc[3],
                             Ah[mt][0], Ah[mt][1], Ah[mt][2], Ah[mt][3], bl_[0], bl_[1]);
                    mma_bf16(cc[0], cc[1], cc[2], cc[3],
                             Al[mt][0], Al[mt][1], Al[mt][2], Al[mt][3], bh_[0], bh_[1]);
                }
        }
    }

    float* Sp = g_S + ((size_t)bh * 1024 + l0) * 1024 + m0;
#pragma unroll
    for (int mt = 0; mt < 4; mt++) {
        int r0 = wm + mt * 16 + (lane >> 2);
#pragma unroll
        for (int ns = 0; ns < 4; ns++) {
            int n = wn + ns * 8 + (lane & 3) * 2;
            *(float2*)&Sp[(size_t)r0 * 1024 + n] = make_float2(c[mt][ns][0], c[mt][ns][1]);
            *(float2*)&Sp[(size_t)(r0 + 8) * 1024 + n] = make_float2(c[mt][ns][2], c[mt][ns][3]);
        }
    }
}

// ---------------------------------------------------------------------------
// lnsm v7: R11 sweep structure (fastest measured) with two more sweeps deleted:
//  - softmax normalization sweep removed: emit UNNORMALIZED e; 1/sum goes to
//    g_inv and is applied in gemm2's epilogue (exact: per-row scalar).
//  - csum sweep merged into the emit sweep (m-outer, h-unrolled inner).
// Sweeps now: copy -> LN -> exp+sum (warp-per-head) -> emit(e hi/lo + csum).
// No max pass (LN-bounded input; shift-invariance; validated R9-R11).
__global__ __launch_bounds__(256) void lnsm_kernel(
    const float* __restrict__ doc, const float* __restrict__ gamma,
    const float* __restrict__ beta)
{
    __shared__ float s[HH][LL];   // 32 KB
    __shared__ float binv[HH];
    int b = blockIdx.y, l = blockIdx.x;
    int len = (int)doc[b];
    int kend  = (len + 63) & ~63;      // GEMM2 reads cols [0, kend)
    int lceil = (len + 127) & ~127;    // GEMM2 reads rows [0, lceil)
    int tid = threadIdx.x;

    if (l >= len) {
        if (l >= lceil) return;
        for (int h = 0; h < HH; ++h) {
            size_t o = ((size_t)(b * HH + h) * LL + l) * LL;
            for (int m = tid; m < kend; m += 256) {
                g_Phi[o + m] = __float2bfloat16(0.f);
                g_Plo[o + m] = __float2bfloat16(0.f);
            }
        }
        if (tid < HH) g_inv[(b * HH + tid) * LL + l] = 0.f;   // finite row scale
        return;
    }

    for (int h = 0; h < HH; ++h) {
        const float* Sr = g_S + ((size_t)(b * HH + h) * LL + l) * LL;
        for (int m = tid; m < len; m += 256) s[h][m] = Sr[m];
    }
    __syncthreads();

    float ga[HH], be[HH];
#pragma unroll
    for (int h = 0; h < HH; h++) { ga[h] = gamma[h]; be[h] = beta[h]; }

    for (int m = tid; m < len; m += 256) {
        float x[HH]; float mu = 0.f;
#pragma unroll
        for (int h = 0; h < HH; h++) { x[h] = s[h][m]; mu += x[h]; }
        mu *= (1.f / HH);
        float var = 0.f;
#pragma unroll
        for (int h = 0; h < HH; h++) { float d0 = x[h] - mu; var += d0 * d0; }
        var *= (1.f / HH);
        float rstd = rsqrtf(var + 1e-5f);
#pragma unroll
        for (int h = 0; h < HH; h++) s[h][m] = (x[h] - mu) * rstd * ga[h] + be[h];
    }
    __syncthreads();

    // exp in place + sum (warp w owns head w); no max, no normalization sweep
    {
        int w = tid >> 5, lane = tid & 31;
        float sum = 0.f;
        for (int m = lane; m < len; m += 32) {
            float e = __expf(s[w][m]);     // bounded by LN: no overflow risk
            s[w][m] = e; sum += e;
        }
#pragma unroll
        for (int o = 16; o; o >>= 1) sum += __shfl_xor_sync(0xffffffffu, sum, o);
        if (lane == 0) {
            float iv = 1.f / sum;
            binv[w] = iv;
            g_inv[(b * HH + w) * LL + l] = iv;
        }
    }
    __syncthreads();

    float iv[HH];
#pragma unroll
    for (int h = 0; h < HH; h++) iv[h] = binv[h];

    // emit unnormalized e as bf16 hi/lo + accumulate normalized column sums
    size_t obase = ((size_t)(b * HH) * LL + l) * LL;
    for (int m = tid; m < kend; m += 256) {
        bool valid = (m < len);
        float csum = 0.f;
#pragma unroll
        for (int h = 0; h < HH; h++) {
            float e = valid ? s[h][m] : 0.f;
            csum += e * iv[h];
            uint16_t hb = bf16_bits(e);
            float hf = __bfloat162float(__ushort_as_bfloat16(hb));
            uint16_t lb = bf16_bits(e - hf);
            size_t o = obase + ((size_t)h << 20) + m;
            g_Phi[o] = __ushort_as_bfloat16(hb);
            g_Plo[o] = __ushort_as_bfloat16(lb);
        }
        if (valid) atomicAdd(&g_wacc[b * LL + m], csum);
    }
}

// ---------------------------------------------------------------------------
// Finalize w: one 1024-thread block per batch, single pass.
__global__ __launch_bounds__(1024) void wfin_kernel(
    const float* __restrict__ doc, float* __restrict__ wout)
{
    __shared__ float red[32];
    __shared__ float s_bmax, s_inv;
    int b = blockIdx.x;
    int len = (int)doc[b];
    int tid = threadIdx.x, w = tid >> 5, lane = tid & 31;
    float scale = 1.f / (8.f * (float)len);

    float v = (tid < len) ? g_wacc[b * LL + tid] * scale : -1e30f;
    float mx = v;
#pragma unroll
    for (int o = 16; o; o >>= 1) mx = fmaxf(mx, __shfl_xor_sync(0xffffffffu, mx, o));
    if (lane == 0) red[w] = mx;
    __syncthreads();
    if (w == 0) {
        float t = red[lane];
#pragma unroll
        for (int o = 16; o; o >>= 1) t = fmaxf(t, __shfl_xor_sync(0xffffffffu, t, o));
        if (lane == 0) s_bmax = t;
    }
    __syncthreads();
    float e = (tid < len) ? __expf(v - s_bmax) : 0.f;
    float sum = e;
#pragma unroll
    for (int o = 16; o; o >>= 1) sum += __shfl_xor_sync(0xffffffffu, sum, o);
    if (lane == 0) red[w] = sum;
    __syncthreads();
    if (w == 0) {
        float t = red[lane];
#pragma unroll
        for (int o = 16; o; o >>= 1) t += __shfl_xor_sync(0xffffffffu, t, o);
        if (lane == 0) s_inv = 1.f / t;
    }
    __syncthreads();
    wout[b * LL + tid] = e * s_inv;
}

// ---------------------------------------------------------------------------
// GEMM2 (mma.sync bf16): out[l,d] = inv[l] * sum_m e[l,m]·Vt[d,m];
// tile 128(l) x 64(d), register-prefetch over K chunks of 32.
// Row scale g_inv applied in the epilogue (softmax normalization moved here).
__global__ __launch_bounds__(256) void gemm2_kernel(
    const float* __restrict__ doc, float* __restrict__ outp)
{
    __shared__ __nv_bfloat16 sP[2][128 * SSTR];
    __shared__ __nv_bfloat16 sV[2][64 * SSTR];

    int b = blockIdx.z, h = blockIdx.y;
    int bh = b * 8 + h;
    int len = (int)doc[b];
    int l0 = blockIdx.x * 128;
    int tid = threadIdx.x, wid = tid >> 5, lane = tid & 31;

    if (l0 >= len) {
        float* dst = outp + ((size_t)b * 1024 + l0 + (tid >> 1)) * 512 + h * 64;
        float4 z = make_float4(0, 0, 0, 0);
#pragma unroll
        for (int j = 0; j < 8; j++) ((float4*)dst)[(tid & 1) * 8 + j] = z;
        return;
    }

    int wm = (wid >> 1) * 32, wn = (wid & 1) * 32;

    const uint4* srcP[2] = { (const uint4*)(g_Phi + ((size_t)bh * 1024 + l0) * 1024),
                             (const uint4*)(g_Plo + ((size_t)bh * 1024 + l0) * 1024) };
    const uint4* srcV[2] = { (const uint4*)(g_Vthi + (size_t)bh * 64 * 1024),
                             (const uint4*)(g_Vtlo + (size_t)bh * 64 * 1024) };

    float c[2][4][4];
#pragma unroll
    for (int i = 0; i < 2; i++)
#pragma unroll
        for (int j = 0; j < 4; j++)
#pragma unroll
            for (int q = 0; q < 4; q++) c[i][j][q] = 0.f;

    uint32_t aoff = (uint32_t)(wm + (lane & 15)) * (SSTR * 2) + (((uint32_t)lane >> 4) << 4);
    uint32_t boff = (uint32_t)(wn + (lane & 7) + (((uint32_t)lane >> 4) << 3)) * (SSTR * 2)
                  + ((((uint32_t)lane >> 3) & 1) << 4);
    uint32_t sPh = smem_u32(&sP[0][0]), sPl = smem_u32(&sP[1][0]);
    uint32_t sVh = smem_u32(&sV[0][0]), sVl = smem_u32(&sV[1][0]);

    int prow = tid >> 2, pc4 = tid & 3;
    int vrow = tid >> 2, vc4 = tid & 3;
    char* stP[2][2];
    char* stV[2];
#pragma unroll
    for (int e = 0; e < 2; e++) {
        stP[e][0] = (char*)&sP[e][0] + prow * (SSTR * 2) + pc4 * 16;
        stP[e][1] = (char*)&sP[e][0] + (prow + 64) * (SSTR * 2) + pc4 * 16;
        stV[e]    = (char*)&sV[e][0] + vrow * (SSTR * 2) + vc4 * 16;
    }

    int kend = (len + 31) & ~31;
    int nch = kend >> 5;

    uint4 rp[2][2], rv[2];
#pragma unroll
    for (int e = 0; e < 2; e++) {
        rp[e][0] = srcP[e][(size_t)prow * 128 + pc4];
        rp[e][1] = srcP[e][(size_t)(prow + 64) * 128 + pc4];
        rv[e]    = srcV[e][(size_t)vrow * 128 + vc4];
    }

    for (int ch = 0; ch < nch; ++ch) {
#pragma unroll
        for (int e = 0; e < 2; e++) {
            *(uint4*)stP[e][0] = rp[e][0];
            *(uint4*)stP[e][1] = rp[e][1];
            *(uint4*)stV[e]    = rv[e];
        }
        __syncthreads();

        if (ch + 1 < nch) {
            int mq = (ch + 1) * 4;
#pragma unroll
            for (int e = 0; e < 2; e++) {
                rp[e][0] = srcP[e][(size_t)prow * 128 + mq + pc4];
                rp[e][1] = srcP[e][(size_t)(prow + 64) * 128 + mq + pc4];
                rv[e]    = srcV[e][(size_t)vrow * 128 + mq + vc4];
            }
        }

#pragma unroll
        for (int ks = 0; ks < 2; ks++) {
            uint32_t k0b = ks * 32;
            uint32_t Ah[2][4], Al[2][4], Bh[2][4], Bl[2][4];
#pragma unroll
            for (int mt = 0; mt < 2; mt++) {
                ldm_x4(Ah[mt][0], Ah[mt][1], Ah[mt][2], Ah[mt][3],
                       sPh + aoff + mt * 16 * (SSTR * 2) + k0b);
                ldm_x4(Al[mt][0], Al[mt][1], Al[mt][2], Al[mt][3],
                       sPl + aoff + mt * 16 * (SSTR * 2) + k0b);
            }
#pragma unroll
            for (int nt = 0; nt < 2; nt++) {
                ldm_x4(Bh[nt][0], Bh[nt][1], Bh[nt][2], Bh[nt][3],
                       sVh + boff + nt * 16 * (SSTR * 2) + k0b);
                ldm_x4(Bl[nt][0], Bl[nt][1], Bl[nt][2], Bl[nt][3],
                       sVl + boff + nt * 16 * (SSTR * 2) + k0b);
            }
#pragma unroll
            for (int mt = 0; mt < 2; mt++)
#pragma unroll
                for (int ns = 0; ns < 4; ns++) {
                    float* cc = c[mt][ns];
                    uint32_t* bh_ = &Bh[ns >> 1][(ns & 1) * 2];
                    uint32_t* bl_ = &Bl[ns >> 1][(ns & 1) * 2];
                    mma_bf16(cc[0], cc[1], cc[2], cc[3],
                             Ah[mt][0], Ah[mt][1], Ah[mt][2], Ah[mt][3], bh_[0], bh_[1]);
                    mma_bf16(cc[0], cc[1], cc[2], cc[3],
                             Ah[mt][0], Ah[mt][1], Ah[mt][2], Ah[mt][3], bl_[0], bl_[1]);
                    mma_bf16(cc[0], cc[1], cc[2], cc[3],
                             Al[mt][0], Al[mt][1], Al[mt][2], Al[mt][3], bh_[0], bh_[1]);
                }
        }
        __syncthreads();
    }

    const float* ginv = g_inv + (size_t)bh * 1024 + l0;
    float* dstb = outp + ((size_t)b * 1024 + l0) * 512 + h * 64;
#pragma unroll
    for (int mt = 0; mt < 2; mt++) {
        int r0 = wm + mt * 16 + (lane >> 2);
        float ia = ginv[r0], ib = ginv[r0 + 8];
#pragma unroll
        for (int ns = 0; ns < 4; ns++) {
            int n = wn + ns * 8 + (lane & 3) * 2;
            *(float2*)&dstb[(size_t)r0 * 512 + n] =
                make_float2(c[mt][ns][0] * ia, c[mt][ns][1] * ia);
            *(float2*)&dstb[(size_t)(r0 + 8) * 512 + n] =
                make_float2(c[mt][ns][2] * ib, c[mt][ns][3] * ib);
        }
    }
}

// ---------------------------------------------------------------------------
extern "C" void kernel_launch(void* const* d_in, const int* in_sizes, int n_in,
                              void* d_out, int out_size) {
    const float* K     = (const float*)d_in[0];
    const float* Q     = (const float*)d_in[1];
    const float* V     = (const float*)d_in[2];
    const float* doc   = (const float*)d_in[3];
    const float* gamma = (const float*)d_in[4];
    const float* beta  = (const float*)d_in[5];
    // pad_mask / bx_packed derivable from doc_sizes; unused.

    float* outp = (float*)d_out;

    prep_kq_kernel<<<(BB * LL * DD) / 256, 256>>>(K, Q);
    prep_v_kernel<<<dim3(LL / 32, DD / 32, BB), dim3(32, 8)>>>(V);

    dim3 g1(LL / 128, LL / 128, BB * HH);      // (8, 8, 32)
    gemm1_kernel<<<g1, 256>>>(doc);

    dim3 g2(LL, BB);
    lnsm_kernel<<<g2, 256>>>(doc, gamma, beta);

    if (out_size >= BB * LL * DD + BB * LL) {
        float* wout = outp + (size_t)BB * LL * DD;
        wfin_kernel<<<BB, 1024>>>(doc, wout);
    }

    dim3 g3(LL / 128, HH, BB);                 // (8, 8, 4)
    gemm2_kernel<<<g3, 256>>>(doc, outp);
}

// round 13
// speedup vs baseline: 1.3869x; 1.0876x over previous
#include <cuda_runtime.h>
#include <cuda_bf16.h>
#include <cstdint>

#define BB 4
#define LL 1024
#define DD 512
#define HH 8
#define HD 64

// ---------------------------------------------------------------------------
// Device scratch (static: no allocations allowed)
__device__ __align__(256) float g_S[(size_t)BB * HH * LL * LL];           // 128 MB scores
__device__ __align__(256) __nv_bfloat16 g_Phi[(size_t)BB * HH * LL * LL]; // 64 MB (unnormalized e, hi)
__device__ __align__(256) __nv_bfloat16 g_Plo[(size_t)BB * HH * LL * LL]; // 64 MB (unnormalized e, lo)
__device__ __align__(256) __nv_bfloat16 g_Khi[(size_t)BB * HH * LL * HD];
__device__ __align__(256) __nv_bfloat16 g_Klo[(size_t)BB * HH * LL * HD];
__device__ __align__(256) __nv_bfloat16 g_Qhi[(size_t)BB * HH * LL * HD];
__device__ __align__(256) __nv_bfloat16 g_Qlo[(size_t)BB * HH * LL * HD];
__device__ __align__(256) __nv_bfloat16 g_Vthi[(size_t)BB * HH * HD * LL]; // [bh][d][m]
__device__ __align__(256) __nv_bfloat16 g_Vtlo[(size_t)BB * HH * HD * LL];
__device__ float g_wacc[BB * LL];
__device__ float g_inv[BB * HH * LL];    // per-(bh,l) softmax 1/sum (row scale)

// ---------------------------------------------------------------------------
__device__ __forceinline__ uint32_t smem_u32(const void* p) {
    uint32_t a;
    asm("{ .reg .u64 t; cvta.to.shared.u64 t, %1; cvt.u32.u64 %0, t; }" : "=r"(a) : "l"(p));
    return a;
}
__device__ __forceinline__ void ldm_x4(uint32_t& r0, uint32_t& r1, uint32_t& r2,
                                       uint32_t& r3, uint32_t addr) {
    asm volatile("ldmatrix.sync.aligned.m8n8.x4.shared.b16 {%0,%1,%2,%3}, [%4];"
                 : "=r"(r0), "=r"(r1), "=r"(r2), "=r"(r3) : "r"(addr));
}
__device__ __forceinline__ void mma_bf16(float& c0, float& c1, float& c2, float& c3,
                                         uint32_t a0, uint32_t a1, uint32_t a2, uint32_t a3,
                                         uint32_t b0, uint32_t b1) {
    asm volatile("mma.sync.aligned.m16n8k16.row.col.f32.bf16.bf16.f32 "
                 "{%0,%1,%2,%3}, {%4,%5,%6,%7}, {%8,%9}, {%0,%1,%2,%3};"
                 : "+f"(c0), "+f"(c1), "+f"(c2), "+f"(c3)
                 : "r"(a0), "r"(a1), "r"(a2), "r"(a3), "r"(b0), "r"(b1));
}
#define CP_ASYNC16(dst, src) \
    asm volatile("cp.async.cg.shared.global [%0], [%1], 16;" :: "r"(dst), "l"(src))
#define CP_COMMIT()  asm volatile("cp.async.commit_group;" ::: "memory")
#define CP_WAIT(n)   asm volatile("cp.async.wait_group %0;" :: "n"(n) : "memory")

// smem row stride for MMA tiles: 40 bf16 = 80 B; conflict-free ldmatrix.
#define SSTR 40

__device__ __forceinline__ uint16_t bf16_bits(float f) {
    return __bfloat16_as_ushort(__float2bfloat16(f));
}

// ---------------------------------------------------------------------------
// Prep 1: split K,Q fp32 -> bf16 hi/lo in [bh][l][64] layout; zero wacc.
__global__ __launch_bounds__(256) void prep_kq_kernel(
    const float* __restrict__ Kp, const float* __restrict__ Qp)
{
    int idx = blockIdx.x * 256 + threadIdx.x;
    int k = idx & 63, h = (idx >> 6) & 7, l = (idx >> 9) & 1023, b = idx >> 19;
    size_t o = (((size_t)(b * 8 + h) * 1024 + l) << 6) | (unsigned)k;
    float kv = Kp[idx];
    __nv_bfloat16 khi = __float2bfloat16(kv);
    g_Khi[o] = khi;
    g_Klo[o] = __float2bfloat16(kv - __bfloat162float(khi));
    float qv = Qp[idx];
    __nv_bfloat16 qhi = __float2bfloat16(qv);
    g_Qhi[o] = qhi;
    g_Qlo[o] = __float2bfloat16(qv - __bfloat162float(qhi));
    if (idx < BB * LL) g_wacc[idx] = 0.f;
}

// Prep 2: transpose-split V [b][m][h*64+d] -> Vt hi/lo [bh][d][m]
__global__ __launch_bounds__(256) void prep_v_kernel(const float* __restrict__ Vp)
{
    __shared__ float t[32][33];
    int b = blockIdx.z;
    int m0 = blockIdx.x * 32, hd0 = blockIdx.y * 32;
    int tx = threadIdx.x, ty = threadIdx.y;   // (32, 8)
#pragma unroll
    for (int i = 0; i < 4; i++)
        t[ty + 8 * i][tx] = Vp[((size_t)b * 1024 + m0 + ty + 8 * i) * 512 + hd0 + tx];
    __syncthreads();
#pragma unroll
    for (int i = 0; i < 4; i++) {
        int hd = hd0 + ty + 8 * i;
        int h = hd >> 6, d = hd & 63;
        float x = t[tx][ty + 8 * i];
        __nv_bfloat16 hi = __float2bfloat16(x);
        size_t o = ((size_t)(b * 8 + h) * 64 + d) * 1024 + m0 + tx;
        g_Vthi[o] = hi;
        g_Vtlo[o] = __float2bfloat16(x - __bfloat162float(hi));
    }
}

// ---------------------------------------------------------------------------
// GEMM1 (mma.sync bf16): S[bh][l][m] = K[l,:]·Q[m,:], tile 128x128, K=64.
// cp.async double-buffer: both K-chunks issued up front; chunk-1 copy overlaps
// chunk-0 compute. Epilogue stores culled to l<len && m<len (consumers read
// only that region). Dynamic smem: 2 chunks x 4 arrays x 128 x SSTR bf16.
#define G1_CHUNK (4 * 128 * SSTR * 2)             // 40960 B per chunk
#define G1_SMEM  (2 * G1_CHUNK)                   // 81920 B
__global__ __launch_bounds__(256) void gemm1_kernel(const float* __restrict__ doc)
{
    extern __shared__ __align__(16) char dsm[];

    int bh = blockIdx.z;
    int b = bh >> 3;
    int len = (int)doc[b];
    int l0 = blockIdx.y * 128, m0 = blockIdx.x * 128;
    if (l0 >= len || m0 >= len) return;

    int tid = threadIdx.x, wid = tid >> 5, lane = tid & 31;
    int wm = (wid >> 2) * 64, wn = (wid & 3) * 32;
    uint32_t sbase = smem_u32(dsm);

    const uint4* srcs[4] = {
        (const uint4*)(g_Khi + ((size_t)bh * 1024 + l0) * 64),
        (const uint4*)(g_Klo + ((size_t)bh * 1024 + l0) * 64),
        (const uint4*)(g_Qhi + ((size_t)bh * 1024 + m0) * 64),
        (const uint4*)(g_Qlo + ((size_t)bh * 1024 + m0) * 64) };

    // Issue BOTH chunks' copies via cp.async (no register staging).
    int row = tid >> 2, c4 = tid & 3;             // each thread: rows {row, row+64}
#pragma unroll
    for (int ch = 0; ch < 2; ch++) {
#pragma unroll
        for (int e = 0; e < 4; e++) {
            uint32_t dbase = sbase + ch * G1_CHUNK + e * (128 * SSTR * 2);
            CP_ASYNC16(dbase + row * (SSTR * 2) + c4 * 16,
                       srcs[e] + (size_t)row * 8 + ch * 4 + c4);
            CP_ASYNC16(dbase + (row + 64) * (SSTR * 2) + c4 * 16,
                       srcs[e] + (size_t)(row + 64) * 8 + ch * 4 + c4);
        }
        CP_COMMIT();
    }

    float c[4][4][4];
#pragma unroll
    for (int i = 0; i < 4; i++)
#pragma unroll
        for (int j = 0; j < 4; j++)
#pragma unroll
            for (int q = 0; q < 4; q++) c[i][j][q] = 0.f;

    uint32_t aoff = (uint32_t)(wm + (lane & 15)) * (SSTR * 2) + (((uint32_t)lane >> 4) << 4);
    uint32_t boff = (uint32_t)(wn + (lane & 7) + (((uint32_t)lane >> 4) << 3)) * (SSTR * 2)
                  + ((((uint32_t)lane >> 3) & 1) << 4);

#pragma unroll
    for (int ch = 0; ch < 2; ch++) {
        if (ch == 0) { CP_WAIT(1); } else { CP_WAIT(0); }
        __syncthreads();
        uint32_t sAh = sbase + ch * G1_CHUNK;
        uint32_t sAl = sAh + 128 * SSTR * 2;
        uint32_t sBh = sAl + 128 * SSTR * 2;
        uint32_t sBl = sBh + 128 * SSTR * 2;

#pragma unroll
        for (int ks = 0; ks < 2; ks++) {
            uint32_t k0b = ks * 32;
            uint32_t Ah[4][4], Al[4][4], Bh[2][4], Bl[2][4];
#pragma unroll
            for (int mt = 0; mt < 4; mt++) {
                ldm_x4(Ah[mt][0], Ah[mt][1], Ah[mt][2], Ah[mt][3],
                       sAh + aoff + mt * 16 * (SSTR * 2) + k0b);
                ldm_x4(Al[mt][0], Al[mt][1], Al[mt][2], Al[mt][3],
                       sAl + aoff + mt * 16 * (SSTR * 2) + k0b);
            }
#pragma unroll
            for (int nt = 0; nt < 2; nt++) {
                ldm_x4(Bh[nt][0], Bh[nt][1], Bh[nt][2], Bh[nt][3],
                       sBh + boff + nt * 16 * (SSTR * 2) + k0b);
                ldm_x4(Bl[nt][0], Bl[nt][1], Bl[nt][2], Bl[nt][3],
                       sBl + boff + nt * 16 * (SSTR * 2) + k0b);
            }
#pragma unroll
            for (int mt = 0; mt < 4; mt++)
#pragma unroll
                for (int ns = 0; ns < 4; ns++) {
                    float* cc = c[mt][ns];
                    uint32_t* bh_ = &Bh[ns >> 1][(ns & 1) * 2];
                    uint32_t* bl_ = &Bl[ns >> 1][(ns & 1) * 2];
                    mma_bf16(cc[0], cc[1], cc[2], cc[3],
                             Ah[mt][0], Ah[mt][1], Ah[mt][2], Ah[mt][3], bh_[0], bh_[1]);
                    mma_bf16(cc[0], cc[1], cc[2], cc[3],
                             Ah[mt][0], Ah[mt][1], Ah[mt][2], Ah[mt][3], bl_[0], bl_[1]);
                    mma_bf16(cc[0], cc[1], cc[2], cc[3],
                             Al[mt][0], Al[mt][1], Al[mt][2], Al[mt][3], bh_[0], bh_[1]);
                }
        }
        if (ch == 0) __syncthreads();   // all reads of chunk0 done (buffers distinct, but cheap safety for scheduling)
    }

    // epilogue: store only rows l<len and cols m<len (downstream reads only those)
    float* Sp = g_S + ((size_t)bh * 1024 + l0) * 1024 + m0;
    int rlim = len - l0, nlim = len - m0;   // > 0 guaranteed by early-exit
#pragma unroll
    for (int mt = 0; mt < 4; mt++) {
        int r0 = wm + mt * 16 + (lane >> 2);
#pragma unroll
        for (int ns = 0; ns < 4; ns++) {
            int n = wn + ns * 8 + (lane & 3) * 2;
            if (n < nlim) {
                if (r0 < rlim)
                    *(float2*)&Sp[(size_t)r0 * 1024 + n] =
                        make_float2(c[mt][ns][0], c[mt][ns][1]);
                if (r0 + 8 < rlim)
                    *(float2*)&Sp[(size_t)(r0 + 8) * 1024 + n] =
                        make_float2(c[mt][ns][2], c[mt][ns][3]);
            }
        }
    }
}

// ---------------------------------------------------------------------------
// lnsm v7 (R12, measured 66.7us): copy -> LN -> exp+sum -> emit(e hi/lo + csum).
// No max pass; normalization deferred to gemm2 via g_inv.
__global__ __launch_bounds__(256) void lnsm_kernel(
    const float* __restrict__ doc, const float* __restrict__ gamma,
    const float* __restrict__ beta)
{
    __shared__ float s[HH][LL];   // 32 KB
    __shared__ float binv[HH];
    int b = blockIdx.y, l = blockIdx.x;
    int len = (int)doc[b];
    int kend  = (len + 63) & ~63;
    int lceil = (len + 127) & ~127;
    int tid = threadIdx.x;

    if (l >= len) {
        if (l >= lceil) return;
        for (int h = 0; h < HH; ++h) {
            size_t o = ((size_t)(b * HH + h) * LL + l) * LL;
            for (int m = tid; m < kend; m += 256) {
                g_Phi[o + m] = __float2bfloat16(0.f);
                g_Plo[o + m] = __float2bfloat16(0.f);
            }
        }
        if (tid < HH) g_inv[(b * HH + tid) * LL + l] = 0.f;
        return;
    }

    for (int h = 0; h < HH; ++h) {
        const float* Sr = g_S + ((size_t)(b * HH + h) * LL + l) * LL;
        for (int m = tid; m < len; m += 256) s[h][m] = Sr[m];
    }
    __syncthreads();

    float ga[HH], be[HH];
#pragma unroll
    for (int h = 0; h < HH; h++) { ga[h] = gamma[h]; be[h] = beta[h]; }

    for (int m = tid; m < len; m += 256) {
        float x[HH]; float mu = 0.f;
#pragma unroll
        for (int h = 0; h < HH; h++) { x[h] = s[h][m]; mu += x[h]; }
        mu *= (1.f / HH);
        float var = 0.f;
#pragma unroll
        for (int h = 0; h < HH; h++) { float d0 = x[h] - mu; var += d0 * d0; }
        var *= (1.f / HH);
        float rstd = rsqrtf(var + 1e-5f);
#pragma unroll
        for (int h = 0; h < HH; h++) s[h][m] = (x[h] - mu) * rstd * ga[h] + be[h];
    }
    __syncthreads();

    {
        int w = tid >> 5, lane = tid & 31;
        float sum = 0.f;
        for (int m = lane; m < len; m += 32) {
            float e = __expf(s[w][m]);
            s[w][m] = e; sum += e;
        }
#pragma unroll
        for (int o = 16; o; o >>= 1) sum += __shfl_xor_sync(0xffffffffu, sum, o);
        if (lane == 0) {
            float iv = 1.f / sum;
            binv[w] = iv;
            g_inv[(b * HH + w) * LL + l] = iv;
        }
    }
    __syncthreads();

    float iv[HH];
#pragma unroll
    for (int h = 0; h < HH; h++) iv[h] = binv[h];

    size_t obase = ((size_t)(b * HH) * LL + l) * LL;
    for (int m = tid; m < kend; m += 256) {
        bool valid = (m < len);
        float csum = 0.f;
#pragma unroll
        for (int h = 0; h < HH; h++) {
            float e = valid ? s[h][m] : 0.f;
            csum += e * iv[h];
            uint16_t hb = bf16_bits(e);
            float hf = __bfloat162float(__ushort_as_bfloat16(hb));
            uint16_t lb = bf16_bits(e - hf);
            size_t o = obase + ((size_t)h << 20) + m;
            g_Phi[o] = __ushort_as_bfloat16(hb);
            g_Plo[o] = __ushort_as_bfloat16(lb);
        }
        if (valid) atomicAdd(&g_wacc[b * LL + m], csum);
    }
}

// ---------------------------------------------------------------------------
// Finalize w: one 1024-thread block per batch, single pass.
__global__ __launch_bounds__(1024) void wfin_kernel(
    const float* __restrict__ doc, float* __restrict__ wout)
{
    __shared__ float red[32];
    __shared__ float s_bmax, s_inv;
    int b = blockIdx.x;
    int len = (int)doc[b];
    int tid = threadIdx.x, w = tid >> 5, lane = tid & 31;
    float scale = 1.f / (8.f * (float)len);

    float v = (tid < len) ? g_wacc[b * LL + tid] * scale : -1e30f;
    float mx = v;
#pragma unroll
    for (int o = 16; o; o >>= 1) mx = fmaxf(mx, __shfl_xor_sync(0xffffffffu, mx, o));
    if (lane == 0) red[w] = mx;
    __syncthreads();
    if (w == 0) {
        float t = red[lane];
#pragma unroll
        for (int o = 16; o; o >>= 1) t = fmaxf(t, __shfl_xor_sync(0xffffffffu, t, o));
        if (lane == 0) s_bmax = t;
    }
    __syncthreads();
    float e = (tid < len) ? __expf(v - s_bmax) : 0.f;
    float sum = e;
#pragma unroll
    for (int o = 16; o; o >>= 1) sum += __shfl_xor_sync(0xffffffffu, sum, o);
    if (lane == 0) red[w] = sum;
    __syncthreads();
    if (w == 0) {
        float t = red[lane];
#pragma unroll
        for (int o = 16; o; o >>= 1) t += __shfl_xor_sync(0xffffffffu, t, o);
        if (lane == 0) s_inv = 1.f / t;
    }
    __syncthreads();
    wout[b * LL + tid] = e * s_inv;
}

// ---------------------------------------------------------------------------
// GEMM2 (mma.sync bf16): out[l,d] = inv[l] * sum_m e[l,m]·Vt[d,m];
// tile 128(l) x 64(d), register-prefetch over K chunks of 32.
__global__ __launch_bounds__(256) void gemm2_kernel(
    const float* __restrict__ doc, float* __restrict__ outp)
{
    __shared__ __nv_bfloat16 sP[2][128 * SSTR];
    __shared__ __nv_bfloat16 sV[2][64 * SSTR];

    int b = blockIdx.z, h = blockIdx.y;
    int bh = b * 8 + h;
    int len = (int)doc[b];
    int l0 = blockIdx.x * 128;
    int tid = threadIdx.x, wid = tid >> 5, lane = tid & 31;

    if (l0 >= len) {
        float* dst = outp + ((size_t)b * 1024 + l0 + (tid >> 1)) * 512 + h * 64;
        float4 z = make_float4(0, 0, 0, 0);
#pragma unroll
        for (int j = 0; j < 8; j++) ((float4*)dst)[(tid & 1) * 8 + j] = z;
        return;
    }

    int wm = (wid >> 1) * 32, wn = (wid & 1) * 32;

    const uint4* srcP[2] = { (const uint4*)(g_Phi + ((size_t)bh * 1024 + l0) * 1024),
                             (const uint4*)(g_Plo + ((size_t)bh * 1024 + l0) * 1024) };
    const uint4* srcV[2] = { (const uint4*)(g_Vthi + (size_t)bh * 64 * 1024),
                             (const uint4*)(g_Vtlo + (size_t)bh * 64 * 1024) };

    float c[2][4][4];
#pragma unroll
    for (int i = 0; i < 2; i++)
#pragma unroll
        for (int j = 0; j < 4; j++)
#pragma unroll
            for (int q = 0; q < 4; q++) c[i][j][q] = 0.f;

    uint32_t aoff = (uint32_t)(wm + (lane & 15)) * (SSTR * 2) + (((uint32_t)lane >> 4) << 4);
    uint32_t boff = (uint32_t)(wn + (lane & 7) + (((uint32_t)lane >> 4) << 3)) * (SSTR * 2)
                  + ((((uint32_t)lane >> 3) & 1) << 4);
    uint32_t sPh = smem_u32(&sP[0][0]), sPl = smem_u32(&sP[1][0]);
    uint32_t sVh = smem_u32(&sV[0][0]), sVl = smem_u32(&sV[1][0]);

    int prow = tid >> 2, pc4 = tid & 3;
    int vrow = tid >> 2, vc4 = tid & 3;
    char* stP[2][2];
    char* stV[2];
#pragma unroll
    for (int e = 0; e < 2; e++) {
        stP[e][0] = (char*)&sP[e][0] + prow * (SSTR * 2) + pc4 * 16;
        stP[e][1] = (char*)&sP[e][0] + (prow + 64) * (SSTR * 2) + pc4 * 16;
        stV[e]    = (char*)&sV[e][0] + vrow * (SSTR * 2) + vc4 * 16;
    }

    int kend = (len + 31) & ~31;
    int nch = kend >> 5;

    uint4 rp[2][2], rv[2];
#pragma unroll
    for (int e = 0; e < 2; e++) {
        rp[e][0] = srcP[e][(size_t)prow * 128 + pc4];
        rp[e][1] = srcP[e][(size_t)(prow + 64) * 128 + pc4];
        rv[e]    = srcV[e][(size_t)vrow * 128 + vc4];
    }

    for (int ch = 0; ch < nch; ++ch) {
#pragma unroll
        for (int e = 0; e < 2; e++) {
            *(uint4*)stP[e][0] = rp[e][0];
            *(uint4*)stP[e][1] = rp[e][1];
            *(uint4*)stV[e]    = rv[e];
        }
        __syncthreads();

        if (ch + 1 < nch) {
            int mq = (ch + 1) * 4;
#pragma unroll
            for (int e = 0; e < 2; e++) {
                rp[e][0] = srcP[e][(size_t)prow * 128 + mq + pc4];
                rp[e][1] = srcP[e][(size_t)(prow + 64) * 128 + mq + pc4];
                rv[e]    = srcV[e][(size_t)vrow * 128 + mq + vc4];
            }
        }

#pragma unroll
        for (int ks = 0; ks < 2; ks++) {
            uint32_t k0b = ks * 32;
            uint32_t Ah[2][4], Al[2][4], Bh[2][4], Bl[2][4];
#pragma unroll
            for (int mt = 0; mt < 2; mt++) {
                ldm_x4(Ah[mt][0], Ah[mt][1], Ah[mt][2], Ah[mt][3],
                       sPh + aoff + mt * 16 * (SSTR * 2) + k0b);
                ldm_x4(Al[mt][0], Al[mt][1], Al[mt][2], Al[mt][3],
                       sPl + aoff + mt * 16 * (SSTR * 2) + k0b);
            }
#pragma unroll
            for (int nt = 0; nt < 2; nt++) {
                ldm_x4(Bh[nt][0], Bh[nt][1], Bh[nt][2], Bh[nt][3],
                       sVh + boff + nt * 16 * (SSTR * 2) + k0b);
                ldm_x4(Bl[nt][0], Bl[nt][1], Bl[nt][2], Bl[nt][3],
                       sVl + boff + nt * 16 * (SSTR * 2) + k0b);
            }
#pragma unroll
            for (int mt = 0; mt < 2; mt++)
#pragma unroll
                for (int ns = 0; ns < 4; ns++) {
                    float* cc = c[mt][ns];
                    uint32_t* bh_ = &Bh[ns >> 1][(ns & 1) * 2];
                    uint32_t* bl_ = &Bl[ns >> 1][(ns & 1) * 2];
                    mma_bf16(cc[0], cc[1], cc[2], cc[3],
                             Ah[mt][0], Ah[mt][1], Ah[mt][2], Ah[mt][3], bh_[0], bh_[1]);
                    mma_bf16(cc[0], cc[1], cc[2], cc[3],
                             Ah[mt][0], Ah[mt][1], Ah[mt][2], Ah[mt][3], bl_[0], bl_[1]);
                    mma_bf16(cc[0], cc[1], cc[2], cc[3],
                             Al[mt][0], Al[mt][1], Al[mt][2], Al[mt][3], bh_[0], bh_[1]);
                }
        }
        __syncthreads();
    }

    const float* ginv = g_inv + (size_t)bh * 1024 + l0;
    float* dstb = outp + ((size_t)b * 1024 + l0) * 512 + h * 64;
#pragma unroll
    for (int mt = 0; mt < 2; mt++) {
        int r0 = wm + mt * 16 + (lane >> 2);
        float ia = ginv[r0], ib = ginv[r0 + 8];
#pragma unroll
        for (int ns = 0; ns < 4; ns++) {
            int n = wn + ns * 8 + (lane & 3) * 2;
            *(float2*)&dstb[(size_t)r0 * 512 + n] =
                make_float2(c[mt][ns][0] * ia, c[mt][ns][1] * ia);
            *(float2*)&dstb[(size_t)(r0 + 8) * 512 + n] =
                make_float2(c[mt][ns][2] * ib, c[mt][ns][3] * ib);
        }
    }
}

// ---------------------------------------------------------------------------
extern "C" void kernel_launch(void* const* d_in, const int* in_sizes, int n_in,
                              void* d_out, int out_size) {
    const float* K     = (const float*)d_in[0];
    const float* Q     = (const float*)d_in[1];
    const float* V     = (const float*)d_in[2];
    const float* doc   = (const float*)d_in[3];
    const float* gamma = (const float*)d_in[4];
    const float* beta  = (const float*)d_in[5];
    // pad_mask / bx_packed derivable from doc_sizes; unused.

    float* outp = (float*)d_out;

    cudaFuncSetAttribute(gemm1_kernel,
                         cudaFuncAttributeMaxDynamicSharedMemorySize, G1_SMEM);

    prep_kq_kernel<<<(BB * LL * DD) / 256, 256>>>(K, Q);
    prep_v_kernel<<<dim3(LL / 32, DD / 32, BB), dim3(32, 8)>>>(V);

    dim3 g1(LL / 128, LL / 128, BB * HH);      // (8, 8, 32)
    gemm1_kernel<<<g1, 256, G1_SMEM>>>(doc);

    dim3 g2(LL, BB);
    lnsm_kernel<<<g2, 256>>>(doc, gamma, beta);

    if (out_size >= BB * LL * DD + BB * LL) {
        float* wout = outp + (size_t)BB * LL * DD;
        wfin_kernel<<<BB, 1024>>>(doc, wout);
    }

    dim3 g3(LL / 128, HH, BB);                 // (8, 8, 4)
    gemm2_kernel<<<g3, 256>>>(doc, outp);
}

// round 14
// speedup vs baseline: 1.4417x; 1.0395x over previous
#include <cuda_runtime.h>
#include <cuda_bf16.h>
#include <cstdint>

#define BB 4
#define LL 1024
#define DD 512
#define HH 8
#define HD 64

// ---------------------------------------------------------------------------
// Device scratch (static: no allocations allowed)
__device__ __align__(256) float g_S[(size_t)BB * HH * LL * LL];           // 128 MB scores
__device__ __align__(256) __nv_bfloat16 g_Phi[(size_t)BB * HH * LL * LL]; // 64 MB (unnormalized e, hi)
__device__ __align__(256) __nv_bfloat16 g_Plo[(size_t)BB * HH * LL * LL]; // 64 MB (unnormalized e, lo)
__device__ __align__(256) __nv_bfloat16 g_Khi[(size_t)BB * HH * LL * HD];
__device__ __align__(256) __nv_bfloat16 g_Klo[(size_t)BB * HH * LL * HD];
__device__ __align__(256) __nv_bfloat16 g_Qhi[(size_t)BB * HH * LL * HD];
__device__ __align__(256) __nv_bfloat16 g_Qlo[(size_t)BB * HH * LL * HD];
__device__ __align__(256) __nv_bfloat16 g_Vthi[(size_t)BB * HH * HD * LL]; // [bh][d][m]
__device__ __align__(256) __nv_bfloat16 g_Vtlo[(size_t)BB * HH * HD * LL];
__device__ float g_wacc[BB * LL];
__device__ float g_inv[BB * HH * LL];    // per-(bh,l) softmax 1/sum (row scale)

// ---------------------------------------------------------------------------
__device__ __forceinline__ uint32_t smem_u32(const void* p) {
    uint32_t a;
    asm("{ .reg .u64 t; cvta.to.shared.u64 t, %1; cvt.u32.u64 %0, t; }" : "=r"(a) : "l"(p));
    return a;
}
__device__ __forceinline__ void ldm_x4(uint32_t& r0, uint32_t& r1, uint32_t& r2,
                                       uint32_t& r3, uint32_t addr) {
    asm volatile("ldmatrix.sync.aligned.m8n8.x4.shared.b16 {%0,%1,%2,%3}, [%4];"
                 : "=r"(r0), "=r"(r1), "=r"(r2), "=r"(r3) : "r"(addr));
}
__device__ __forceinline__ void mma_bf16(float& c0, float& c1, float& c2, float& c3,
                                         uint32_t a0, uint32_t a1, uint32_t a2, uint32_t a3,
                                         uint32_t b0, uint32_t b1) {
    asm volatile("mma.sync.aligned.m16n8k16.row.col.f32.bf16.bf16.f32 "
                 "{%0,%1,%2,%3}, {%4,%5,%6,%7}, {%8,%9}, {%0,%1,%2,%3};"
                 : "+f"(c0), "+f"(c1), "+f"(c2), "+f"(c3)
                 : "r"(a0), "r"(a1), "r"(a2), "r"(a3), "r"(b0), "r"(b1));
}
#define CP_ASYNC16(dst, src) \
    asm volatile("cp.async.cg.shared.global [%0], [%1], 16;" :: "r"(dst), "l"(src))
#define CP_COMMIT()  asm volatile("cp.async.commit_group;" ::: "memory")
#define CP_WAIT(n)   asm volatile("cp.async.wait_group %0;" :: "n"(n) : "memory")

// smem row stride for MMA tiles: 40 bf16 = 80 B; conflict-free ldmatrix.
#define SSTR 40

__device__ __forceinline__ uint16_t bf16_bits(float f) {
    return __bfloat16_as_ushort(__float2bfloat16(f));
}

// ---------------------------------------------------------------------------
// Prep 1: split K,Q fp32 -> bf16 hi/lo in [bh][l][64] layout; zero wacc.
__global__ __launch_bounds__(256) void prep_kq_kernel(
    const float* __restrict__ Kp, const float* __restrict__ Qp)
{
    int idx = blockIdx.x * 256 + threadIdx.x;
    int k = idx & 63, h = (idx >> 6) & 7, l = (idx >> 9) & 1023, b = idx >> 19;
    size_t o = (((size_t)(b * 8 + h) * 1024 + l) << 6) | (unsigned)k;
    float kv = Kp[idx];
    __nv_bfloat16 khi = __float2bfloat16(kv);
    g_Khi[o] = khi;
    g_Klo[o] = __float2bfloat16(kv - __bfloat162float(khi));
    float qv = Qp[idx];
    __nv_bfloat16 qhi = __float2bfloat16(qv);
    g_Qhi[o] = qhi;
    g_Qlo[o] = __float2bfloat16(qv - __bfloat162float(qhi));
    if (idx < BB * LL) g_wacc[idx] = 0.f;
}

// Prep 2: transpose-split V [b][m][h*64+d] -> Vt hi/lo [bh][d][m]
__global__ __launch_bounds__(256) void prep_v_kernel(const float* __restrict__ Vp)
{
    __shared__ float t[32][33];
    int b = blockIdx.z;
    int m0 = blockIdx.x * 32, hd0 = blockIdx.y * 32;
    int tx = threadIdx.x, ty = threadIdx.y;   // (32, 8)
#pragma unroll
    for (int i = 0; i < 4; i++)
        t[ty + 8 * i][tx] = Vp[((size_t)b * 1024 + m0 + ty + 8 * i) * 512 + hd0 + tx];
    __syncthreads();
#pragma unroll
    for (int i = 0; i < 4; i++) {
        int hd = hd0 + ty + 8 * i;
        int h = hd >> 6, d = hd & 63;
        float x = t[tx][ty + 8 * i];
        __nv_bfloat16 hi = __float2bfloat16(x);
        size_t o = ((size_t)(b * 8 + h) * 64 + d) * 1024 + m0 + tx;
        g_Vthi[o] = hi;
        g_Vtlo[o] = __float2bfloat16(x - __bfloat162float(hi));
    }
}

// ---------------------------------------------------------------------------
// GEMM1 (mma.sync bf16): S[bh][l][m] = K[l,:]·Q[m,:], tile 128x128, K=64.
// cp.async double-buffer; epilogue stores culled to l<len && m<len. (R13)
#define G1_CHUNK (4 * 128 * SSTR * 2)             // 40960 B per chunk
#define G1_SMEM  (2 * G1_CHUNK)                   // 81920 B
__global__ __launch_bounds__(256) void gemm1_kernel(const float* __restrict__ doc)
{
    extern __shared__ __align__(16) char dsm[];

    int bh = blockIdx.z;
    int b = bh >> 3;
    int len = (int)doc[b];
    int l0 = blockIdx.y * 128, m0 = blockIdx.x * 128;
    if (l0 >= len || m0 >= len) return;

    int tid = threadIdx.x, wid = tid >> 5, lane = tid & 31;
    int wm = (wid >> 2) * 64, wn = (wid & 3) * 32;
    uint32_t sbase = smem_u32(dsm);

    const uint4* srcs[4] = {
        (const uint4*)(g_Khi + ((size_t)bh * 1024 + l0) * 64),
        (const uint4*)(g_Klo + ((size_t)bh * 1024 + l0) * 64),
        (const uint4*)(g_Qhi + ((size_t)bh * 1024 + m0) * 64),
        (const uint4*)(g_Qlo + ((size_t)bh * 1024 + m0) * 64) };

    int row = tid >> 2, c4 = tid & 3;
#pragma unroll
    for (int ch = 0; ch < 2; ch++) {
#pragma unroll
        for (int e = 0; e < 4; e++) {
            uint32_t dbase = sbase + ch * G1_CHUNK + e * (128 * SSTR * 2);
            CP_ASYNC16(dbase + row * (SSTR * 2) + c4 * 16,
                       srcs[e] + (size_t)row * 8 + ch * 4 + c4);
            CP_ASYNC16(dbase + (row + 64) * (SSTR * 2) + c4 * 16,
                       srcs[e] + (size_t)(row + 64) * 8 + ch * 4 + c4);
        }
        CP_COMMIT();
    }

    float c[4][4][4];
#pragma unroll
    for (int i = 0; i < 4; i++)
#pragma unroll
        for (int j = 0; j < 4; j++)
#pragma unroll
            for (int q = 0; q < 4; q++) c[i][j][q] = 0.f;

    uint32_t aoff = (uint32_t)(wm + (lane & 15)) * (SSTR * 2) + (((uint32_t)lane >> 4) << 4);
    uint32_t boff = (uint32_t)(wn + (lane & 7) + (((uint32_t)lane >> 4) << 3)) * (SSTR * 2)
                  + ((((uint32_t)lane >> 3) & 1) << 4);

#pragma unroll
    for (int ch = 0; ch < 2; ch++) {
        if (ch == 0) { CP_WAIT(1); } else { CP_WAIT(0); }
        __syncthreads();
        uint32_t sAh = sbase + ch * G1_CHUNK;
        uint32_t sAl = sAh + 128 * SSTR * 2;
        uint32_t sBh = sAl + 128 * SSTR * 2;
        uint32_t sBl = sBh + 128 * SSTR * 2;

#pragma unroll
        for (int ks = 0; ks < 2; ks++) {
            uint32_t k0b = ks * 32;
            uint32_t Ah[4][4], Al[4][4], Bh[2][4], Bl[2][4];
#pragma unroll
            for (int mt = 0; mt < 4; mt++) {
                ldm_x4(Ah[mt][0], Ah[mt][1], Ah[mt][2], Ah[mt][3],
                       sAh + aoff + mt * 16 * (SSTR * 2) + k0b);
                ldm_x4(Al[mt][0], Al[mt][1], Al[mt][2], Al[mt][3],
                       sAl + aoff + mt * 16 * (SSTR * 2) + k0b);
            }
#pragma unroll
            for (int nt = 0; nt < 2; nt++) {
                ldm_x4(Bh[nt][0], Bh[nt][1], Bh[nt][2], Bh[nt][3],
                       sBh + boff + nt * 16 * (SSTR * 2) + k0b);
                ldm_x4(Bl[nt][0], Bl[nt][1], Bl[nt][2], Bl[nt][3],
                       sBl + boff + nt * 16 * (SSTR * 2) + k0b);
            }
#pragma unroll
            for (int mt = 0; mt < 4; mt++)
#pragma unroll
                for (int ns = 0; ns < 4; ns++) {
                    float* cc = c[mt][ns];
                    uint32_t* bh_ = &Bh[ns >> 1][(ns & 1) * 2];
                    uint32_t* bl_ = &Bl[ns >> 1][(ns & 1) * 2];
                    mma_bf16(cc[0], cc[1], cc[2], cc[3],
                             Ah[mt][0], Ah[mt][1], Ah[mt][2], Ah[mt][3], bh_[0], bh_[1]);
                    mma_bf16(cc[0], cc[1], cc[2], cc[3],
                             Ah[mt][0], Ah[mt][1], Ah[mt][2], Ah[mt][3], bl_[0], bl_[1]);
                    mma_bf16(cc[0], cc[1], cc[2], cc[3],
                             Al[mt][0], Al[mt][1], Al[mt][2], Al[mt][3], bh_[0], bh_[1]);
                }
        }
        if (ch == 0) __syncthreads();
    }

    float* Sp = g_S + ((size_t)bh * 1024 + l0) * 1024 + m0;
    int rlim = len - l0, nlim = len - m0;
#pragma unroll
    for (int mt = 0; mt < 4; mt++) {
        int r0 = wm + mt * 16 + (lane >> 2);
#pragma unroll
        for (int ns = 0; ns < 4; ns++) {
            int n = wn + ns * 8 + (lane & 3) * 2;
            if (n < nlim) {
                if (r0 < rlim)
                    *(float2*)&Sp[(size_t)r0 * 1024 + n] =
                        make_float2(c[mt][ns][0], c[mt][ns][1]);
                if (r0 + 8 < rlim)
                    *(float2*)&Sp[(size_t)(r0 + 8) * 1024 + n] =
                        make_float2(c[mt][ns][2], c[mt][ns][3]);
            }
        }
    }
}

// ---------------------------------------------------------------------------
// lnsm v7 (R12, measured 66us): copy -> LN -> exp+sum -> emit(e hi/lo + csum).
__global__ __launch_bounds__(256) void lnsm_kernel(
    const float* __restrict__ doc, const float* __restrict__ gamma,
    const float* __restrict__ beta)
{
    __shared__ float s[HH][LL];   // 32 KB
    __shared__ float binv[HH];
    int b = blockIdx.y, l = blockIdx.x;
    int len = (int)doc[b];
    int kend  = (len + 63) & ~63;
    int lceil = (len + 127) & ~127;
    int tid = threadIdx.x;

    if (l >= len) {
        if (l >= lceil) return;
        for (int h = 0; h < HH; ++h) {
            size_t o = ((size_t)(b * HH + h) * LL + l) * LL;
            for (int m = tid; m < kend; m += 256) {
                g_Phi[o + m] = __float2bfloat16(0.f);
                g_Plo[o + m] = __float2bfloat16(0.f);
            }
        }
        if (tid < HH) g_inv[(b * HH + tid) * LL + l] = 0.f;
        return;
    }

    for (int h = 0; h < HH; ++h) {
        const float* Sr = g_S + ((size_t)(b * HH + h) * LL + l) * LL;
        for (int m = tid; m < len; m += 256) s[h][m] = Sr[m];
    }
    __syncthreads();

    float ga[HH], be[HH];
#pragma unroll
    for (int h = 0; h < HH; h++) { ga[h] = gamma[h]; be[h] = beta[h]; }

    for (int m = tid; m < len; m += 256) {
        float x[HH]; float mu = 0.f;
#pragma unroll
        for (int h = 0; h < HH; h++) { x[h] = s[h][m]; mu += x[h]; }
        mu *= (1.f / HH);
        float var = 0.f;
#pragma unroll
        for (int h = 0; h < HH; h++) { float d0 = x[h] - mu; var += d0 * d0; }
        var *= (1.f / HH);
        float rstd = rsqrtf(var + 1e-5f);
#pragma unroll
        for (int h = 0; h < HH; h++) s[h][m] = (x[h] - mu) * rstd * ga[h] + be[h];
    }
    __syncthreads();

    {
        int w = tid >> 5, lane = tid & 31;
        float sum = 0.f;
        for (int m = lane; m < len; m += 32) {
            float e = __expf(s[w][m]);
            s[w][m] = e; sum += e;
        }
#pragma unroll
        for (int o = 16; o; o >>= 1) sum += __shfl_xor_sync(0xffffffffu, sum, o);
        if (lane == 0) {
            float iv = 1.f / sum;
            binv[w] = iv;
            g_inv[(b * HH + w) * LL + l] = iv;
        }
    }
    __syncthreads();

    float iv[HH];
#pragma unroll
    for (int h = 0; h < HH; h++) iv[h] = binv[h];

    size_t obase = ((size_t)(b * HH) * LL + l) * LL;
    for (int m = tid; m < kend; m += 256) {
        bool valid = (m < len);
        float csum = 0.f;
#pragma unroll
        for (int h = 0; h < HH; h++) {
            float e = valid ? s[h][m] : 0.f;
            csum += e * iv[h];
            uint16_t hb = bf16_bits(e);
            float hf = __bfloat162float(__ushort_as_bfloat16(hb));
            uint16_t lb = bf16_bits(e - hf);
            size_t o = obase + ((size_t)h << 20) + m;
            g_Phi[o] = __ushort_as_bfloat16(hb);
            g_Plo[o] = __ushort_as_bfloat16(lb);
        }
        if (valid) atomicAdd(&g_wacc[b * LL + m], csum);
    }
}

// ---------------------------------------------------------------------------
// Finalize w: one 1024-thread block per batch, single pass.
__global__ __launch_bounds__(1024) void wfin_kernel(
    const float* __restrict__ doc, float* __restrict__ wout)
{
    __shared__ float red[32];
    __shared__ float s_bmax, s_inv;
    int b = blockIdx.x;
    int len = (int)doc[b];
    int tid = threadIdx.x, w = tid >> 5, lane = tid & 31;
    float scale = 1.f / (8.f * (float)len);

    float v = (tid < len) ? g_wacc[b * LL + tid] * scale : -1e30f;
    float mx = v;
#pragma unroll
    for (int o = 16; o; o >>= 1) mx = fmaxf(mx, __shfl_xor_sync(0xffffffffu, mx, o));
    if (lane == 0) red[w] = mx;
    __syncthreads();
    if (w == 0) {
        float t = red[lane];
#pragma unroll
        for (int o = 16; o; o >>= 1) t = fmaxf(t, __shfl_xor_sync(0xffffffffu, t, o));
        if (lane == 0) s_bmax = t;
    }
    __syncthreads();
    float e = (tid < len) ? __expf(v - s_bmax) : 0.f;
    float sum = e;
#pragma unroll
    for (int o = 16; o; o >>= 1) sum += __shfl_xor_sync(0xffffffffu, sum, o);
    if (lane == 0) red[w] = sum;
    __syncthreads();
    if (w == 0) {
        float t = red[lane];
#pragma unroll
        for (int o = 16; o; o >>= 1) t += __shfl_xor_sync(0xffffffffu, t, o);
        if (lane == 0) s_inv = 1.f / t;
    }
    __syncthreads();
    wout[b * LL + tid] = e * s_inv;
}

// ---------------------------------------------------------------------------
// GEMM2 (mma.sync bf16): out[l,d] = inv[l] * sum_m e[l,m]·Vt[d,m];
// tile 128(l) x 64(d). 3-stage cp.async ring, ONE __syncthreads per chunk:
//   CP_WAIT(<=1 pending) ; bar ; issue ch+2 into stage (ch+2)%3 ; compute ch%3
// The issue is AFTER the barrier, which orders it against all threads'
// reads of that stage at chunk ch-1 (since (ch+2)%3 == (ch-1)%3).
#define G2_PH 0
#define G2_PL (128 * SSTR * 2)          // 10240
#define G2_VH (2 * 128 * SSTR * 2)      // 20480
#define G2_VL (G2_VH + 64 * SSTR * 2)   // 25600
#define G2_STAGE (G2_VL + 64 * SSTR * 2) // 30720
#define G2_SMEM (3 * G2_STAGE)           // 92160
__global__ __launch_bounds__(256) void gemm2_kernel(
    const float* __restrict__ doc, float* __restrict__ outp)
{
    extern __shared__ __align__(16) char dsm[];

    int b = blockIdx.z, h = blockIdx.y;
    int bh = b * 8 + h;
    int len = (int)doc[b];
    int l0 = blockIdx.x * 128;
    int tid = threadIdx.x, wid = tid >> 5, lane = tid & 31;

    if (l0 >= len) {
        float* dst = outp + ((size_t)b * 1024 + l0 + (tid >> 1)) * 512 + h * 64;
        float4 z = make_float4(0, 0, 0, 0);
#pragma unroll
        for (int j = 0; j < 8; j++) ((float4*)dst)[(tid & 1) * 8 + j] = z;
        return;
    }

    int wm = (wid >> 1) * 32, wn = (wid & 1) * 32;
    uint32_t sbase = smem_u32(dsm);

    const uint4* srcPh = (const uint4*)(g_Phi + ((size_t)bh * 1024 + l0) * 1024);
    const uint4* srcPl = (const uint4*)(g_Plo + ((size_t)bh * 1024 + l0) * 1024);
    const uint4* srcVh = (const uint4*)(g_Vthi + (size_t)bh * 64 * 1024);
    const uint4* srcVl = (const uint4*)(g_Vtlo + (size_t)bh * 64 * 1024);

    int prow = tid >> 2, pc4 = tid & 3;          // prow in [0,64)
    uint32_t dP0 = prow * (SSTR * 2) + pc4 * 16;
    uint32_t dP1 = (prow + 64) * (SSTR * 2) + pc4 * 16;
    uint32_t dV  = prow * (SSTR * 2) + pc4 * 16;

    int kend = (len + 31) & ~31;
    int nch = kend >> 5;

    // prologue: issue chunks 0 and 1
#pragma unroll
    for (int ch = 0; ch < 2; ch++) {
        if (ch < nch) {
            uint32_t sb = sbase + (ch % 3) * G2_STAGE;
            int mq = ch * 4;
            CP_ASYNC16(sb + G2_PH + dP0, srcPh + (size_t)prow * 128 + mq + pc4);
            CP_ASYNC16(sb + G2_PH + dP1, srcPh + (size_t)(prow + 64) * 128 + mq + pc4);
            CP_ASYNC16(sb + G2_PL + dP0, srcPl + (size_t)prow * 128 + mq + pc4);
            CP_ASYNC16(sb + G2_PL + dP1, srcPl + (size_t)(prow + 64) * 128 + mq + pc4);
            CP_ASYNC16(sb + G2_VH + dV,  srcVh + (size_t)prow * 128 + mq + pc4);
            CP_ASYNC16(sb + G2_VL + dV,  srcVl + (size_t)prow * 128 + mq + pc4);
        }
        CP_COMMIT();   // commit even if empty: keeps group accounting uniform
    }

    float c[2][4][4];
#pragma unroll
    for (int i = 0; i < 2; i++)
#pragma unroll
        for (int j = 0; j < 4; j++)
#pragma unroll
            for (int q = 0; q < 4; q++) c[i][j][q] = 0.f;

    uint32_t aoff = (uint32_t)(wm + (lane & 15)) * (SSTR * 2) + (((uint32_t)lane >> 4) << 4);
    uint32_t boff = (uint32_t)(wn + (lane & 7) + (((uint32_t)lane >> 4) << 3)) * (SSTR * 2)
                  + ((((uint32_t)lane >> 3) & 1) << 4);

    for (int ch = 0; ch < nch; ++ch) {
        CP_WAIT(1);            // chunk ch complete (only ch+1's group may pend)
        __syncthreads();       // all threads done reading stage (ch-1)%3

        if (ch + 2 < nch) {    // issue into stage (ch+2)%3 == (ch-1)%3 — safe now
            uint32_t sb = sbase + ((ch + 2) % 3) * G2_STAGE;
            int mq = (ch + 2) * 4;
            CP_ASYNC16(sb + G2_PH + dP0, srcPh + (size_t)prow * 128 + mq + pc4);
            CP_ASYNC16(sb + G2_PH + dP1, srcPh + (size_t)(prow + 64) * 128 + mq + pc4);
            CP_ASYNC16(sb + G2_PL + dP0, srcPl + (size_t)prow * 128 + mq + pc4);
            CP_ASYNC16(sb + G2_PL + dP1, srcPl + (size_t)(prow + 64) * 128 + mq + pc4);
            CP_ASYNC16(sb + G2_VH + dV,  srcVh + (size_t)prow * 128 + mq + pc4);
            CP_ASYNC16(sb + G2_VL + dV,  srcVl + (size_t)prow * 128 + mq + pc4);
        }
        CP_COMMIT();

        uint32_t sb = sbase + (ch % 3) * G2_STAGE;
        uint32_t sPh = sb + G2_PH, sPl = sb + G2_PL;
        uint32_t sVh = sb + G2_VH, sVl = sb + G2_VL;

#pragma unroll
        for (int ks = 0; ks < 2; ks++) {
            uint32_t k0b = ks * 32;
            uint32_t Ah[2][4], Al[2][4], Bh[2][4], Bl[2][4];
#pragma unroll
            for (int mt = 0; mt < 2; mt++) {
                ldm_x4(Ah[mt][0], Ah[mt][1], Ah[mt][2], Ah[mt][3],
                       sPh + aoff + mt * 16 * (SSTR * 2) + k0b);
                ldm_x4(Al[mt][0], Al[mt][1], Al[mt][2], Al[mt][3],
                       sPl + aoff + mt * 16 * (SSTR * 2) + k0b);
            }
#pragma unroll
            for (int nt = 0; nt < 2; nt++) {
                ldm_x4(Bh[nt][0], Bh[nt][1], Bh[nt][2], Bh[nt][3],
                       sVh + boff + nt * 16 * (SSTR * 2) + k0b);
                ldm_x4(Bl[nt][0], Bl[nt][1], Bl[nt][2], Bl[nt][3],
                       sVl + boff + nt * 16 * (SSTR * 2) + k0b);
            }
#pragma unroll
            for (int mt = 0; mt < 2; mt++)
#pragma unroll
                for (int ns = 0; ns < 4; ns++) {
                    float* cc = c[mt][ns];
                    uint32_t* bh_ = &Bh[ns >> 1][(ns & 1) * 2];
                    uint32_t* bl_ = &Bl[ns >> 1][(ns & 1) * 2];
                    mma_bf16(cc[0], cc[1], cc[2], cc[3],
                             Ah[mt][0], Ah[mt][1], Ah[mt][2], Ah[mt][3], bh_[0], bh_[1]);
                    mma_bf16(cc[0], cc[1], cc[2], cc[3],
                             Ah[mt][0], Ah[mt][1], Ah[mt][2], Ah[mt][3], bl_[0], bl_[1]);
                    mma_bf16(cc[0], cc[1], cc[2], cc[3],
                             Al[mt][0], Al[mt][1], Al[mt][2], Al[mt][3], bh_[0], bh_[1]);
                }
        }
    }

    const float* ginv = g_inv + (size_t)bh * 1024 + l0;
    float* dstb = outp + ((size_t)b * 1024 + l0) * 512 + h * 64;
#pragma unroll
    for (int mt = 0; mt < 2; mt++) {
        int r0 = wm + mt * 16 + (lane >> 2);
        float ia = ginv[r0], ib = ginv[r0 + 8];
#pragma unroll
        for (int ns = 0; ns < 4; ns++) {
            int n = wn + ns * 8 + (lane & 3) * 2;
            *(float2*)&dstb[(size_t)r0 * 512 + n] =
                make_float2(c[mt][ns][0] * ia, c[mt][ns][1] * ia);
            *(float2*)&dstb[(size_t)(r0 + 8) * 512 + n] =
                make_float2(c[mt][ns][2] * ib, c[mt][ns][3] * ib);
        }
    }
}

// ---------------------------------------------------------------------------
extern "C" void kernel_launch(void* const* d_in, const int* in_sizes, int n_in,
                              void* d_out, int out_size) {
    const float* K     = (const float*)d_in[0];
    const float* Q     = (const float*)d_in[1];
    const float* V     = (const float*)d_in[2];
    const float* doc   = (const float*)d_in[3];
    const float* gamma = (const float*)d_in[4];
    const float* beta  = (const float*)d_in[5];
    // pad_mask / bx_packed derivable from doc_sizes; unused.

    float* outp = (float*)d_out;

    cudaFuncSetAttribute(gemm1_kernel,
                         cudaFuncAttributeMaxDynamicSharedMemorySize, G1_SMEM);
    cudaFuncSetAttribute(gemm2_kernel,
                         cudaFuncAttributeMaxDynamicSharedMemorySize, G2_SMEM);

    prep_kq_kernel<<<(BB * LL * DD) / 256, 256>>>(K, Q);
    prep_v_kernel<<<dim3(LL / 32, DD / 32, BB), dim3(32, 8)>>>(V);

    dim3 g1(LL / 128, LL / 128, BB * HH);      // (8, 8, 32)
    gemm1_kernel<<<g1, 256, G1_SMEM>>>(doc);

    dim3 g2(LL, BB);
    lnsm_kernel<<<g2, 256>>>(doc, gamma, beta);

    if (out_size >= BB * LL * DD + BB * LL) {
        float* wout = outp + (size_t)BB * LL * DD;
        wfin_kernel<<<BB, 1024>>>(doc, wout);
    }

    dim3 g3(LL / 128, HH, BB);                 // (8, 8, 4)
    gemm2_kernel<<<g3, 256, G2_SMEM>>>(doc, outp);
}

// round 15
// speedup vs baseline: 1.7071x; 1.1841x over previous
#include <cuda_runtime.h>
#include <cuda_bf16.h>
#include <cstdint>

#define BB 4
#define LL 1024
#define DD 512
#define HH 8
#define HD 64

// ---------------------------------------------------------------------------
// Device scratch (static: no allocations allowed)
__device__ __align__(256) float g_S[(size_t)BB * HH * LL * LL];           // 128 MB scores
__device__ __align__(256) __nv_bfloat16 g_Phi[(size_t)BB * HH * LL * LL]; // 64 MB (unnormalized e, hi)
__device__ __align__(256) __nv_bfloat16 g_Plo[(size_t)BB * HH * LL * LL]; // 64 MB (unnormalized e, lo)
__device__ __align__(256) __nv_bfloat16 g_Khi[(size_t)BB * HH * LL * HD];
__device__ __align__(256) __nv_bfloat16 g_Klo[(size_t)BB * HH * LL * HD];
__device__ __align__(256) __nv_bfloat16 g_Qhi[(size_t)BB * HH * LL * HD];
__device__ __align__(256) __nv_bfloat16 g_Qlo[(size_t)BB * HH * LL * HD];
__device__ __align__(256) __nv_bfloat16 g_Vthi[(size_t)BB * HH * HD * LL]; // [bh][d][m]
__device__ __align__(256) __nv_bfloat16 g_Vtlo[(size_t)BB * HH * HD * LL];
__device__ float g_wacc[BB * LL];
__device__ float g_inv[BB * HH * LL];    // per-(bh,l) softmax 1/sum (row scale)

// ---------------------------------------------------------------------------
__device__ __forceinline__ uint32_t smem_u32(const void* p) {
    uint32_t a;
    asm("{ .reg .u64 t; cvta.to.shared.u64 t, %1; cvt.u32.u64 %0, t; }" : "=r"(a) : "l"(p));
    return a;
}
__device__ __forceinline__ void ldm_x4(uint32_t& r0, uint32_t& r1, uint32_t& r2,
                                       uint32_t& r3, uint32_t addr) {
    asm volatile("ldmatrix.sync.aligned.m8n8.x4.shared.b16 {%0,%1,%2,%3}, [%4];"
                 : "=r"(r0), "=r"(r1), "=r"(r2), "=r"(r3) : "r"(addr));
}
__device__ __forceinline__ void mma_bf16(float& c0, float& c1, float& c2, float& c3,
                                         uint32_t a0, uint32_t a1, uint32_t a2, uint32_t a3,
                                         uint32_t b0, uint32_t b1) {
    asm volatile("mma.sync.aligned.m16n8k16.row.col.f32.bf16.bf16.f32 "
                 "{%0,%1,%2,%3}, {%4,%5,%6,%7}, {%8,%9}, {%0,%1,%2,%3};"
                 : "+f"(c0), "+f"(c1), "+f"(c2), "+f"(c3)
                 : "r"(a0), "r"(a1), "r"(a2), "r"(a3), "r"(b0), "r"(b1));
}
#define CP_ASYNC16(dst, src) \
    asm volatile("cp.async.cg.shared.global [%0], [%1], 16;" :: "r"(dst), "l"(src))
#define CP_COMMIT()  asm volatile("cp.async.commit_group;" ::: "memory")
#define CP_WAIT(n)   asm volatile("cp.async.wait_group %0;" :: "n"(n) : "memory")

// smem row stride for MMA tiles: 40 bf16 = 80 B; conflict-free ldmatrix.
#define SSTR 40

__device__ __forceinline__ uint16_t bf16_bits(float f) {
    return __bfloat16_as_ushort(__float2bfloat16(f));
}

// ---------------------------------------------------------------------------
// Prep 1: split K,Q fp32 -> bf16 hi/lo in [bh][l][64] layout; zero wacc.
__global__ __launch_bounds__(256) void prep_kq_kernel(
    const float* __restrict__ Kp, const float* __restrict__ Qp)
{
    int idx = blockIdx.x * 256 + threadIdx.x;
    int k = idx & 63, h = (idx >> 6) & 7, l = (idx >> 9) & 1023, b = idx >> 19;
    size_t o = (((size_t)(b * 8 + h) * 1024 + l) << 6) | (unsigned)k;
    float kv = Kp[idx];
    __nv_bfloat16 khi = __float2bfloat16(kv);
    g_Khi[o] = khi;
    g_Klo[o] = __float2bfloat16(kv - __bfloat162float(khi));
    float qv = Qp[idx];
    __nv_bfloat16 qhi = __float2bfloat16(qv);
    g_Qhi[o] = qhi;
    g_Qlo[o] = __float2bfloat16(qv - __bfloat162float(qhi));
    if (idx < BB * LL) g_wacc[idx] = 0.f;
}

// Prep 2: transpose-split V [b][m][h*64+d] -> Vt hi/lo [bh][d][m]
__global__ __launch_bounds__(256) void prep_v_kernel(const float* __restrict__ Vp)
{
    __shared__ float t[32][33];
    int b = blockIdx.z;
    int m0 = blockIdx.x * 32, hd0 = blockIdx.y * 32;
    int tx = threadIdx.x, ty = threadIdx.y;   // (32, 8)
#pragma unroll
    for (int i = 0; i < 4; i++)
        t[ty + 8 * i][tx] = Vp[((size_t)b * 1024 + m0 + ty + 8 * i) * 512 + hd0 + tx];
    __syncthreads();
#pragma unroll
    for (int i = 0; i < 4; i++) {
        int hd = hd0 + ty + 8 * i;
        int h = hd >> 6, d = hd & 63;
        float x = t[tx][ty + 8 * i];
        __nv_bfloat16 hi = __float2bfloat16(x);
        size_t o = ((size_t)(b * 8 + h) * 64 + d) * 1024 + m0 + tx;
        g_Vthi[o] = hi;
        g_Vtlo[o] = __float2bfloat16(x - __bfloat162float(hi));
    }
}

// ---------------------------------------------------------------------------
// GEMM1 (mma.sync bf16): S[bh][l][m] = K[l,:]·Q[m,:], tile 128x128, K=64.
// cp.async double-buffer; epilogue stores culled to l<len && m<len. (R13)
#define G1_CHUNK (4 * 128 * SSTR * 2)             // 40960 B per chunk
#define G1_SMEM  (2 * G1_CHUNK)                   // 81920 B
__global__ __launch_bounds__(256) void gemm1_kernel(const float* __restrict__ doc)
{
    extern __shared__ __align__(16) char dsm[];

    int bh = blockIdx.z;
    int b = bh >> 3;
    int len = (int)doc[b];
    int l0 = blockIdx.y * 128, m0 = blockIdx.x * 128;
    if (l0 >= len || m0 >= len) return;

    int tid = threadIdx.x, wid = tid >> 5, lane = tid & 31;
    int wm = (wid >> 2) * 64, wn = (wid & 3) * 32;
    uint32_t sbase = smem_u32(dsm);

    const uint4* srcs[4] = {
        (const uint4*)(g_Khi + ((size_t)bh * 1024 + l0) * 64),
        (const uint4*)(g_Klo + ((size_t)bh * 1024 + l0) * 64),
        (const uint4*)(g_Qhi + ((size_t)bh * 1024 + m0) * 64),
        (const uint4*)(g_Qlo + ((size_t)bh * 1024 + m0) * 64) };

    int row = tid >> 2, c4 = tid & 3;
#pragma unroll
    for (int ch = 0; ch < 2; ch++) {
#pragma unroll
        for (int e = 0; e < 4; e++) {
            uint32_t dbase = sbase + ch * G1_CHUNK + e * (128 * SSTR * 2);
            CP_ASYNC16(dbase + row * (SSTR * 2) + c4 * 16,
                       srcs[e] + (size_t)row * 8 + ch * 4 + c4);
            CP_ASYNC16(dbase + (row + 64) * (SSTR * 2) + c4 * 16,
                       srcs[e] + (size_t)(row + 64) * 8 + ch * 4 + c4);
        }
        CP_COMMIT();
    }

    float c[4][4][4];
#pragma unroll
    for (int i = 0; i < 4; i++)
#pragma unroll
        for (int j = 0; j < 4; j++)
#pragma unroll
            for (int q = 0; q < 4; q++) c[i][j][q] = 0.f;

    uint32_t aoff = (uint32_t)(wm + (lane & 15)) * (SSTR * 2) + (((uint32_t)lane >> 4) << 4);
    uint32_t boff = (uint32_t)(wn + (lane & 7) + (((uint32_t)lane >> 4) << 3)) * (SSTR * 2)
                  + ((((uint32_t)lane >> 3) & 1) << 4);

#pragma unroll
    for (int ch = 0; ch < 2; ch++) {
        if (ch == 0) { CP_WAIT(1); } else { CP_WAIT(0); }
        __syncthreads();
        uint32_t sAh = sbase + ch * G1_CHUNK;
        uint32_t sAl = sAh + 128 * SSTR * 2;
        uint32_t sBh = sAl + 128 * SSTR * 2;
        uint32_t sBl = sBh + 128 * SSTR * 2;

#pragma unroll
        for (int ks = 0; ks < 2; ks++) {
            uint32_t k0b = ks * 32;
            uint32_t Ah[4][4], Al[4][4], Bh[2][4], Bl[2][4];
#pragma unroll
            for (int mt = 0; mt < 4; mt++) {
                ldm_x4(Ah[mt][0], Ah[mt][1], Ah[mt][2], Ah[mt][3],
                       sAh + aoff + mt * 16 * (SSTR * 2) + k0b);
                ldm_x4(Al[mt][0], Al[mt][1], Al[mt][2], Al[mt][3],
                       sAl + aoff + mt * 16 * (SSTR * 2) + k0b);
            }
#pragma unroll
            for (int nt = 0; nt < 2; nt++) {
                ldm_x4(Bh[nt][0], Bh[nt][1], Bh[nt][2], Bh[nt][3],
                       sBh + boff + nt * 16 * (SSTR * 2) + k0b);
                ldm_x4(Bl[nt][0], Bl[nt][1], Bl[nt][2], Bl[nt][3],
                       sBl + boff + nt * 16 * (SSTR * 2) + k0b);
            }
#pragma unroll
            for (int mt = 0; mt < 4; mt++)
#pragma unroll
                for (int ns = 0; ns < 4; ns++) {
                    float* cc = c[mt][ns];
                    uint32_t* bh_ = &Bh[ns >> 1][(ns & 1) * 2];
                    uint32_t* bl_ = &Bl[ns >> 1][(ns & 1) * 2];
                    mma_bf16(cc[0], cc[1], cc[2], cc[3],
                             Ah[mt][0], Ah[mt][1], Ah[mt][2], Ah[mt][3], bh_[0], bh_[1]);
                    mma_bf16(cc[0], cc[1], cc[2], cc[3],
                             Ah[mt][0], Ah[mt][1], Ah[mt][2], Ah[mt][3], bl_[0], bl_[1]);
                    mma_bf16(cc[0], cc[1], cc[2], cc[3],
                             Al[mt][0], Al[mt][1], Al[mt][2], Al[mt][3], bh_[0], bh_[1]);
                }
        }
        if (ch == 0) __syncthreads();
    }

    float* Sp = g_S + ((size_t)bh * 1024 + l0) * 1024 + m0;
    int rlim = len - l0, nlim = len - m0;
#pragma unroll
    for (int mt = 0; mt < 4; mt++) {
        int r0 = wm + mt * 16 + (lane >> 2);
#pragma unroll
        for (int ns = 0; ns < 4; ns++) {
            int n = wn + ns * 8 + (lane & 3) * 2;
            if (n < nlim) {
                if (r0 < rlim)
                    *(float2*)&Sp[(size_t)r0 * 1024 + n] =
                        make_float2(c[mt][ns][0], c[mt][ns][1]);
                if (r0 + 8 < rlim)
                    *(float2*)&Sp[(size_t)(r0 + 8) * 1024 + n] =
                        make_float2(c[mt][ns][2], c[mt][ns][3]);
            }
        }
    }
}

// ---------------------------------------------------------------------------
// lnsm v8: three sweeps.
//  1) FUSED load+LN+exp: read 8 heads straight from global (coalesced),
//     LayerNorm across heads, exp (no max: LN-bounded), store e to smem.
//     (R9-vs-R10 evidence: copy+LN fusion is neutral/positive; the R9-era
//      regression was the vectorized emit, which stays strided here.)
//  2) read-only per-head sum (warp-per-head) -> binv/g_inv. No STS.
//  3) emit (R12 form verbatim): e -> bf16 hi/lo + fused column-sum atomics.
__global__ __launch_bounds__(256) void lnsm_kernel(
    const float* __restrict__ doc, const float* __restrict__ gamma,
    const float* __restrict__ beta)
{
    __shared__ float s[HH][LL];   // 32 KB
    __shared__ float binv[HH];
    int b = blockIdx.y, l = blockIdx.x;
    int len = (int)doc[b];
    int kend  = (len + 63) & ~63;
    int lceil = (len + 127) & ~127;
    int tid = threadIdx.x;

    if (l >= len) {
        if (l >= lceil) return;
        for (int h = 0; h < HH; ++h) {
            size_t o = ((size_t)(b * HH + h) * LL + l) * LL;
            for (int m = tid; m < kend; m += 256) {
                g_Phi[o + m] = __float2bfloat16(0.f);
                g_Plo[o + m] = __float2bfloat16(0.f);
            }
        }
        if (tid < HH) g_inv[(b * HH + tid) * LL + l] = 0.f;
        return;
    }

    const float* Sb = g_S + ((size_t)(b * 8) * 1024 + l) * 1024;
    float ga[HH], be[HH];
#pragma unroll
    for (int h = 0; h < HH; h++) { ga[h] = gamma[h]; be[h] = beta[h]; }

    // ---- sweep 1: load + LN + exp -> smem (e), zeros in [len, kend) ----
    for (int m = tid; m < LL; m += 256) {
        if (m < len) {
            float x[HH];
#pragma unroll
            for (int h = 0; h < HH; h++) x[h] = Sb[((size_t)h << 20) + m];
            float mu = 0.f;
#pragma unroll
            for (int h = 0; h < HH; h++) mu += x[h];
            mu *= (1.f / HH);
            float var = 0.f;
#pragma unroll
            for (int h = 0; h < HH; h++) { float d0 = x[h] - mu; var += d0 * d0; }
            var *= (1.f / HH);
            float rstd = rsqrtf(var + 1e-5f);
#pragma unroll
            for (int h = 0; h < HH; h++)
                s[h][m] = __expf((x[h] - mu) * rstd * ga[h] + be[h]);
        } else if (m < kend) {
#pragma unroll
            for (int h = 0; h < HH; h++) s[h][m] = 0.f;
        }
    }
    __syncthreads();

    // ---- sweep 2: read-only per-head sums (warp w owns head w) ----
    {
        int w = tid >> 5, lane = tid & 31;
        float sum = 0.f;
        for (int m = lane; m < len; m += 32) sum += s[w][m];
#pragma unroll
        for (int o = 16; o; o >>= 1) sum += __shfl_xor_sync(0xffffffffu, sum, o);
        if (lane == 0) {
            float iv = 1.f / sum;
            binv[w] = iv;
            g_inv[(b * HH + w) * LL + l] = iv;
        }
    }
    __syncthreads();

    float iv[HH];
#pragma unroll
    for (int h = 0; h < HH; h++) iv[h] = binv[h];

    // ---- sweep 3: emit unnormalized e as bf16 hi/lo + column sums ----
    size_t obase = ((size_t)(b * HH) * LL + l) * LL;
    for (int m = tid; m < kend; m += 256) {
        bool valid = (m < len);
        float csum = 0.f;
#pragma unroll
        for (int h = 0; h < HH; h++) {
            float e = valid ? s[h][m] : 0.f;
            csum += e * iv[h];
            uint16_t hb = bf16_bits(e);
            float hf = __bfloat162float(__ushort_as_bfloat16(hb));
            uint16_t lb = bf16_bits(e - hf);
            size_t o = obase + ((size_t)h << 20) + m;
            g_Phi[o] = __ushort_as_bfloat16(hb);
            g_Plo[o] = __ushort_as_bfloat16(lb);
        }
        if (valid) atomicAdd(&g_wacc[b * LL + m], csum);
    }
}

// ---------------------------------------------------------------------------
// Finalize w: one 1024-thread block per batch, single pass.
__global__ __launch_bounds__(1024) void wfin_kernel(
    const float* __restrict__ doc, float* __restrict__ wout)
{
    __shared__ float red[32];
    __shared__ float s_bmax, s_inv;
    int b = blockIdx.x;
    int len = (int)doc[b];
    int tid = threadIdx.x, w = tid >> 5, lane = tid & 31;
    float scale = 1.f / (8.f * (float)len);

    float v = (tid < len) ? g_wacc[b * LL + tid] * scale : -1e30f;
    float mx = v;
#pragma unroll
    for (int o = 16; o; o >>= 1) mx = fmaxf(mx, __shfl_xor_sync(0xffffffffu, mx, o));
    if (lane == 0) red[w] = mx;
    __syncthreads();
    if (w == 0) {
        float t = red[lane];
#pragma unroll
        for (int o = 16; o; o >>= 1) t = fmaxf(t, __shfl_xor_sync(0xffffffffu, t, o));
        if (lane == 0) s_bmax = t;
    }
    __syncthreads();
    float e = (tid < len) ? __expf(v - s_bmax) : 0.f;
    float sum = e;
#pragma unroll
    for (int o = 16; o; o >>= 1) sum += __shfl_xor_sync(0xffffffffu, sum, o);
    if (lane == 0) red[w] = sum;
    __syncthreads();
    if (w == 0) {
        float t = red[lane];
#pragma unroll
        for (int o = 16; o; o >>= 1) t += __shfl_xor_sync(0xffffffffu, t, o);
        if (lane == 0) s_inv = 1.f / t;
    }
    __syncthreads();
    wout[b * LL + tid] = e * s_inv;
}

// ---------------------------------------------------------------------------
// GEMM2 (mma.sync bf16): out[l,d] = inv[l] * sum_m e[l,m]·Vt[d,m];
// tile 128(l) x 64(d). 3-stage cp.async ring, one __syncthreads per chunk. (R14)
#define G2_PH 0
#define G2_PL (128 * SSTR * 2)          // 10240
#define G2_VH (2 * 128 * SSTR * 2)      // 20480
#define G2_VL (G2_VH + 64 * SSTR * 2)   // 25600
#define G2_STAGE (G2_VL + 64 * SSTR * 2) // 30720
#define G2_SMEM (3 * G2_STAGE)           // 92160
__global__ __launch_bounds__(256) void gemm2_kernel(
    const float* __restrict__ doc, float* __restrict__ outp)
{
    extern __shared__ __align__(16) char dsm[];

    int b = blockIdx.z, h = blockIdx.y;
    int bh = b * 8 + h;
    int len = (int)doc[b];
    int l0 = blockIdx.x * 128;
    int tid = threadIdx.x, wid = tid >> 5, lane = tid & 31;

    if (l0 >= len) {
        float* dst = outp + ((size_t)b * 1024 + l0 + (tid >> 1)) * 512 + h * 64;
        float4 z = make_float4(0, 0, 0, 0);
#pragma unroll
        for (int j = 0; j < 8; j++) ((float4*)dst)[(tid & 1) * 8 + j] = z;
        return;
    }

    int wm = (wid >> 1) * 32, wn = (wid & 1) * 32;
    uint32_t sbase = smem_u32(dsm);

    const uint4* srcPh = (const uint4*)(g_Phi + ((size_t)bh * 1024 + l0) * 1024);
    const uint4* srcPl = (const uint4*)(g_Plo + ((size_t)bh * 1024 + l0) * 1024);
    const uint4* srcVh = (const uint4*)(g_Vthi + (size_t)bh * 64 * 1024);
    const uint4* srcVl = (const uint4*)(g_Vtlo + (size_t)bh * 64 * 1024);

    int prow = tid >> 2, pc4 = tid & 3;
    uint32_t dP0 = prow * (SSTR * 2) + pc4 * 16;
    uint32_t dP1 = (prow + 64) * (SSTR * 2) + pc4 * 16;
    uint32_t dV  = prow * (SSTR * 2) + pc4 * 16;

    int kend = (len + 31) & ~31;
    int nch = kend >> 5;

#pragma unroll
    for (int ch = 0; ch < 2; ch++) {
        if (ch < nch) {
            uint32_t sb = sbase + (ch % 3) * G2_STAGE;
            int mq = ch * 4;
            CP_ASYNC16(sb + G2_PH + dP0, srcPh + (size_t)prow * 128 + mq + pc4);
            CP_ASYNC16(sb + G2_PH + dP1, srcPh + (size_t)(prow + 64) * 128 + mq + pc4);
            CP_ASYNC16(sb + G2_PL + dP0, srcPl + (size_t)prow * 128 + mq + pc4);
            CP_ASYNC16(sb + G2_PL + dP1, srcPl + (size_t)(prow + 64) * 128 + mq + pc4);
            CP_ASYNC16(sb + G2_VH + dV,  srcVh + (size_t)prow * 128 + mq + pc4);
            CP_ASYNC16(sb + G2_VL + dV,  srcVl + (size_t)prow * 128 + mq + pc4);
        }
        CP_COMMIT();
    }

    float c[2][4][4];
#pragma unroll
    for (int i = 0; i < 2; i++)
#pragma unroll
        for (int j = 0; j < 4; j++)
#pragma unroll
            for (int q = 0; q < 4; q++) c[i][j][q] = 0.f;

    uint32_t aoff = (uint32_t)(wm + (lane & 15)) * (SSTR * 2) + (((uint32_t)lane >> 4) << 4);
    uint32_t boff = (uint32_t)(wn + (lane & 7) + (((uint32_t)lane >> 4) << 3)) * (SSTR * 2)
                  + ((((uint32_t)lane >> 3) & 1) << 4);

    for (int ch = 0; ch < nch; ++ch) {
        CP_WAIT(1);
        __syncthreads();

        if (ch + 2 < nch) {
            uint32_t sb = sbase + ((ch + 2) % 3) * G2_STAGE;
            int mq = (ch + 2) * 4;
            CP_ASYNC16(sb + G2_PH + dP0, srcPh + (size_t)prow * 128 + mq + pc4);
            CP_ASYNC16(sb + G2_PH + dP1, srcPh + (size_t)(prow + 64) * 128 + mq + pc4);
            CP_ASYNC16(sb + G2_PL + dP0, srcPl + (size_t)prow * 128 + mq + pc4);
            CP_ASYNC16(sb + G2_PL + dP1, srcPl + (size_t)(prow + 64) * 128 + mq + pc4);
            CP_ASYNC16(sb + G2_VH + dV,  srcVh + (size_t)prow * 128 + mq + pc4);
            CP_ASYNC16(sb + G2_VL + dV,  srcVl + (size_t)prow * 128 + mq + pc4);
        }
        CP_COMMIT();

        uint32_t sb = sbase + (ch % 3) * G2_STAGE;
        uint32_t sPh = sb + G2_PH, sPl = sb + G2_PL;
        uint32_t sVh = sb + G2_VH, sVl = sb + G2_VL;

#pragma unroll
        for (int ks = 0; ks < 2; ks++) {
            uint32_t k0b = ks * 32;
            uint32_t Ah[2][4], Al[2][4], Bh[2][4], Bl[2][4];
#pragma unroll
            for (int mt = 0; mt < 2; mt++) {
                ldm_x4(Ah[mt][0], Ah[mt][1], Ah[mt][2], Ah[mt][3],
                       sPh + aoff + mt * 16 * (SSTR * 2) + k0b);
                ldm_x4(Al[mt][0], Al[mt][1], Al[mt][2], Al[mt][3],
                       sPl + aoff + mt * 16 * (SSTR * 2) + k0b);
            }
#pragma unroll
            for (int nt = 0; nt < 2; nt++) {
                ldm_x4(Bh[nt][0], Bh[nt][1], Bh[nt][2], Bh[nt][3],
                       sVh + boff + nt * 16 * (SSTR * 2) + k0b);
                ldm_x4(Bl[nt][0], Bl[nt][1], Bl[nt][2], Bl[nt][3],
                       sVl + boff + nt * 16 * (SSTR * 2) + k0b);
            }
#pragma unroll
            for (int mt = 0; mt < 2; mt++)
#pragma unroll
                for (int ns = 0; ns < 4; ns++) {
                    float* cc = c[mt][ns];
                    uint32_t* bh_ = &Bh[ns >> 1][(ns & 1) * 2];
                    uint32_t* bl_ = &Bl[ns >> 1][(ns & 1) * 2];
                    mma_bf16(cc[0], cc[1], cc[2], cc[3],
                             Ah[mt][0], Ah[mt][1], Ah[mt][2], Ah[mt][3], bh_[0], bh_[1]);
                    mma_bf16(cc[0], cc[1], cc[2], cc[3],
                             Ah[mt][0], Ah[mt][1], Ah[mt][2], Ah[mt][3], bl_[0], bl_[1]);
                    mma_bf16(cc[0], cc[1], cc[2], cc[3],
                             Al[mt][0], Al[mt][1], Al[mt][2], Al[mt][3], bh_[0], bh_[1]);
                }
        }
    }

    const float* ginv = g_inv + (size_t)bh * 1024 + l0;
    float* dstb = outp + ((size_t)b * 1024 + l0) * 512 + h * 64;
#pragma unroll
    for (int mt = 0; mt < 2; mt++) {
        int r0 = wm + mt * 16 + (lane >> 2);
        float ia = ginv[r0], ib = ginv[r0 + 8];
#pragma unroll
        for (int ns = 0; ns < 4; ns++) {
            int n = wn + ns * 8 + (lane & 3) * 2;
            *(float2*)&dstb[(size_t)r0 * 512 + n] =
                make_float2(c[mt][ns][0] * ia, c[mt][ns][1] * ia);
            *(float2*)&dstb[(size_t)(r0 + 8) * 512 + n] =
                make_float2(c[mt][ns][2] * ib, c[mt][ns][3] * ib);
        }
    }
}

// ---------------------------------------------------------------------------
extern "C" void kernel_launch(void* const* d_in, const int* in_sizes, int n_in,
                              void* d_out, int out_size) {
    const float* K     = (const float*)d_in[0];
    const float* Q     = (const float*)d_in[1];
    const float* V     = (const float*)d_in[2];
    const float* doc   = (const float*)d_in[3];
    const float* gamma = (const float*)d_in[4];
    const float* beta  = (const float*)d_in[5];
    // pad_mask / bx_packed derivable from doc_sizes; unused.

    float* outp = (float*)d_out;

    cudaFuncSetAttribute(gemm1_kernel,
                         cudaFuncAttributeMaxDynamicSharedMemorySize, G1_SMEM);
    cudaFuncSetAttribute(gemm2_kernel,
                         cudaFuncAttributeMaxDynamicSharedMemorySize, G2_SMEM);

    prep_kq_kernel<<<(BB * LL * DD) / 256, 256>>>(K, Q);
    prep_v_kernel<<<dim3(LL / 32, DD / 32, BB), dim3(32, 8)>>>(V);

    dim3 g1(LL / 128, LL / 128, BB * HH);      // (8, 8, 32)
    gemm1_kernel<<<g1, 256, G1_SMEM>>>(doc);

    dim3 g2(LL, BB);
    lnsm_kernel<<<g2, 256>>>(doc, gamma, beta);

    if (out_size >= BB * LL * DD + BB * LL) {
        float* wout = outp + (size_t)BB * LL * DD;
        wfin_kernel<<<BB, 1024>>>(doc, wout);
    }

    dim3 g3(LL / 128, HH, BB);                 // (8, 8, 4)
    gemm2_kernel<<<g3, 256, G2_SMEM>>>(doc, outp);
}

// round 16
// speedup vs baseline: 1.7104x; 1.0019x over previous
#include <cuda_runtime.h>
#include <cuda_bf16.h>
#include <cstdint>

#define BB 4
#define LL 1024
#define DD 512
#define HH 8
#define HD 64

// ---------------------------------------------------------------------------
// Device scratch (static: no allocations allowed)
// g_S layout: [b][l][h][m]  -- 8 heads of one (b,l) row are contiguous (32 KB)
__device__ __align__(256) float g_S[(size_t)BB * LL * HH * LL];           // 128 MB scores
__device__ __align__(256) __nv_bfloat16 g_Phi[(size_t)BB * HH * LL * LL]; // 64 MB (unnormalized e, hi)
__device__ __align__(256) __nv_bfloat16 g_Plo[(size_t)BB * HH * LL * LL]; // 64 MB (unnormalized e, lo)
__device__ __align__(256) __nv_bfloat16 g_Khi[(size_t)BB * HH * LL * HD];
__device__ __align__(256) __nv_bfloat16 g_Klo[(size_t)BB * HH * LL * HD];
__device__ __align__(256) __nv_bfloat16 g_Qhi[(size_t)BB * HH * LL * HD];
__device__ __align__(256) __nv_bfloat16 g_Qlo[(size_t)BB * HH * LL * HD];
__device__ __align__(256) __nv_bfloat16 g_Vthi[(size_t)BB * HH * HD * LL]; // [bh][d][m]
__device__ __align__(256) __nv_bfloat16 g_Vtlo[(size_t)BB * HH * HD * LL];
__device__ float g_wacc[BB * LL];
__device__ float g_inv[BB * HH * LL];    // per-(bh,l) softmax 1/sum (row scale)

// ---------------------------------------------------------------------------
__device__ __forceinline__ uint32_t smem_u32(const void* p) {
    uint32_t a;
    asm("{ .reg .u64 t; cvta.to.shared.u64 t, %1; cvt.u32.u64 %0, t; }" : "=r"(a) : "l"(p));
    return a;
}
__device__ __forceinline__ void ldm_x4(uint32_t& r0, uint32_t& r1, uint32_t& r2,
                                       uint32_t& r3, uint32_t addr) {
    asm volatile("ldmatrix.sync.aligned.m8n8.x4.shared.b16 {%0,%1,%2,%3}, [%4];"
                 : "=r"(r0), "=r"(r1), "=r"(r2), "=r"(r3) : "r"(addr));
}
__device__ __forceinline__ void mma_bf16(float& c0, float& c1, float& c2, float& c3,
                                         uint32_t a0, uint32_t a1, uint32_t a2, uint32_t a3,
                                         uint32_t b0, uint32_t b1) {
    asm volatile("mma.sync.aligned.m16n8k16.row.col.f32.bf16.bf16.f32 "
                 "{%0,%1,%2,%3}, {%4,%5,%6,%7}, {%8,%9}, {%0,%1,%2,%3};"
                 : "+f"(c0), "+f"(c1), "+f"(c2), "+f"(c3)
                 : "r"(a0), "r"(a1), "r"(a2), "r"(a3), "r"(b0), "r"(b1));
}
#define CP_ASYNC16(dst, src) \
    asm volatile("cp.async.cg.shared.global [%0], [%1], 16;" :: "r"(dst), "l"(src))
#define CP_COMMIT()  asm volatile("cp.async.commit_group;" ::: "memory")
#define CP_WAIT(n)   asm volatile("cp.async.wait_group %0;" :: "n"(n) : "memory")

// smem row stride for MMA tiles: 40 bf16 = 80 B; conflict-free ldmatrix.
#define SSTR 40

__device__ __forceinline__ uint16_t bf16_bits(float f) {
    return __bfloat16_as_ushort(__float2bfloat16(f));
}

// ---------------------------------------------------------------------------
// Prep 1: split K,Q fp32 -> bf16 hi/lo in [bh][l][64] layout; zero wacc.
__global__ __launch_bounds__(256) void prep_kq_kernel(
    const float* __restrict__ Kp, const float* __restrict__ Qp)
{
    int idx = blockIdx.x * 256 + threadIdx.x;
    int k = idx & 63, h = (idx >> 6) & 7, l = (idx >> 9) & 1023, b = idx >> 19;
    size_t o = (((size_t)(b * 8 + h) * 1024 + l) << 6) | (unsigned)k;
    float kv = Kp[idx];
    __nv_bfloat16 khi = __float2bfloat16(kv);
    g_Khi[o] = khi;
    g_Klo[o] = __float2bfloat16(kv - __bfloat162float(khi));
    float qv = Qp[idx];
    __nv_bfloat16 qhi = __float2bfloat16(qv);
    g_Qhi[o] = qhi;
    g_Qlo[o] = __float2bfloat16(qv - __bfloat162float(qhi));
    if (idx < BB * LL) g_wacc[idx] = 0.f;
}

// Prep 2: transpose-split V [b][m][h*64+d] -> Vt hi/lo [bh][d][m]
__global__ __launch_bounds__(256) void prep_v_kernel(const float* __restrict__ Vp)
{
    __shared__ float t[32][33];
    int b = blockIdx.z;
    int m0 = blockIdx.x * 32, hd0 = blockIdx.y * 32;
    int tx = threadIdx.x, ty = threadIdx.y;   // (32, 8)
#pragma unroll
    for (int i = 0; i < 4; i++)
        t[ty + 8 * i][tx] = Vp[((size_t)b * 1024 + m0 + ty + 8 * i) * 512 + hd0 + tx];
    __syncthreads();
#pragma unroll
    for (int i = 0; i < 4; i++) {
        int hd = hd0 + ty + 8 * i;
        int h = hd >> 6, d = hd & 63;
        float x = t[tx][ty + 8 * i];
        __nv_bfloat16 hi = __float2bfloat16(x);
        size_t o = ((size_t)(b * 8 + h) * 64 + d) * 1024 + m0 + tx;
        g_Vthi[o] = hi;
        g_Vtlo[o] = __float2bfloat16(x - __bfloat162float(hi));
    }
}

// ---------------------------------------------------------------------------
// GEMM1 (mma.sync bf16): S[b][l][h][m] = K[l,:]·Q[m,:], tile 128x128, K=64.
// cp.async double-buffer; epilogue stores culled to l<len && m<len. (R13)
// Only change vs R15: S epilogue row stride is now 8*1024 (interleaved heads).
#define G1_CHUNK (4 * 128 * SSTR * 2)             // 40960 B per chunk
#define G1_SMEM  (2 * G1_CHUNK)                   // 81920 B
__global__ __launch_bounds__(256) void gemm1_kernel(const float* __restrict__ doc)
{
    extern __shared__ __align__(16) char dsm[];

    int bh = blockIdx.z;
    int b = bh >> 3, h = bh & 7;
    int len = (int)doc[b];
    int l0 = blockIdx.y * 128, m0 = blockIdx.x * 128;
    if (l0 >= len || m0 >= len) return;

    int tid = threadIdx.x, wid = tid >> 5, lane = tid & 31;
    int wm = (wid >> 2) * 64, wn = (wid & 3) * 32;
    uint32_t sbase = smem_u32(dsm);

    const uint4* srcs[4] = {
        (const uint4*)(g_Khi + ((size_t)bh * 1024 + l0) * 64),
        (const uint4*)(g_Klo + ((size_t)bh * 1024 + l0) * 64),
        (const uint4*)(g_Qhi + ((size_t)bh * 1024 + m0) * 64),
        (const uint4*)(g_Qlo + ((size_t)bh * 1024 + m0) * 64) };

    int row = tid >> 2, c4 = tid & 3;
#pragma unroll
    for (int ch = 0; ch < 2; ch++) {
#pragma unroll
        for (int e = 0; e < 4; e++) {
            uint32_t dbase = sbase + ch * G1_CHUNK + e * (128 * SSTR * 2);
            CP_ASYNC16(dbase + row * (SSTR * 2) + c4 * 16,
                       srcs[e] + (size_t)row * 8 + ch * 4 + c4);
            CP_ASYNC16(dbase + (row + 64) * (SSTR * 2) + c4 * 16,
                       srcs[e] + (size_t)(row + 64) * 8 + ch * 4 + c4);
        }
        CP_COMMIT();
    }

    float c[4][4][4];
#pragma unroll
    for (int i = 0; i < 4; i++)
#pragma unroll
        for (int j = 0; j < 4; j++)
#pragma unroll
            for (int q = 0; q < 4; q++) c[i][j][q] = 0.f;

    uint32_t aoff = (uint32_t)(wm + (lane & 15)) * (SSTR * 2) + (((uint32_t)lane >> 4) << 4);
    uint32_t boff = (uint32_t)(wn + (lane & 7) + (((uint32_t)lane >> 4) << 3)) * (SSTR * 2)
                  + ((((uint32_t)lane >> 3) & 1) << 4);

#pragma unroll
    for (int ch = 0; ch < 2; ch++) {
        if (ch == 0) { CP_WAIT(1); } else { CP_WAIT(0); }
        __syncthreads();
        uint32_t sAh = sbase + ch * G1_CHUNK;
        uint32_t sAl = sAh + 128 * SSTR * 2;
        uint32_t sBh = sAl + 128 * SSTR * 2;
        uint32_t sBl = sBh + 128 * SSTR * 2;

#pragma unroll
        for (int ks = 0; ks < 2; ks++) {
            uint32_t k0b = ks * 32;
            uint32_t Ah[4][4], Al[4][4], Bh[2][4], Bl[2][4];
#pragma unroll
            for (int mt = 0; mt < 4; mt++) {
                ldm_x4(Ah[mt][0], Ah[mt][1], Ah[mt][2], Ah[mt][3],
                       sAh + aoff + mt * 16 * (SSTR * 2) + k0b);
                ldm_x4(Al[mt][0], Al[mt][1], Al[mt][2], Al[mt][3],
                       sAl + aoff + mt * 16 * (SSTR * 2) + k0b);
            }
#pragma unroll
            for (int nt = 0; nt < 2; nt++) {
                ldm_x4(Bh[nt][0], Bh[nt][1], Bh[nt][2], Bh[nt][3],
                       sBh + boff + nt * 16 * (SSTR * 2) + k0b);
                ldm_x4(Bl[nt][0], Bl[nt][1], Bl[nt][2], Bl[nt][3],
                       sBl + boff + nt * 16 * (SSTR * 2) + k0b);
            }
#pragma unroll
            for (int mt = 0; mt < 4; mt++)
#pragma unroll
                for (int ns = 0; ns < 4; ns++) {
                    float* cc = c[mt][ns];
                    uint32_t* bh_ = &Bh[ns >> 1][(ns & 1) * 2];
                    uint32_t* bl_ = &Bl[ns >> 1][(ns & 1) * 2];
                    mma_bf16(cc[0], cc[1], cc[2], cc[3],
                             Ah[mt][0], Ah[mt][1], Ah[mt][2], Ah[mt][3], bh_[0], bh_[1]);
                    mma_bf16(cc[0], cc[1], cc[2], cc[3],
                             Ah[mt][0], Ah[mt][1], Ah[mt][2], Ah[mt][3], bl_[0], bl_[1]);
                    mma_bf16(cc[0], cc[1], cc[2], cc[3],
                             Al[mt][0], Al[mt][1], Al[mt][2], Al[mt][3], bh_[0], bh_[1]);
                }
        }
        if (ch == 0) __syncthreads();
    }

    // epilogue: S[b][l][h][m]; row stride = 8*1024 floats; culled to valid region
    float* Sp = g_S + (((size_t)(b * 1024 + l0) * 8 + h) << 10) + m0;
    int rlim = len - l0, nlim = len - m0;
#pragma unroll
    for (int mt = 0; mt < 4; mt++) {
        int r0 = wm + mt * 16 + (lane >> 2);
#pragma unroll
        for (int ns = 0; ns < 4; ns++) {
            int n = wn + ns * 8 + (lane & 3) * 2;
            if (n < nlim) {
                if (r0 < rlim)
                    *(float2*)&Sp[(size_t)r0 * 8192 + n] =
                        make_float2(c[mt][ns][0], c[mt][ns][1]);
                if (r0 + 8 < rlim)
                    *(float2*)&Sp[(size_t)(r0 + 8) * 8192 + n] =
                        make_float2(c[mt][ns][2], c[mt][ns][3]);
            }
        }
    }
}

// ---------------------------------------------------------------------------
// lnsm v8 (R15 structure) + S[b][l][h][m] layout: the 8 head values per (l,m)
// now live in one contiguous 32 KB block -> streaming DRAM reads.
//  1) FUSED load+LN+exp -> smem e
//  2) read-only per-head sums -> binv/g_inv
//  3) emit e as bf16 hi/lo + fused column-sum atomics
__global__ __launch_bounds__(256) void lnsm_kernel(
    const float* __restrict__ doc, const float* __restrict__ gamma,
    const float* __restrict__ beta)
{
    __shared__ float s[HH][LL];   // 32 KB
    __shared__ float binv[HH];
    int b = blockIdx.y, l = blockIdx.x;
    int len = (int)doc[b];
    int kend  = (len + 63) & ~63;
    int lceil = (len + 127) & ~127;
    int tid = threadIdx.x;

    if (l >= len) {
        if (l >= lceil) return;
        for (int h = 0; h < HH; ++h) {
            size_t o = ((size_t)(b * HH + h) * LL + l) * LL;
            for (int m = tid; m < kend; m += 256) {
                g_Phi[o + m] = __float2bfloat16(0.f);
                g_Plo[o + m] = __float2bfloat16(0.f);
            }
        }
        if (tid < HH) g_inv[(b * HH + tid) * LL + l] = 0.f;
        return;
    }

    const float* Sb = g_S + ((size_t)(b * 1024 + l) << 13);   // [l][h][m] block
    float ga[HH], be[HH];
#pragma unroll
    for (int h = 0; h < HH; h++) { ga[h] = gamma[h]; be[h] = beta[h]; }

    // ---- sweep 1: load + LN + exp -> smem (e), zeros in [len, kend) ----
    for (int m = tid; m < LL; m += 256) {
        if (m < len) {
            float x[HH];
#pragma unroll
            for (int h = 0; h < HH; h++) x[h] = Sb[(h << 10) + m];
            float mu = 0.f;
#pragma unroll
            for (int h = 0; h < HH; h++) mu += x[h];
            mu *= (1.f / HH);
            float var = 0.f;
#pragma unroll
            for (int h = 0; h < HH; h++) { float d0 = x[h] - mu; var += d0 * d0; }
            var *= (1.f / HH);
            float rstd = rsqrtf(var + 1e-5f);
#pragma unroll
            for (int h = 0; h < HH; h++)
                s[h][m] = __expf((x[h] - mu) * rstd * ga[h] + be[h]);
        } else if (m < kend) {
#pragma unroll
            for (int h = 0; h < HH; h++) s[h][m] = 0.f;
        }
    }
    __syncthreads();

    // ---- sweep 2: read-only per-head sums (warp w owns head w) ----
    {
        int w = tid >> 5, lane = tid & 31;
        float sum = 0.f;
        for (int m = lane; m < len; m += 32) sum += s[w][m];
#pragma unroll
        for (int o = 16; o; o >>= 1) sum += __shfl_xor_sync(0xffffffffu, sum, o);
        if (lane == 0) {
            float iv = 1.f / sum;
            binv[w] = iv;
            g_inv[(b * HH + w) * LL + l] = iv;
        }
    }
    __syncthreads();

    float iv[HH];
#pragma unroll
    for (int h = 0; h < HH; h++) iv[h] = binv[h];

    // ---- sweep 3: emit unnormalized e as bf16 hi/lo + column sums ----
    size_t obase = ((size_t)(b * HH) * LL + l) * LL;
    for (int m = tid; m < kend; m += 256) {
        bool valid = (m < len);
        float csum = 0.f;
#pragma unroll
        for (int h = 0; h < HH; h++) {
            float e = valid ? s[h][m] : 0.f;
            csum += e * iv[h];
            uint16_t hb = bf16_bits(e);
            float hf = __bfloat162float(__ushort_as_bfloat16(hb));
            uint16_t lb = bf16_bits(e - hf);
            size_t o = obase + ((size_t)h << 20) + m;
            g_Phi[o] = __ushort_as_bfloat16(hb);
            g_Plo[o] = __ushort_as_bfloat16(lb);
        }
        if (valid) atomicAdd(&g_wacc[b * LL + m], csum);
    }
}

// ---------------------------------------------------------------------------
// Finalize w: one 1024-thread block per batch, single pass.
__global__ __launch_bounds__(1024) void wfin_kernel(
    const float* __restrict__ doc, float* __restrict__ wout)
{
    __shared__ float red[32];
    __shared__ float s_bmax, s_inv;
    int b = blockIdx.x;
    int len = (int)doc[b];
    int tid = threadIdx.x, w = tid >> 5, lane = tid & 31;
    float scale = 1.f / (8.f * (float)len);

    float v = (tid < len) ? g_wacc[b * LL + tid] * scale : -1e30f;
    float mx = v;
#pragma unroll
    for (int o = 16; o; o >>= 1) mx = fmaxf(mx, __shfl_xor_sync(0xffffffffu, mx, o));
    if (lane == 0) red[w] = mx;
    __syncthreads();
    if (w == 0) {
        float t = red[lane];
#pragma unroll
        for (int o = 16; o; o >>= 1) t = fmaxf(t, __shfl_xor_sync(0xffffffffu, t, o));
        if (lane == 0) s_bmax = t;
    }
    __syncthreads();
    float e = (tid < len) ? __expf(v - s_bmax) : 0.f;
    float sum = e;
#pragma unroll
    for (int o = 16; o; o >>= 1) sum += __shfl_xor_sync(0xffffffffu, sum, o);
    if (lane == 0) red[w] = sum;
    __syncthreads();
    if (w == 0) {
        float t = red[lane];
#pragma unroll
        for (int o = 16; o; o >>= 1) t += __shfl_xor_sync(0xffffffffu, t, o);
        if (lane == 0) s_inv = 1.f / t;
    }
    __syncthreads();
    wout[b * LL + tid] = e * s_inv;
}

// ---------------------------------------------------------------------------
// GEMM2 (mma.sync bf16): out[l,d] = inv[l] * sum_m e[l,m]·Vt[d,m];
// tile 128(l) x 64(d). 3-stage cp.async ring, one __syncthreads per chunk. (R14)
#define G2_PH 0
#define G2_PL (128 * SSTR * 2)          // 10240
#define G2_VH (2 * 128 * SSTR * 2)      // 20480
#define G2_VL (G2_VH + 64 * SSTR * 2)   // 25600
#define G2_STAGE (G2_VL + 64 * SSTR * 2) // 30720
#define G2_SMEM (3 * G2_STAGE)           // 92160
__global__ __launch_bounds__(256) void gemm2_kernel(
    const float* __restrict__ doc, float* __restrict__ outp)
{
    extern __shared__ __align__(16) char dsm[];

    int b = blockIdx.z, h = blockIdx.y;
    int bh = b * 8 + h;
    int len = (int)doc[b];
    int l0 = blockIdx.x * 128;
    int tid = threadIdx.x, wid = tid >> 5, lane = tid & 31;

    if (l0 >= len) {
        float* dst = outp + ((size_t)b * 1024 + l0 + (tid >> 1)) * 512 + h * 64;
        float4 z = make_float4(0, 0, 0, 0);
#pragma unroll
        for (int j = 0; j < 8; j++) ((float4*)dst)[(tid & 1) * 8 + j] = z;
        return;
    }

    int wm = (wid >> 1) * 32, wn = (wid & 1) * 32;
    uint32_t sbase = smem_u32(dsm);

    const uint4* srcPh = (const uint4*)(g_Phi + ((size_t)bh * 1024 + l0) * 1024);
    const uint4* srcPl = (const uint4*)(g_Plo + ((size_t)bh * 1024 + l0) * 1024);
    const uint4* srcVh = (const uint4*)(g_Vthi + (size_t)bh * 64 * 1024);
    const uint4* srcVl = (const uint4*)(g_Vtlo + (size_t)bh * 64 * 1024);

    int prow = tid >> 2, pc4 = tid & 3;
    uint32_t dP0 = prow * (SSTR * 2) + pc4 * 16;
    uint32_t dP1 = (prow + 64) * (SSTR * 2) + pc4 * 16;
    uint32_t dV  = prow * (SSTR * 2) + pc4 * 16;

    int kend = (len + 31) & ~31;
    int nch = kend >> 5;

#pragma unroll
    for (int ch = 0; ch < 2; ch++) {
        if (ch < nch) {
            uint32_t sb = sbase + (ch % 3) * G2_STAGE;
            int mq = ch * 4;
            CP_ASYNC16(sb + G2_PH + dP0, srcPh + (size_t)prow * 128 + mq + pc4);
            CP_ASYNC16(sb + G2_PH + dP1, srcPh + (size_t)(prow + 64) * 128 + mq + pc4);
            CP_ASYNC16(sb + G2_PL + dP0, srcPl + (size_t)prow * 128 + mq + pc4);
            CP_ASYNC16(sb + G2_PL + dP1, srcPl + (size_t)(prow + 64) * 128 + mq + pc4);
            CP_ASYNC16(sb + G2_VH + dV,  srcVh + (size_t)prow * 128 + mq + pc4);
            CP_ASYNC16(sb + G2_VL + dV,  srcVl + (size_t)prow * 128 + mq + pc4);
        }
        CP_COMMIT();
    }

    float c[2][4][4];
#pragma unroll
    for (int i = 0; i < 2; i++)
#pragma unroll
        for (int j = 0; j < 4; j++)
#pragma unroll
            for (int q = 0; q < 4; q++) c[i][j][q] = 0.f;

    uint32_t aoff = (uint32_t)(wm + (lane & 15)) * (SSTR * 2) + (((uint32_t)lane >> 4) << 4);
    uint32_t boff = (uint32_t)(wn + (lane & 7) + (((uint32_t)lane >> 4) << 3)) * (SSTR * 2)
                  + ((((uint32_t)lane >> 3) & 1) << 4);

    for (int ch = 0; ch < nch; ++ch) {
        CP_WAIT(1);
        __syncthreads();

        if (ch + 2 < nch) {
            uint32_t sb = sbase + ((ch + 2) % 3) * G2_STAGE;
            int mq = (ch + 2) * 4;
            CP_ASYNC16(sb + G2_PH + dP0, srcPh + (size_t)prow * 128 + mq + pc4);
            CP_ASYNC16(sb + G2_PH + dP1, srcPh + (size_t)(prow + 64) * 128 + mq + pc4);
            CP_ASYNC16(sb + G2_PL + dP0, srcPl + (size_t)prow * 128 + mq + pc4);
            CP_ASYNC16(sb + G2_PL + dP1, srcPl + (size_t)(prow + 64) * 128 + mq + pc4);
            CP_ASYNC16(sb + G2_VH + dV,  srcVh + (size_t)prow * 128 + mq + pc4);
            CP_ASYNC16(sb + G2_VL + dV,  srcVl + (size_t)prow * 128 + mq + pc4);
        }
        CP_COMMIT();

        uint32_t sb = sbase + (ch % 3) * G2_STAGE;
        uint32_t sPh = sb + G2_PH, sPl = sb + G2_PL;
        uint32_t sVh = sb + G2_VH, sVl = sb + G2_VL;

#pragma unroll
        for (int ks = 0; ks < 2; ks++) {
            uint32_t k0b = ks * 32;
            uint32_t Ah[2][4], Al[2][4], Bh[2][4], Bl[2][4];
#pragma unroll
            for (int mt = 0; mt < 2; mt++) {
                ldm_x4(Ah[mt][0], Ah[mt][1], Ah[mt][2], Ah[mt][3],
                       sPh + aoff + mt * 16 * (SSTR * 2) + k0b);
                ldm_x4(Al[mt][0], Al[mt][1], Al[mt][2], Al[mt][3],
                       sPl + aoff + mt * 16 * (SSTR * 2) + k0b);
            }
#pragma unroll
            for (int nt = 0; nt < 2; nt++) {
                ldm_x4(Bh[nt][0], Bh[nt][1], Bh[nt][2], Bh[nt][3],
                       sVh + boff + nt * 16 * (SSTR * 2) + k0b);
                ldm_x4(Bl[nt][0], Bl[nt][1], Bl[nt][2], Bl[nt][3],
                       sVl + boff + nt * 16 * (SSTR * 2) + k0b);
            }
#pragma unroll
            for (int mt = 0; mt < 2; mt++)
#pragma unroll
                for (int ns = 0; ns < 4; ns++) {
                    float* cc = c[mt][ns];
                    uint32_t* bh_ = &Bh[ns >> 1][(ns & 1) * 2];
                    uint32_t* bl_ = &Bl[ns >> 1][(ns & 1) * 2];
                    mma_bf16(cc[0], cc[1], cc[2], cc[3],
                             Ah[mt][0], Ah[mt][1], Ah[mt][2], Ah[mt][3], bh_[0], bh_[1]);
                    mma_bf16(cc[0], cc[1], cc[2], cc[3],
                             Ah[mt][0], Ah[mt][1], Ah[mt][2], Ah[mt][3], bl_[0], bl_[1]);
                    mma_bf16(cc[0], cc[1], cc[2], cc[3],
                             Al[mt][0], Al[mt][1], Al[mt][2], Al[mt][3], bh_[0], bh_[1]);
                }
        }
    }

    const float* ginv = g_inv + (size_t)bh * 1024 + l0;
    float* dstb = outp + ((size_t)b * 1024 + l0) * 512 + h * 64;
#pragma unroll
    for (int mt = 0; mt < 2; mt++) {
        int r0 = wm + mt * 16 + (lane >> 2);
        float ia = ginv[r0], ib = ginv[r0 + 8];
#pragma unroll
        for (int ns = 0; ns < 4; ns++) {
            int n = wn + ns * 8 + (lane & 3) * 2;
            *(float2*)&dstb[(size_t)r0 * 512 + n] =
                make_float2(c[mt][ns][0] * ia, c[mt][ns][1] * ia);
            *(float2*)&dstb[(size_t)(r0 + 8) * 512 + n] =
                make_float2(c[mt][ns][2] * ib, c[mt][ns][3] * ib);
        }
    }
}

// ---------------------------------------------------------------------------
extern "C" void kernel_launch(void* const* d_in, const int* in_sizes, int n_in,
                              void* d_out, int out_size) {
    const float* K     = (const float*)d_in[0];
    const float* Q     = (const float*)d_in[1];
    const float* V     = (const float*)d_in[2];
    const float* doc   = (const float*)d_in[3];
    const float* gamma = (const float*)d_in[4];
    const float* beta  = (const float*)d_in[5];
    // pad_mask / bx_packed derivable from doc_sizes; unused.

    float* outp = (float*)d_out;

    cudaFuncSetAttribute(gemm1_kernel,
                         cudaFuncAttributeMaxDynamicSharedMemorySize, G1_SMEM);
    cudaFuncSetAttribute(gemm2_kernel,
                         cudaFuncAttributeMaxDynamicSharedMemorySize, G2_SMEM);

    prep_kq_kernel<<<(BB * LL * DD) / 256, 256>>>(K, Q);
    prep_v_kernel<<<dim3(LL / 32, DD / 32, BB), dim3(32, 8)>>>(V);

    dim3 g1(LL / 128, LL / 128, BB * HH);      // (8, 8, 32)
    gemm1_kernel<<<g1, 256, G1_SMEM>>>(doc);

    dim3 g2(LL, BB);
    lnsm_kernel<<<g2, 256>>>(doc, gamma, beta);

    if (out_size >= BB * LL * DD + BB * LL) {
        float* wout = outp + (size_t)BB * LL * DD;
        wfin_kernel<<<BB, 1024>>>(doc, wout);
    }

    dim3 g3(LL / 128, HH, BB);                 // (8, 8, 4)
    gemm2_kernel<<<g3, 256, G2_SMEM>>>(doc, outp);
}

// round 17
// speedup vs baseline: 1.9376x; 1.1328x over previous
#include <cuda_runtime.h>
#include <cuda_bf16.h>
#include <cuda_fp16.h>
#include <cstdint>

#define BB 4
#define LL 1024
#define DD 512
#define HH 8
#define HD 64

// ---------------------------------------------------------------------------
// Device scratch (static: no allocations allowed)
// g_S layout: [b][l][h][m]  -- 8 heads of one (b,l) row are contiguous (32 KB)
__device__ __align__(256) float g_S[(size_t)BB * LL * HH * LL];           // 128 MB scores
__device__ __align__(256) __half g_Pf[(size_t)BB * HH * LL * LL];         // 64 MB (unnormalized e, fp16)
__device__ __align__(256) __nv_bfloat16 g_Khi[(size_t)BB * HH * LL * HD];
__device__ __align__(256) __nv_bfloat16 g_Klo[(size_t)BB * HH * LL * HD];
__device__ __align__(256) __nv_bfloat16 g_Qhi[(size_t)BB * HH * LL * HD];
__device__ __align__(256) __nv_bfloat16 g_Qlo[(size_t)BB * HH * LL * HD];
__device__ __align__(256) __half g_Vthf[(size_t)BB * HH * HD * LL];       // [bh][d][m] fp16 hi
__device__ __align__(256) __half g_Vtlf[(size_t)BB * HH * HD * LL];       // fp16 lo
__device__ float g_wacc[BB * LL];
__device__ float g_inv[BB * HH * LL];    // per-(bh,l) softmax 1/sum (row scale)

// ---------------------------------------------------------------------------
__device__ __forceinline__ uint32_t smem_u32(const void* p) {
    uint32_t a;
    asm("{ .reg .u64 t; cvta.to.shared.u64 t, %1; cvt.u32.u64 %0, t; }" : "=r"(a) : "l"(p));
    return a;
}
__device__ __forceinline__ void ldm_x4(uint32_t& r0, uint32_t& r1, uint32_t& r2,
                                       uint32_t& r3, uint32_t addr) {
    asm volatile("ldmatrix.sync.aligned.m8n8.x4.shared.b16 {%0,%1,%2,%3}, [%4];"
                 : "=r"(r0), "=r"(r1), "=r"(r2), "=r"(r3) : "r"(addr));
}
__device__ __forceinline__ void mma_bf16(float& c0, float& c1, float& c2, float& c3,
                                         uint32_t a0, uint32_t a1, uint32_t a2, uint32_t a3,
                                         uint32_t b0, uint32_t b1) {
    asm volatile("mma.sync.aligned.m16n8k16.row.col.f32.bf16.bf16.f32 "
                 "{%0,%1,%2,%3}, {%4,%5,%6,%7}, {%8,%9}, {%0,%1,%2,%3};"
                 : "+f"(c0), "+f"(c1), "+f"(c2), "+f"(c3)
                 : "r"(a0), "r"(a1), "r"(a2), "r"(a3), "r"(b0), "r"(b1));
}
__device__ __forceinline__ void mma_f16(float& c0, float& c1, float& c2, float& c3,
                                        uint32_t a0, uint32_t a1, uint32_t a2, uint32_t a3,
                                        uint32_t b0, uint32_t b1) {
    asm volatile("mma.sync.aligned.m16n8k16.row.col.f32.f16.f16.f32 "
                 "{%0,%1,%2,%3}, {%4,%5,%6,%7}, {%8,%9}, {%0,%1,%2,%3};"
                 : "+f"(c0), "+f"(c1), "+f"(c2), "+f"(c3)
                 : "r"(a0), "r"(a1), "r"(a2), "r"(a3), "r"(b0), "r"(b1));
}
#define CP_ASYNC16(dst, src) \
    asm volatile("cp.async.cg.shared.global [%0], [%1], 16;" :: "r"(dst), "l"(src))
#define CP_COMMIT()  asm volatile("cp.async.commit_group;" ::: "memory")
#define CP_WAIT(n)   asm volatile("cp.async.wait_group %0;" :: "n"(n) : "memory")

// smem row stride for MMA tiles: 40 b16 = 80 B; conflict-free ldmatrix.
#define SSTR 40

__device__ __forceinline__ uint16_t bf16_bits(float f) {
    return __bfloat16_as_ushort(__float2bfloat16(f));
}

// ---------------------------------------------------------------------------
// Prep 1: split K,Q fp32 -> bf16 hi/lo in [bh][l][64] layout; zero wacc.
__global__ __launch_bounds__(256) void prep_kq_kernel(
    const float* __restrict__ Kp, const float* __restrict__ Qp)
{
    int idx = blockIdx.x * 256 + threadIdx.x;
    int k = idx & 63, h = (idx >> 6) & 7, l = (idx >> 9) & 1023, b = idx >> 19;
    size_t o = (((size_t)(b * 8 + h) * 1024 + l) << 6) | (unsigned)k;
    float kv = Kp[idx];
    __nv_bfloat16 khi = __float2bfloat16(kv);
    g_Khi[o] = khi;
    g_Klo[o] = __float2bfloat16(kv - __bfloat162float(khi));
    float qv = Qp[idx];
    __nv_bfloat16 qhi = __float2bfloat16(qv);
    g_Qhi[o] = qhi;
    g_Qlo[o] = __float2bfloat16(qv - __bfloat162float(qhi));
    if (idx < BB * LL) g_wacc[idx] = 0.f;
}

// Prep 2: transpose-split V [b][m][h*64+d] -> Vt fp16 hi/lo [bh][d][m]
__global__ __launch_bounds__(256) void prep_v_kernel(const float* __restrict__ Vp)
{
    __shared__ float t[32][33];
    int b = blockIdx.z;
    int m0 = blockIdx.x * 32, hd0 = blockIdx.y * 32;
    int tx = threadIdx.x, ty = threadIdx.y;   // (32, 8)
#pragma unroll
    for (int i = 0; i < 4; i++)
        t[ty + 8 * i][tx] = Vp[((size_t)b * 1024 + m0 + ty + 8 * i) * 512 + hd0 + tx];
    __syncthreads();
#pragma unroll
    for (int i = 0; i < 4; i++) {
        int hd = hd0 + ty + 8 * i;
        int h = hd >> 6, d = hd & 63;
        float x = t[tx][ty + 8 * i];
        __half hi = __float2half(x);
        size_t o = ((size_t)(b * 8 + h) * 64 + d) * 1024 + m0 + tx;
        g_Vthf[o] = hi;
        g_Vtlf[o] = __float2half(x - __half2float(hi));
    }
}

// ---------------------------------------------------------------------------
// GEMM1 (mma.sync bf16): S[b][l][h][m] = K[l,:]·Q[m,:], tile 128x128, K=64.
// cp.async double-buffer; epilogue stores culled to l<len && m<len. (R13/R16)
#define G1_CHUNK (4 * 128 * SSTR * 2)             // 40960 B per chunk
#define G1_SMEM  (2 * G1_CHUNK)                   // 81920 B
__global__ __launch_bounds__(256) void gemm1_kernel(const float* __restrict__ doc)
{
    extern __shared__ __align__(16) char dsm[];

    int bh = blockIdx.z;
    int b = bh >> 3, h = bh & 7;
    int len = (int)doc[b];
    int l0 = blockIdx.y * 128, m0 = blockIdx.x * 128;
    if (l0 >= len || m0 >= len) return;

    int tid = threadIdx.x, wid = tid >> 5, lane = tid & 31;
    int wm = (wid >> 2) * 64, wn = (wid & 3) * 32;
    uint32_t sbase = smem_u32(dsm);

    const uint4* srcs[4] = {
        (const uint4*)(g_Khi + ((size_t)bh * 1024 + l0) * 64),
        (const uint4*)(g_Klo + ((size_t)bh * 1024 + l0) * 64),
        (const uint4*)(g_Qhi + ((size_t)bh * 1024 + m0) * 64),
        (const uint4*)(g_Qlo + ((size_t)bh * 1024 + m0) * 64) };

    int row = tid >> 2, c4 = tid & 3;
#pragma unroll
    for (int ch = 0; ch < 2; ch++) {
#pragma unroll
        for (int e = 0; e < 4; e++) {
            uint32_t dbase = sbase + ch * G1_CHUNK + e * (128 * SSTR * 2);
            CP_ASYNC16(dbase + row * (SSTR * 2) + c4 * 16,
                       srcs[e] + (size_t)row * 8 + ch * 4 + c4);
            CP_ASYNC16(dbase + (row + 64) * (SSTR * 2) + c4 * 16,
                       srcs[e] + (size_t)(row + 64) * 8 + ch * 4 + c4);
        }
        CP_COMMIT();
    }

    float c[4][4][4];
#pragma unroll
    for (int i = 0; i < 4; i++)
#pragma unroll
        for (int j = 0; j < 4; j++)
#pragma unroll
            for (int q = 0; q < 4; q++) c[i][j][q] = 0.f;

    uint32_t aoff = (uint32_t)(wm + (lane & 15)) * (SSTR * 2) + (((uint32_t)lane >> 4) << 4);
    uint32_t boff = (uint32_t)(wn + (lane & 7) + (((uint32_t)lane >> 4) << 3)) * (SSTR * 2)
                  + ((((uint32_t)lane >> 3) & 1) << 4);

#pragma unroll
    for (int ch = 0; ch < 2; ch++) {
        if (ch == 0) { CP_WAIT(1); } else { CP_WAIT(0); }
        __syncthreads();
        uint32_t sAh = sbase + ch * G1_CHUNK;
        uint32_t sAl = sAh + 128 * SSTR * 2;
        uint32_t sBh = sAl + 128 * SSTR * 2;
        uint32_t sBl = sBh + 128 * SSTR * 2;

#pragma unroll
        for (int ks = 0; ks < 2; ks++) {
            uint32_t k0b = ks * 32;
            uint32_t Ah[4][4], Al[4][4], Bh[2][4], Bl[2][4];
#pragma unroll
            for (int mt = 0; mt < 4; mt++) {
                ldm_x4(Ah[mt][0], Ah[mt][1], Ah[mt][2], Ah[mt][3],
                       sAh + aoff + mt * 16 * (SSTR * 2) + k0b);
                ldm_x4(Al[mt][0], Al[mt][1], Al[mt][2], Al[mt][3],
                       sAl + aoff + mt * 16 * (SSTR * 2) + k0b);
            }
#pragma unroll
            for (int nt = 0; nt < 2; nt++) {
                ldm_x4(Bh[nt][0], Bh[nt][1], Bh[nt][2], Bh[nt][3],
                       sBh + boff + nt * 16 * (SSTR * 2) + k0b);
                ldm_x4(Bl[nt][0], Bl[nt][1], Bl[nt][2], Bl[nt][3],
                       sBl + boff + nt * 16 * (SSTR * 2) + k0b);
            }
#pragma unroll
            for (int mt = 0; mt < 4; mt++)
#pragma unroll
                for (int ns = 0; ns < 4; ns++) {
                    float* cc = c[mt][ns];
                    uint32_t* bh_ = &Bh[ns >> 1][(ns & 1) * 2];
                    uint32_t* bl_ = &Bl[ns >> 1][(ns & 1) * 2];
                    mma_bf16(cc[0], cc[1], cc[2], cc[3],
                             Ah[mt][0], Ah[mt][1], Ah[mt][2], Ah[mt][3], bh_[0], bh_[1]);
                    mma_bf16(cc[0], cc[1], cc[2], cc[3],
                             Ah[mt][0], Ah[mt][1], Ah[mt][2], Ah[mt][3], bl_[0], bl_[1]);
                    mma_bf16(cc[0], cc[1], cc[2], cc[3],
                             Al[mt][0], Al[mt][1], Al[mt][2], Al[mt][3], bh_[0], bh_[1]);
                }
        }
        if (ch == 0) __syncthreads();
    }

    // epilogue: S[b][l][h][m]; row stride = 8*1024 floats; culled to valid region
    float* Sp = g_S + (((size_t)(b * 1024 + l0) * 8 + h) << 10) + m0;
    int rlim = len - l0, nlim = len - m0;
#pragma unroll
    for (int mt = 0; mt < 4; mt++) {
        int r0 = wm + mt * 16 + (lane >> 2);
#pragma unroll
        for (int ns = 0; ns < 4; ns++) {
            int n = wn + ns * 8 + (lane & 3) * 2;
            if (n < nlim) {
                if (r0 < rlim)
                    *(float2*)&Sp[(size_t)r0 * 8192 + n] =
                        make_float2(c[mt][ns][0], c[mt][ns][1]);
                if (r0 + 8 < rlim)
                    *(float2*)&Sp[(size_t)(r0 + 8) * 8192 + n] =
                        make_float2(c[mt][ns][2], c[mt][ns][3]);
            }
        }
    }
}

// ---------------------------------------------------------------------------
// lnsm v9 (R15 structure): fused load+LN+exp -> smem; read-only sums; emit
// single fp16 e (csum from fp32 e, so w keeps fp32 precision).
__global__ __launch_bounds__(256) void lnsm_kernel(
    const float* __restrict__ doc, const float* __restrict__ gamma,
    const float* __restrict__ beta)
{
    __shared__ float s[HH][LL];   // 32 KB
    __shared__ float binv[HH];
    int b = blockIdx.y, l = blockIdx.x;
    int len = (int)doc[b];
    int kend  = (len + 63) & ~63;
    int lceil = (len + 127) & ~127;
    int tid = threadIdx.x;

    if (l >= len) {
        if (l >= lceil) return;
        for (int h = 0; h < HH; ++h) {
            size_t o = ((size_t)(b * HH + h) * LL + l) * LL;
            for (int m = tid; m < kend; m += 256) g_Pf[o + m] = __float2half(0.f);
        }
        if (tid < HH) g_inv[(b * HH + tid) * LL + l] = 0.f;
        return;
    }

    const float* Sb = g_S + ((size_t)(b * 1024 + l) << 13);   // [l][h][m] block
    float ga[HH], be[HH];
#pragma unroll
    for (int h = 0; h < HH; h++) { ga[h] = gamma[h]; be[h] = beta[h]; }

    // ---- sweep 1: load + LN + exp -> smem (e), zeros in [len, kend) ----
    for (int m = tid; m < LL; m += 256) {
        if (m < len) {
            float x[HH];
#pragma unroll
            for (int h = 0; h < HH; h++) x[h] = Sb[(h << 10) + m];
            float mu = 0.f;
#pragma unroll
            for (int h = 0; h < HH; h++) mu += x[h];
            mu *= (1.f / HH);
            float var = 0.f;
#pragma unroll
            for (int h = 0; h < HH; h++) { float d0 = x[h] - mu; var += d0 * d0; }
            var *= (1.f / HH);
            float rstd = rsqrtf(var + 1e-5f);
#pragma unroll
            for (int h = 0; h < HH; h++)
                s[h][m] = __expf((x[h] - mu) * rstd * ga[h] + be[h]);
        } else if (m < kend) {
#pragma unroll
            for (int h = 0; h < HH; h++) s[h][m] = 0.f;
        }
    }
    __syncthreads();

    // ---- sweep 2: read-only per-head sums (warp w owns head w) ----
    {
        int w = tid >> 5, lane = tid & 31;
        float sum = 0.f;
        for (int m = lane; m < len; m += 32) sum += s[w][m];
#pragma unroll
        for (int o = 16; o; o >>= 1) sum += __shfl_xor_sync(0xffffffffu, sum, o);
        if (lane == 0) {
            float iv = 1.f / sum;
            binv[w] = iv;
            g_inv[(b * HH + w) * LL + l] = iv;
        }
    }
    __syncthreads();

    float iv[HH];
#pragma unroll
    for (int h = 0; h < HH; h++) iv[h] = binv[h];

    // ---- sweep 3: emit unnormalized e as fp16 + column sums ----
    size_t obase = ((size_t)(b * HH) * LL + l) * LL;
    for (int m = tid; m < kend; m += 256) {
        bool valid = (m < len);
        float csum = 0.f;
#pragma unroll
        for (int h = 0; h < HH; h++) {
            float e = valid ? s[h][m] : 0.f;
            csum += e * iv[h];
            g_Pf[obase + ((size_t)h << 20) + m] = __float2half(e);
        }
        if (valid) atomicAdd(&g_wacc[b * LL + m], csum);
    }
}

// ---------------------------------------------------------------------------
// Finalize w: one 1024-thread block per batch, single pass.
__global__ __launch_bounds__(1024) void wfin_kernel(
    const float* __restrict__ doc, float* __restrict__ wout)
{
    __shared__ float red[32];
    __shared__ float s_bmax, s_inv;
    int b = blockIdx.x;
    int len = (int)doc[b];
    int tid = threadIdx.x, w = tid >> 5, lane = tid & 31;
    float scale = 1.f / (8.f * (float)len);

    float v = (tid < len) ? g_wacc[b * LL + tid] * scale : -1e30f;
    float mx = v;
#pragma unroll
    for (int o = 16; o; o >>= 1) mx = fmaxf(mx, __shfl_xor_sync(0xffffffffu, mx, o));
    if (lane == 0) red[w] = mx;
    __syncthreads();
    if (w == 0) {
        float t = red[lane];
#pragma unroll
        for (int o = 16; o; o >>= 1) t = fmaxf(t, __shfl_xor_sync(0xffffffffu, t, o));
        if (lane == 0) s_bmax = t;
    }
    __syncthreads();
    float e = (tid < len) ? __expf(v - s_bmax) : 0.f;
    float sum = e;
#pragma unroll
    for (int o = 16; o; o >>= 1) sum += __shfl_xor_sync(0xffffffffu, sum, o);
    if (lane == 0) red[w] = sum;
    __syncthreads();
    if (w == 0) {
        float t = red[lane];
#pragma unroll
        for (int o = 16; o; o >>= 1) t += __shfl_xor_sync(0xffffffffu, t, o);
        if (lane == 0) s_inv = 1.f / t;
    }
    __syncthreads();
    wout[b * LL + tid] = e * s_inv;
}

// ---------------------------------------------------------------------------
// GEMM2 (mma.sync fp16): out[l,d] = inv[l] * sum_m e[l,m]·Vt[d,m];
// tile 128(l) x 64(d). P single fp16 (A), V fp16 hi/lo (B): 2 MMA terms.
// 3-stage cp.async ring, one __syncthreads per chunk. (R14 recipe)
#define G2_P  0
#define G2_VH (128 * SSTR * 2)            // 10240
#define G2_VL (G2_VH + 64 * SSTR * 2)     // 15360
#define G2_STAGE (G2_VL + 64 * SSTR * 2)  // 20480
#define G2_SMEM (3 * G2_STAGE)            // 61440
__global__ __launch_bounds__(256) void gemm2_kernel(
    const float* __restrict__ doc, float* __restrict__ outp)
{
    extern __shared__ __align__(16) char dsm[];

    int b = blockIdx.z, h = blockIdx.y;
    int bh = b * 8 + h;
    int len = (int)doc[b];
    int l0 = blockIdx.x * 128;
    int tid = threadIdx.x, wid = tid >> 5, lane = tid & 31;

    if (l0 >= len) {
        float* dst = outp + ((size_t)b * 1024 + l0 + (tid >> 1)) * 512 + h * 64;
        float4 z = make_float4(0, 0, 0, 0);
#pragma unroll
        for (int j = 0; j < 8; j++) ((float4*)dst)[(tid & 1) * 8 + j] = z;
        return;
    }

    int wm = (wid >> 1) * 32, wn = (wid & 1) * 32;
    uint32_t sbase = smem_u32(dsm);

    const uint4* srcP  = (const uint4*)(g_Pf + ((size_t)bh * 1024 + l0) * 1024);
    const uint4* srcVh = (const uint4*)(g_Vthf + (size_t)bh * 64 * 1024);
    const uint4* srcVl = (const uint4*)(g_Vtlf + (size_t)bh * 64 * 1024);

    // P: 128 rows x 32 half = 8192 B/chunk -> 512 uint4, 2 per thread
    int prow = tid >> 1, pc4 = (tid & 1) * 2;      // uint4 slots pc4, pc4+1
    uint32_t dPa = prow * (SSTR * 2) + pc4 * 16;
    // V: 64 rows x 32 half = 4096 B/chunk -> 256 uint4, 1 per thread
    int vrow = tid >> 2, vc4 = tid & 3;
    uint32_t dV = vrow * (SSTR * 2) + vc4 * 16;

    int kend = (len + 31) & ~31;
    int nch = kend >> 5;

#pragma unroll
    for (int ch = 0; ch < 2; ch++) {
        if (ch < nch) {
            uint32_t sb = sbase + (ch % 3) * G2_STAGE;
            int mq = ch * 4;
            CP_ASYNC16(sb + G2_P + dPa,      srcP + (size_t)prow * 128 + mq + pc4);
            CP_ASYNC16(sb + G2_P + dPa + 16, srcP + (size_t)prow * 128 + mq + pc4 + 1);
            CP_ASYNC16(sb + G2_VH + dV, srcVh + (size_t)vrow * 128 + mq + vc4);
            CP_ASYNC16(sb + G2_VL + dV, srcVl + (size_t)vrow * 128 + mq + vc4);
        }
        CP_COMMIT();
    }

    float c[2][4][4];
#pragma unroll
    for (int i = 0; i < 2; i++)
#pragma unroll
        for (int j = 0; j < 4; j++)
#pragma unroll
            for (int q = 0; q < 4; q++) c[i][j][q] = 0.f;

    uint32_t aoff = (uint32_t)(wm + (lane & 15)) * (SSTR * 2) + (((uint32_t)lane >> 4) << 4);
    uint32_t boff = (uint32_t)(wn + (lane & 7) + (((uint32_t)lane >> 4) << 3)) * (SSTR * 2)
                  + ((((uint32_t)lane >> 3) & 1) << 4);

    for (int ch = 0; ch < nch; ++ch) {
        CP_WAIT(1);
        __syncthreads();

        if (ch + 2 < nch) {
            uint32_t sb = sbase + ((ch + 2) % 3) * G2_STAGE;
            int mq = (ch + 2) * 4;
            CP_ASYNC16(sb + G2_P + dPa,      srcP + (size_t)prow * 128 + mq + pc4);
            CP_ASYNC16(sb + G2_P + dPa + 16, srcP + (size_t)prow * 128 + mq + pc4 + 1);
            CP_ASYNC16(sb + G2_VH + dV, srcVh + (size_t)vrow * 128 + mq + vc4);
            CP_ASYNC16(sb + G2_VL + dV, srcVl + (size_t)vrow * 128 + mq + vc4);
        }
        CP_COMMIT();

        uint32_t sb = sbase + (ch % 3) * G2_STAGE;
        uint32_t sP = sb + G2_P, sVh = sb + G2_VH, sVl = sb + G2_VL;

#pragma unroll
        for (int ks = 0; ks < 2; ks++) {
            uint32_t k0b = ks * 32;
            uint32_t A[2][4], Bh[2][4], Bl[2][4];
#pragma unroll
            for (int mt = 0; mt < 2; mt++)
                ldm_x4(A[mt][0], A[mt][1], A[mt][2], A[mt][3],
                       sP + aoff + mt * 16 * (SSTR * 2) + k0b);
#pragma unroll
            for (int nt = 0; nt < 2; nt++) {
                ldm_x4(Bh[nt][0], Bh[nt][1], Bh[nt][2], Bh[nt][3],
                       sVh + boff + nt * 16 * (SSTR * 2) + k0b);
                ldm_x4(Bl[nt][0], Bl[nt][1], Bl[nt][2], Bl[nt][3],
                       sVl + boff + nt * 16 * (SSTR * 2) + k0b);
            }
#pragma unroll
            for (int mt = 0; mt < 2; mt++)
#pragma unroll
                for (int ns = 0; ns < 4; ns++) {
                    float* cc = c[mt][ns];
                    uint32_t* bh_ = &Bh[ns >> 1][(ns & 1) * 2];
                    uint32_t* bl_ = &Bl[ns >> 1][(ns & 1) * 2];
                    mma_f16(cc[0], cc[1], cc[2], cc[3],
                            A[mt][0], A[mt][1], A[mt][2], A[mt][3], bh_[0], bh_[1]);
                    mma_f16(cc[0], cc[1], cc[2], cc[3],
                            A[mt][0], A[mt][1], A[mt][2], A[mt][3], bl_[0], bl_[1]);
                }
        }
    }

    const float* ginv = g_inv + (size_t)bh * 1024 + l0;
    float* dstb = outp + ((size_t)b * 1024 + l0) * 512 + h * 64;
#pragma unroll
    for (int mt = 0; mt < 2; mt++) {
        int r0 = wm + mt * 16 + (lane >> 2);
        float ia = ginv[r0], ib = ginv[r0 + 8];
#pragma unroll
        for (int ns = 0; ns < 4; ns++) {
            int n = wn + ns * 8 + (lane & 3) * 2;
            *(float2*)&dstb[(size_t)r0 * 512 + n] =
                make_float2(c[mt][ns][0] * ia, c[mt][ns][1] * ia);
            *(float2*)&dstb[(size_t)(r0 + 8) * 512 + n] =
                make_float2(c[mt][ns][2] * ib, c[mt][ns][3] * ib);
        }
    }
}

// ---------------------------------------------------------------------------
extern "C" void kernel_launch(void* const* d_in, const int* in_sizes, int n_in,
                              void* d_out, int out_size) {
    const float* K     = (const float*)d_in[0];
    const float* Q     = (const float*)d_in[1];
    const float* V     = (const float*)d_in[2];
    const float* doc   = (const float*)d_in[3];
    const float* gamma = (const float*)d_in[4];
    const float* beta  = (const float*)d_in[5];
    // pad_mask / bx_packed derivable from doc_sizes; unused.

    float* outp = (float*)d_out;

    cudaFuncSetAttribute(gemm1_kernel,
                         cudaFuncAttributeMaxDynamicSharedMemorySize, G1_SMEM);
    cudaFuncSetAttribute(gemm2_kernel,
                         cudaFuncAttributeMaxDynamicSharedMemorySize, G2_SMEM);

    prep_kq_kernel<<<(BB * LL * DD) / 256, 256>>>(K, Q);
    prep_v_kernel<<<dim3(LL / 32, DD / 32, BB), dim3(32, 8)>>>(V);

    dim3 g1(LL / 128, LL / 128, BB * HH);      // (8, 8, 32)
    gemm1_kernel<<<g1, 256, G1_SMEM>>>(doc);

    dim3 g2(LL, BB);
    lnsm_kernel<<<g2, 256>>>(doc, gamma, beta);

    if (out_size >= BB * LL * DD + BB * LL) {
        float* wout = outp + (size_t)BB * LL * DD;
        wfin_kernel<<<BB, 1024>>>(doc, wout);
    }

    dim3 g3(LL / 128, HH, BB);                 // (8, 8, 4)
    gemm2_kernel<<<g3, 256, G2_SMEM>>>(doc, outp);
}